// round 5
// baseline (speedup 1.0000x reference)
#include <cuda_runtime.h>
#include <math.h>

#define BATCH  512
#define L      100
#define D      128
#define P      132            // padded row pitch (floats) for SMEM tiles
#define NITEMS 100000
#define NEGV   -1000000000.0f

// scratch between kernels (allocation-free contract)
__device__ __align__(16) float g_hread[BATCH * D];
__device__ int g_cnt[BATCH];

__device__ __forceinline__ float sigmoidf_(float v) { return 1.0f / (1.0f + expf(-v)); }

// ---------------------------------------------------------------------------
// Kernel A: one block per sample. Builds the session graph, runs the GGNN/GRU
// step fully in shared memory, attention readout, writes h_read + cnt.
// ---------------------------------------------------------------------------
__global__ __launch_bounds__(512) void sample_kernel(
    const int*   __restrict__ x,
    const float* __restrict__ emb,
    const float* __restrict__ W_in,
    const float* __restrict__ W_out,
    const float* __restrict__ w_ih,
    const float* __restrict__ w_hh,
    const float* __restrict__ b_ih,
    const float* __restrict__ b_hh,
    const float* __restrict__ W_read,
    const float* __restrict__ b_read)
{
    extern __shared__ float dyn[];
    float* H0 = dyn;                 // [L][P]  node embeddings
    float* X  = H0 + L * P;          // [L][P]  Hin -> xin
    float* HO = X  + L * P;          // [L][P]  Hout -> H
    float* WS = HO + L * P;          // [96][P] staged weight tiles

    __shared__ int   s_seq[L];
    __shared__ int   s_rep[L];
    __shared__ int   s_nodes[L];
    __shared__ int   s_cinv[L];
    __shared__ float s_deg[L];
    __shared__ float s_sc[L];
    __shared__ float s_hlast[D];
    __shared__ float s_local[D];
    __shared__ int   s_nn, s_cnt;

    const int b   = blockIdx.x;
    const int tid = threadIdx.x;
    const int NT  = 512;

    if (tid == 0) { s_nn = 0; s_cnt = 0; }
    for (int i = tid; i < L; i += NT) s_seq[i] = x[b * L + i];
    __syncthreads();

    // --- pass 1: first-occurrence flag + compact position (O(L^2), trivial) ---
    int mypos = 0;
    if (tid < L) {
        int s = s_seq[tid];
        int rep = (s != 0);
        for (int j = 0; j < tid; j++) {
            int sj = s_seq[j];
            if (sj != 0) { mypos++; if (sj == s) rep = 0; }
        }
        s_rep[tid] = rep;
    }
    __syncthreads();

    // --- pass 2: distinct rank (== searchsorted into sorted unique nodes) ---
    if (tid < L) {
        int s = s_seq[tid];
        if (s != 0) {
            int rank = 0;
            for (int j = 0; j < L; j++)
                if (s_rep[j] && s_seq[j] < s) rank++;
            if (s_rep[tid]) { s_nodes[rank] = s; atomicAdd(&s_nn, 1); }
            s_cinv[mypos] = rank;
            atomicAdd(&s_cnt, 1);
        }
    }
    if (tid < L) s_deg[tid] = 0.0f;
    __syncthreads();

    const int nn  = s_nn;
    const int cnt = s_cnt;

    // in-degree per node (duplicate edges count)
    if (tid < cnt - 1) atomicAdd(&s_deg[s_cinv[tid + 1]], 1.0f);

    // gather H0 = emb[nodes]
    for (int idx = tid; idx < nn * 32; idx += NT) {
        int r = idx >> 5, q = idx & 31;
        float4 v = ((const float4*)(emb + (size_t)s_nodes[r] * D))[q];
        *((float4*)(H0 + r * P) + q) = v;
    }
    __syncthreads();

    const int jj = tid & 15;
    const int ii = tid >> 4;     // 0..31

    // --- Hin = H0 @ W_in^T ; Hout = H0 @ W_out^T (staged 16-col weight tiles) ---
    for (int j0 = 0; j0 < D; j0 += 16) {
        for (int idx = tid; idx < 1024; idx += NT) {          // 2*16*32 float4
            int which = idx >> 9;
            int rem = idx & 511;
            int jr = rem >> 5, q = rem & 31;
            const float* src = (which == 0 ? W_in : W_out) + (size_t)(j0 + jr) * D;
            *((float4*)(WS + (which * 16 + jr) * P) + q) = ((const float4*)src)[q];
        }
        __syncthreads();
        #pragma unroll
        for (int ic = 0; ic < 4; ic++) {
            int i = ic * 32 + ii;
            if (i < nn) {
                const float* h0r = H0 + i * P;
                const float* w0  = WS + jj * P;
                const float* w1  = WS + (16 + jj) * P;
                float a0 = 0.f, a1 = 0.f;
                #pragma unroll
                for (int k = 0; k < D; k += 4) {
                    float4 h = *(const float4*)(h0r + k);
                    float4 u = *(const float4*)(w0 + k);
                    float4 v = *(const float4*)(w1 + k);
                    a0 = fmaf(h.x,u.x,fmaf(h.y,u.y,fmaf(h.z,u.z,fmaf(h.w,u.w,a0))));
                    a1 = fmaf(h.x,v.x,fmaf(h.y,v.y,fmaf(h.z,v.z,fmaf(h.w,v.w,a1))));
                }
                X [i * P + j0 + jj] = a0;
                HO[i * P + j0 + jj] = a1;
            }
        }
        __syncthreads();
    }

    // --- xin = Hin + agg/deg : scatter Hout[src]/deg[dst] into X[dst] ---
    {
        int nedge = (cnt >= 1) ? (cnt - 1) : 0;
        for (int idx = tid; idx < nedge * D; idx += NT) {
            int t = idx >> 7, k = idx & 127;
            int src = s_cinv[t], dst = s_cinv[t + 1];
            float rd = 1.0f / fmaxf(s_deg[dst], 1.0f);
            atomicAdd(&X[dst * P + k], HO[src * P + k] * rd);
        }
    }
    __syncthreads();

    // --- GRU cell: 6 gate dots per (i,j), staged weight tiles, H -> HO ---
    for (int j0 = 0; j0 < D; j0 += 16) {
        for (int idx = tid; idx < 3072; idx += NT) {          // 6*16*32 float4
            int r = idx >> 5, q = idx & 31;
            int g = r >> 4, jr = r & 15;
            const float* base = (g < 3) ? w_ih : w_hh;
            int row = ((g < 3) ? g : g - 3) * D + j0 + jr;
            *((float4*)(WS + r * P) + q) = ((const float4*)(base + (size_t)row * D))[q];
        }
        __syncthreads();
        int j = j0 + jj;
        float bi0 = b_ih[j], bi1 = b_ih[D + j], bi2 = b_ih[2 * D + j];
        float bh0 = b_hh[j], bh1 = b_hh[D + j], bh2 = b_hh[2 * D + j];
        #pragma unroll
        for (int ic = 0; ic < 4; ic++) {
            int i = ic * 32 + ii;
            if (i < nn) {
                const float* xr = X  + i * P;
                const float* hr = H0 + i * P;
                const float* u0 = WS + (0 * 16 + jj) * P;
                const float* u1 = WS + (1 * 16 + jj) * P;
                const float* u2 = WS + (2 * 16 + jj) * P;
                const float* u3 = WS + (3 * 16 + jj) * P;
                const float* u4 = WS + (4 * 16 + jj) * P;
                const float* u5 = WS + (5 * 16 + jj) * P;
                float a0=0.f,a1=0.f,a2=0.f,a3=0.f,a4=0.f,a5=0.f;
                #pragma unroll
                for (int k = 0; k < D; k += 4) {
                    float4 xv = *(const float4*)(xr + k);
                    float4 hv = *(const float4*)(hr + k);
                    float4 t0 = *(const float4*)(u0 + k);
                    float4 t1 = *(const float4*)(u1 + k);
                    float4 t2 = *(const float4*)(u2 + k);
                    float4 t3 = *(const float4*)(u3 + k);
                    float4 t4 = *(const float4*)(u4 + k);
                    float4 t5 = *(const float4*)(u5 + k);
                    a0 = fmaf(xv.x,t0.x,fmaf(xv.y,t0.y,fmaf(xv.z,t0.z,fmaf(xv.w,t0.w,a0))));
                    a1 = fmaf(xv.x,t1.x,fmaf(xv.y,t1.y,fmaf(xv.z,t1.z,fmaf(xv.w,t1.w,a1))));
                    a2 = fmaf(xv.x,t2.x,fmaf(xv.y,t2.y,fmaf(xv.z,t2.z,fmaf(xv.w,t2.w,a2))));
                    a3 = fmaf(hv.x,t3.x,fmaf(hv.y,t3.y,fmaf(hv.z,t3.z,fmaf(hv.w,t3.w,a3))));
                    a4 = fmaf(hv.x,t4.x,fmaf(hv.y,t4.y,fmaf(hv.z,t4.z,fmaf(hv.w,t4.w,a4))));
                    a5 = fmaf(hv.x,t5.x,fmaf(hv.y,t5.y,fmaf(hv.z,t5.z,fmaf(hv.w,t5.w,a5))));
                }
                float rr = sigmoidf_(a0 + bi0 + a3 + bh0);
                float zz = sigmoidf_(a1 + bi1 + a4 + bh1);
                float nc = tanhf(a2 + bi2 + rr * (a5 + bh2));
                HO[i * P + j] = (1.0f - zz) * nc + zz * hr[j];
            }
        }
        __syncthreads();
    }

    // --- attention readout ---
    int li = (cnt > 0) ? s_cinv[cnt - 1] : 0;
    for (int k = tid; k < D; k += NT) s_hlast[k] = HO[li * P + k];
    __syncthreads();

    if (tid < nn) {
        const float* hrow = HO + tid * P;
        float acc = 0.f;
        for (int k = 0; k < D; k++) acc = fmaf(hrow[k], s_hlast[k], acc);
        s_sc[tid] = acc;
    }
    __syncthreads();

    if (tid == 0) {
        float m = -1e30f;
        for (int i = 0; i < nn; i++) m = fmaxf(m, s_sc[i]);
        float sum = 0.f;
        for (int i = 0; i < nn; i++) { float e = expf(s_sc[i] - m); s_sc[i] = e; sum += e; }
        float inv = (sum > 0.f) ? 1.0f / sum : 0.f;
        for (int i = 0; i < nn; i++) s_sc[i] *= inv;
    }
    __syncthreads();

    for (int k = tid; k < D; k += NT) {
        float acc = 0.f;
        for (int i = 0; i < nn; i++) acc = fmaf(s_sc[i], HO[i * P + k], acc);
        s_local[k] = acc;
    }
    __syncthreads();

    // --- h_read = tanh(W_read[:, :256] @ [h_last; local] + b_read) ---
    {
        int w = tid >> 5, l = tid & 31;       // 16 warps, 8 outputs each
        #pragma unroll
        for (int t = 0; t < 8; t++) {
            int j = w * 8 + t;
            const float* wr = W_read + (size_t)j * (3 * D);
            float acc = 0.f;
            for (int k = l; k < D; k += 32)
                acc += wr[k] * s_hlast[k] + wr[D + k] * s_local[k];
            #pragma unroll
            for (int off = 16; off; off >>= 1)
                acc += __shfl_down_sync(0xffffffffu, acc, off);
            if (l == 0) g_hread[b * D + j] = tanhf(acc + b_read[j]);
        }
    }
    if (tid == 0) g_cnt[b] = cnt;
}

// ---------------------------------------------------------------------------
// Kernel B: out[b][n] = cnt[b]>=2 ? h_read[b]·emb[n] : default row.
// Register-tiled SGEMM, BM=64, BN=128, K=128 (full), 256 threads, 4x8 micro.
// ---------------------------------------------------------------------------
#define BM 64
#define BN 128
#define PA 68
#define PB 132

__global__ __launch_bounds__(256) void score_gemm_kernel(
    const float* __restrict__ emb, float* __restrict__ out)
{
    extern __shared__ float sm[];
    float* As = sm;             // [128][PA]  k-major h_read tile
    float* Bs = sm + D * PA;    // [128][PB]  k-major emb tile

    const int tid   = threadIdx.x;
    const int mbase = blockIdx.x * BM;
    const int nbase = blockIdx.y * BN;

    for (int idx = tid; idx < BM * 32; idx += 256) {
        int m = idx >> 5, q = idx & 31;
        float4 v = ((const float4*)(g_hread + (size_t)(mbase + m) * D))[q];
        As[(q * 4 + 0) * PA + m] = v.x;
        As[(q * 4 + 1) * PA + m] = v.y;
        As[(q * 4 + 2) * PA + m] = v.z;
        As[(q * 4 + 3) * PA + m] = v.w;
    }
    for (int idx = tid; idx < BN * 32; idx += 256) {
        int n = idx >> 5, q = idx & 31;
        int item = nbase + n;
        float4 v = make_float4(0.f, 0.f, 0.f, 0.f);
        if (item < NITEMS) v = ((const float4*)(emb + (size_t)item * D))[q];
        Bs[(q * 4 + 0) * PB + n] = v.x;
        Bs[(q * 4 + 1) * PB + n] = v.y;
        Bs[(q * 4 + 2) * PB + n] = v.z;
        Bs[(q * 4 + 3) * PB + n] = v.w;
    }
    __syncthreads();

    const int tx = tid & 15, ty = tid >> 4;
    const int n0 = tx * 8, m0 = ty * 4;

    float acc[4][8];
    #pragma unroll
    for (int i = 0; i < 4; i++)
        #pragma unroll
        for (int j = 0; j < 8; j++) acc[i][j] = 0.f;

    #pragma unroll 8
    for (int k = 0; k < D; k++) {
        float4 av  = *(const float4*)(As + k * PA + m0);
        float4 bv0 = *(const float4*)(Bs + k * PB + n0);
        float4 bv1 = *(const float4*)(Bs + k * PB + n0 + 4);
        float am[4] = {av.x, av.y, av.z, av.w};
        float bn[8] = {bv0.x, bv0.y, bv0.z, bv0.w, bv1.x, bv1.y, bv1.z, bv1.w};
        #pragma unroll
        for (int i = 0; i < 4; i++)
            #pragma unroll
            for (int j = 0; j < 8; j++)
                acc[i][j] = fmaf(am[i], bn[j], acc[i][j]);
    }

    #pragma unroll
    for (int mi = 0; mi < 4; mi++) {
        int m = mbase + m0 + mi;
        bool ok = (g_cnt[m] >= 2);
        #pragma unroll
        for (int q = 0; q < 2; q++) {
            int item = nbase + n0 + q * 4;
            if (item < NITEMS) {
                float4 v;
                if (ok) {
                    v.x = acc[mi][q * 4 + 0]; v.y = acc[mi][q * 4 + 1];
                    v.z = acc[mi][q * 4 + 2]; v.w = acc[mi][q * 4 + 3];
                } else {
                    v.x = (item == 0) ? 0.0f : NEGV;
                    v.y = NEGV; v.z = NEGV; v.w = NEGV;
                }
                *(float4*)(out + (size_t)m * NITEMS + item) = v;
            }
        }
    }
}

// ---------------------------------------------------------------------------
extern "C" void kernel_launch(void* const* d_in, const int* in_sizes, int n_in,
                              void* d_out, int out_size)
{
    const int*   x      = (const int*)  d_in[0];
    // d_in[1] = attn_mask (unused; reference ignores it)
    const float* emb    = (const float*)d_in[2];
    const float* W_in   = (const float*)d_in[3];
    const float* W_out  = (const float*)d_in[4];
    const float* w_ih   = (const float*)d_in[5];
    const float* w_hh   = (const float*)d_in[6];
    const float* b_ih   = (const float*)d_in[7];
    const float* b_hh   = (const float*)d_in[8];
    const float* W_read = (const float*)d_in[9];
    const float* b_read = (const float*)d_in[10];
    float* out = (float*)d_out;

    size_t smA = (size_t)(3 * L * P + 96 * P) * sizeof(float);   // 209,088 B
    cudaFuncSetAttribute(sample_kernel, cudaFuncAttributeMaxDynamicSharedMemorySize, (int)smA);
    sample_kernel<<<BATCH, 512, smA>>>(x, emb, W_in, W_out, w_ih, w_hh,
                                       b_ih, b_hh, W_read, b_read);

    size_t smB = (size_t)(D * PA + D * PB) * sizeof(float);      // 102,400 B
    cudaFuncSetAttribute(score_gemm_kernel, cudaFuncAttributeMaxDynamicSharedMemorySize, (int)smB);
    dim3 gridB(BATCH / BM, (NITEMS + BN - 1) / BN);              // (8, 782)
    score_gemm_kernel<<<gridB, 256, smB>>>(emb, out);
}

// round 6
// speedup vs baseline: 2.0821x; 2.0821x over previous
#include <cuda_runtime.h>
#include <math.h>

#define BATCH  512
#define L      100
#define D      128
#define NITEMS 100000
#define NEGV   -1000000000.0f
#define ROWS   (BATCH * L)          // 51200 padded node rows

// ---- scratch blob offsets (floats) ----
#define OFF_HALL  0
#define OFF_HIO   (ROWS * D)                  // [ROWS][256]  Hin | Hout
#define OFF_X     (OFF_HIO + ROWS * 2 * D)    // [ROWS][128]
#define OFF_GI    (OFF_X + ROWS * D)          // [ROWS][384]
#define OFF_GH    (OFF_GI + ROWS * 3 * D)     // [ROWS][384]
#define OFF_HREAD (OFF_GH + ROWS * 3 * D)     // [512][128]
#define BLOB_SZ   (OFF_HREAD + BATCH * D)

__device__ __align__(128) float g_blob[BLOB_SZ];
__device__ int g_cinv[BATCH * L];
__device__ int g_nn[BATCH];
__device__ int g_cntv[BATCH];
__device__ int g_li[BATCH];

// ---------------------------------------------------------------------------
// K1: per-sample graph build + gather H0 into Hall (zero-padded to 100 rows)
// ---------------------------------------------------------------------------
__global__ __launch_bounds__(256) void build_kernel(
    const int* __restrict__ x, const float* __restrict__ emb)
{
    __shared__ int s_seq[L], s_rep[L], s_nodes[L], s_cinv[L];
    __shared__ int s_nn, s_cnt;
    const int b = blockIdx.x, tid = threadIdx.x;

    if (tid == 0) { s_nn = 0; s_cnt = 0; }
    if (tid < L) { s_seq[tid] = x[b * L + tid]; s_cinv[tid] = 0; }
    __syncthreads();

    int mypos = 0;
    if (tid < L) {
        int s = s_seq[tid];
        int rep = (s != 0);
        for (int j = 0; j < tid; j++) {
            int sj = s_seq[j];
            if (sj != 0) { mypos++; if (sj == s) rep = 0; }
        }
        s_rep[tid] = rep;
    }
    __syncthreads();

    if (tid < L) {
        int s = s_seq[tid];
        if (s != 0) {
            int rank = 0;
            for (int j = 0; j < L; j++)
                if (s_rep[j] && s_seq[j] < s) rank++;
            if (s_rep[tid]) { s_nodes[rank] = s; atomicAdd(&s_nn, 1); }
            s_cinv[mypos] = rank;
            atomicAdd(&s_cnt, 1);
        }
    }
    __syncthreads();

    const int nn = s_nn, cnt = s_cnt;

    float* Hall = g_blob + OFF_HALL + (size_t)b * L * D;
    for (int idx = tid; idx < L * 32; idx += 256) {
        int r = idx >> 5, q = idx & 31;
        float4 v = make_float4(0.f, 0.f, 0.f, 0.f);
        if (r < nn) v = ((const float4*)(emb + (size_t)s_nodes[r] * D))[q];
        ((float4*)(Hall + r * D))[q] = v;
    }
    if (tid < L) g_cinv[b * L + tid] = s_cinv[tid];
    if (tid == 0) {
        g_nn[b] = nn;
        g_cntv[b] = cnt;
        g_li[b] = (cnt > 0) ? s_cinv[cnt - 1] : 0;
    }
}

// ---------------------------------------------------------------------------
// SGEMM template: C[128-tile] = A @ B^T.  A = g_blob+AOFF [.][128] row-major,
// B [N][128] row-major input pointer.  BM=BN=128, BK=16 double-buffered,
// 8x8 micro-tile split 4+4 (conflict-free frag loads), 256 threads.
// SCORE: A = h_read, C = d_out with cnt>=2 masking + default row.
// ---------------------------------------------------------------------------
template<int AOFF, int COFF, int LDC, bool SCORE>
__global__ __launch_bounds__(256, 2) void gemm128(
    const float* __restrict__ Bmat, float* __restrict__ Cout, int Nvalid)
{
    __shared__ float As[2][16][132];
    __shared__ float Bs[2][16][132];

    const int tid = threadIdx.x;
    const int m0  = blockIdx.x * 128;
    const int n0  = blockIdx.y * 128;
    const float* A = g_blob + AOFF;

    const int rowL = tid >> 2;        // 0..63
    const int cq   = tid & 3;
    const float* pA = A + (size_t)(m0 + rowL) * D + cq * 4;
    const float* pB = Bmat + (size_t)(n0 + rowL) * D + cq * 4;
    const bool bok0 = (n0 + rowL) < Nvalid;
    const bool bok1 = (n0 + rowL + 64) < Nvalid;

    const int tx4 = (tid & 15) << 2;
    const int ty4 = (tid >> 4) << 2;

    float acc[8][8];
    #pragma unroll
    for (int i = 0; i < 8; i++)
        #pragma unroll
        for (int j = 0; j < 8; j++) acc[i][j] = 0.f;

    // stage 0
    {
        float4 va0 = *(const float4*)(pA);
        float4 va1 = *(const float4*)(pA + 64 * D);
        float4 vb0 = bok0 ? *(const float4*)(pB) : make_float4(0.f,0.f,0.f,0.f);
        float4 vb1 = bok1 ? *(const float4*)(pB + 64 * D) : make_float4(0.f,0.f,0.f,0.f);
        As[0][cq*4+0][rowL] = va0.x; As[0][cq*4+1][rowL] = va0.y;
        As[0][cq*4+2][rowL] = va0.z; As[0][cq*4+3][rowL] = va0.w;
        As[0][cq*4+0][rowL+64] = va1.x; As[0][cq*4+1][rowL+64] = va1.y;
        As[0][cq*4+2][rowL+64] = va1.z; As[0][cq*4+3][rowL+64] = va1.w;
        Bs[0][cq*4+0][rowL] = vb0.x; Bs[0][cq*4+1][rowL] = vb0.y;
        Bs[0][cq*4+2][rowL] = vb0.z; Bs[0][cq*4+3][rowL] = vb0.w;
        Bs[0][cq*4+0][rowL+64] = vb1.x; Bs[0][cq*4+1][rowL+64] = vb1.y;
        Bs[0][cq*4+2][rowL+64] = vb1.z; Bs[0][cq*4+3][rowL+64] = vb1.w;
    }
    __syncthreads();

    int buf = 0;
    #pragma unroll
    for (int s = 0; s < 8; s++) {
        float4 na0, na1, nb0, nb1;
        if (s < 7) {
            int k0 = (s + 1) * 16;
            na0 = *(const float4*)(pA + k0);
            na1 = *(const float4*)(pA + 64 * D + k0);
            nb0 = bok0 ? *(const float4*)(pB + k0) : make_float4(0.f,0.f,0.f,0.f);
            nb1 = bok1 ? *(const float4*)(pB + 64 * D + k0) : make_float4(0.f,0.f,0.f,0.f);
        }
        #pragma unroll
        for (int k = 0; k < 16; k++) {
            float4 a0 = *(const float4*)&As[buf][k][ty4];
            float4 a1 = *(const float4*)&As[buf][k][ty4 + 64];
            float4 b0 = *(const float4*)&Bs[buf][k][tx4];
            float4 b1 = *(const float4*)&Bs[buf][k][tx4 + 64];
            float av[8] = {a0.x,a0.y,a0.z,a0.w,a1.x,a1.y,a1.z,a1.w};
            float bv[8] = {b0.x,b0.y,b0.z,b0.w,b1.x,b1.y,b1.z,b1.w};
            #pragma unroll
            for (int i = 0; i < 8; i++)
                #pragma unroll
                for (int j = 0; j < 8; j++)
                    acc[i][j] = fmaf(av[i], bv[j], acc[i][j]);
        }
        if (s < 7) {
            int nb = buf ^ 1;
            As[nb][cq*4+0][rowL] = na0.x; As[nb][cq*4+1][rowL] = na0.y;
            As[nb][cq*4+2][rowL] = na0.z; As[nb][cq*4+3][rowL] = na0.w;
            As[nb][cq*4+0][rowL+64] = na1.x; As[nb][cq*4+1][rowL+64] = na1.y;
            As[nb][cq*4+2][rowL+64] = na1.z; As[nb][cq*4+3][rowL+64] = na1.w;
            Bs[nb][cq*4+0][rowL] = nb0.x; Bs[nb][cq*4+1][rowL] = nb0.y;
            Bs[nb][cq*4+2][rowL] = nb0.z; Bs[nb][cq*4+3][rowL] = nb0.w;
            Bs[nb][cq*4+0][rowL+64] = nb1.x; Bs[nb][cq*4+1][rowL+64] = nb1.y;
            Bs[nb][cq*4+2][rowL+64] = nb1.z; Bs[nb][cq*4+3][rowL+64] = nb1.w;
            __syncthreads();
            buf = nb;
        }
    }

    // epilogue
    #pragma unroll
    for (int gi_ = 0; gi_ < 2; gi_++) {
        #pragma unroll
        for (int i = 0; i < 4; i++) {
            int m = m0 + gi_ * 64 + ty4 + i;
            bool ok = true;
            if (SCORE) ok = (g_cntv[m] >= 2);
            #pragma unroll
            for (int gj = 0; gj < 2; gj++) {
                int n = n0 + gj * 64 + tx4;
                float4 v;
                v.x = acc[gi_*4+i][gj*4+0];
                v.y = acc[gi_*4+i][gj*4+1];
                v.z = acc[gi_*4+i][gj*4+2];
                v.w = acc[gi_*4+i][gj*4+3];
                if (SCORE) {
                    if (n < Nvalid) {
                        if (!ok) {
                            v.x = (n == 0) ? 0.0f : NEGV;
                            v.y = NEGV; v.z = NEGV; v.w = NEGV;
                        }
                        *(float4*)&Cout[(size_t)m * NITEMS + n] = v;
                    }
                } else {
                    float* C = g_blob + COFF;
                    *(float4*)&C[(size_t)m * LDC + n] = v;
                }
            }
        }
    }
}

// ---------------------------------------------------------------------------
// K3: per-sample edge aggregation.  X = Hin + agg(Hout[src])/deg
// ---------------------------------------------------------------------------
__global__ __launch_bounds__(256) void agg_kernel()
{
    extern __shared__ float agg[];            // L*D floats
    __shared__ int   cinv[L];
    __shared__ float rdeg[L];
    const int b = blockIdx.x, tid = threadIdx.x;

    if (tid < L) { cinv[tid] = g_cinv[b * L + tid]; rdeg[tid] = 0.f; }
    for (int i = tid; i < L * D / 4; i += 256)
        ((float4*)agg)[i] = make_float4(0.f, 0.f, 0.f, 0.f);
    __syncthreads();

    const int cnt = g_cntv[b];
    if (tid < cnt - 1) atomicAdd(&rdeg[cinv[tid + 1]], 1.0f);
    __syncthreads();
    if (tid < L) rdeg[tid] = 1.0f / fmaxf(rdeg[tid], 1.0f);

    const float* Hio = g_blob + OFF_HIO + (size_t)b * L * 2 * D;
    const int nedge = (cnt >= 1) ? cnt - 1 : 0;
    for (int idx = tid; idx < nedge * D; idx += 256) {
        int t = idx >> 7, k = idx & 127;
        atomicAdd(&agg[cinv[t + 1] * D + k], Hio[(size_t)cinv[t] * 2 * D + D + k]);
    }
    __syncthreads();

    float* X = g_blob + OFF_X + (size_t)b * L * D;
    for (int idx = tid; idx < L * D; idx += 256) {
        int r = idx >> 7;
        X[idx] = Hio[(size_t)r * 2 * D + (idx & 127)] + agg[idx] * rdeg[r];
    }
}

// ---------------------------------------------------------------------------
// K4: elementwise GRU, Hall updated in place
// ---------------------------------------------------------------------------
__global__ __launch_bounds__(256) void gru_kernel(
    const float* __restrict__ b_ih, const float* __restrict__ b_hh)
{
    int idx = blockIdx.x * 256 + threadIdx.x;          // < ROWS*D
    int row = idx >> 7, j = idx & 127;
    const float* gi = g_blob + OFF_GI + (size_t)row * 3 * D;
    const float* gh = g_blob + OFF_GH + (size_t)row * 3 * D;
    float gir = gi[j]         + b_ih[j];
    float giz = gi[D + j]     + b_ih[D + j];
    float gin = gi[2 * D + j] + b_ih[2 * D + j];
    float ghr = gh[j]         + b_hh[j];
    float ghz = gh[D + j]     + b_hh[D + j];
    float ghn = gh[2 * D + j] + b_hh[2 * D + j];
    float h0 = g_blob[OFF_HALL + idx];
    float r = 1.0f / (1.0f + expf(-(gir + ghr)));
    float z = 1.0f / (1.0f + expf(-(giz + ghz)));
    float n = tanhf(gin + r * ghn);
    g_blob[OFF_HALL + idx] = (1.0f - z) * n + z * h0;
}

// ---------------------------------------------------------------------------
// K5: attention readout -> h_read
// ---------------------------------------------------------------------------
__global__ __launch_bounds__(256) void attn_kernel(
    const float* __restrict__ W_read, const float* __restrict__ b_read)
{
    __shared__ float hlast[D], loc[D], sc[L];
    const int b = blockIdx.x, tid = threadIdx.x;
    const int nn = g_nn[b], li = g_li[b];
    const float* H = g_blob + OFF_HALL + (size_t)b * L * D;

    if (tid < D) hlast[tid] = H[(size_t)li * D + tid];
    __syncthreads();

    const int w = tid >> 5, lane = tid & 31;
    for (int r = w; r < nn; r += 8) {
        const float* hr = H + (size_t)r * D;
        float acc = 0.f;
        #pragma unroll
        for (int k = lane; k < D; k += 32) acc = fmaf(hr[k], hlast[k], acc);
        #pragma unroll
        for (int off = 16; off; off >>= 1)
            acc += __shfl_down_sync(0xffffffffu, acc, off);
        if (lane == 0) sc[r] = acc;
    }
    __syncthreads();

    if (tid == 0) {
        float m = -1e30f;
        for (int i = 0; i < nn; i++) m = fmaxf(m, sc[i]);
        float s = 0.f;
        for (int i = 0; i < nn; i++) { float e = expf(sc[i] - m); sc[i] = e; s += e; }
        float inv = (s > 0.f) ? 1.0f / s : 0.f;
        for (int i = 0; i < nn; i++) sc[i] *= inv;
    }
    __syncthreads();

    if (tid < D) {
        float acc = 0.f;
        for (int r = 0; r < nn; r++) acc = fmaf(sc[r], H[(size_t)r * D + tid], acc);
        loc[tid] = acc;
    }
    __syncthreads();

    #pragma unroll
    for (int t = 0; t < 16; t++) {
        int j = w * 16 + t;
        const float* wr = W_read + (size_t)j * (3 * D);
        float acc = 0.f;
        #pragma unroll
        for (int k = lane; k < D; k += 32)
            acc += wr[k] * hlast[k] + wr[D + k] * loc[k];
        #pragma unroll
        for (int off = 16; off; off >>= 1)
            acc += __shfl_down_sync(0xffffffffu, acc, off);
        if (lane == 0) g_blob[OFF_HREAD + b * D + j] = tanhf(acc + b_read[j]);
    }
}

// ---------------------------------------------------------------------------
extern "C" void kernel_launch(void* const* d_in, const int* in_sizes, int n_in,
                              void* d_out, int out_size)
{
    const int*   x      = (const int*)  d_in[0];
    // d_in[1] = attn_mask (unused by reference)
    const float* emb    = (const float*)d_in[2];
    const float* W_in   = (const float*)d_in[3];
    const float* W_out  = (const float*)d_in[4];
    const float* w_ih   = (const float*)d_in[5];
    const float* w_hh   = (const float*)d_in[6];
    const float* b_ih   = (const float*)d_in[7];
    const float* b_hh   = (const float*)d_in[8];
    const float* W_read = (const float*)d_in[9];
    const float* b_read = (const float*)d_in[10];
    float* out = (float*)d_out;

    cudaFuncSetAttribute(agg_kernel,
        cudaFuncAttributeMaxDynamicSharedMemorySize, L * D * (int)sizeof(float));

    // K1: graph build + gather
    build_kernel<<<BATCH, 256>>>(x, emb);

    // G1: Hin | Hout = Hall @ {W_in, W_out}^T
    gemm128<OFF_HALL, OFF_HIO,       2*D, false><<<dim3(ROWS/128, 1), 256>>>(W_in,  nullptr, D);
    gemm128<OFF_HALL, OFF_HIO + D,   2*D, false><<<dim3(ROWS/128, 1), 256>>>(W_out, nullptr, D);

    // G2: gh = Hall @ w_hh^T
    gemm128<OFF_HALL, OFF_GH, 3*D, false><<<dim3(ROWS/128, 3), 256>>>(w_hh, nullptr, 3*D);

    // K3: X = Hin + agg/deg
    agg_kernel<<<BATCH, 256, L * D * sizeof(float)>>>();

    // G3: gi = X @ w_ih^T
    gemm128<OFF_X, OFF_GI, 3*D, false><<<dim3(ROWS/128, 3), 256>>>(w_ih, nullptr, 3*D);

    // K4: GRU elementwise (Hall <- H)
    gru_kernel<<<(ROWS * D) / 256, 256>>>(b_ih, b_hh);

    // K5: attention -> h_read
    attn_kernel<<<BATCH, 256>>>(W_read, b_read);

    // K6: scores = h_read @ emb^T  (with cnt<2 default rows)
    gemm128<OFF_HREAD, 0, 1, true><<<dim3(BATCH/128, (NITEMS + 127)/128), 256>>>(emb, out, NITEMS);
}

// round 7
// speedup vs baseline: 3.1058x; 1.4916x over previous
#include <cuda_runtime.h>
#include <math.h>

#define BATCH  512
#define L      100
#define D      128
#define NITEMS 100000
#define NEGV   -1000000000.0f
#define ROWS   (BATCH * L)          // 51200 padded node rows

// ---- scratch blob offsets (floats) ----
#define OFF_HALL  0
#define OFF_HIO   (ROWS * D)                  // [ROWS][256]  Hin | Hout
#define OFF_X     (OFF_HIO + ROWS * 2 * D)    // [ROWS][128]
#define OFF_GI    (OFF_X + ROWS * D)          // [ROWS][384]
#define OFF_GH    (OFF_GI + ROWS * 3 * D)     // [ROWS][384]
#define OFF_HREAD (OFF_GH + ROWS * 3 * D)     // [512][128]
#define BLOB_SZ   (OFF_HREAD + BATCH * D)

__device__ __align__(128) float g_blob[BLOB_SZ];
__device__ int g_cinv[BATCH * L];
__device__ int g_nn[BATCH];
__device__ int g_cntv[BATCH];
__device__ int g_li[BATCH];

typedef unsigned long long u64;

// packed f32x2 helpers (sm_103a FFMA2 path — not emitted by ptxas from C++)
__device__ __forceinline__ u64 pack2(float v) {
    u64 r;
    asm("mov.b64 %0, {%1, %1};" : "=l"(r) : "f"(v));
    return r;
}
__device__ __forceinline__ void ffma2(u64& d, u64 a, u64 b) {
    asm("fma.rn.f32x2 %0, %1, %2, %0;" : "+l"(d) : "l"(a), "l"(b));
}
__device__ __forceinline__ float lo32(u64 v) { return __uint_as_float((unsigned)v); }
__device__ __forceinline__ float hi32(u64 v) { return __uint_as_float((unsigned)(v >> 32)); }

// ---------------------------------------------------------------------------
// K1: per-sample graph build + gather H0 into Hall (zero-padded to 100 rows)
// ---------------------------------------------------------------------------
__global__ __launch_bounds__(256) void build_kernel(
    const int* __restrict__ x, const float* __restrict__ emb)
{
    __shared__ int s_seq[L], s_rep[L], s_nodes[L], s_cinv[L];
    __shared__ int s_nn, s_cnt;
    const int b = blockIdx.x, tid = threadIdx.x;

    if (tid == 0) { s_nn = 0; s_cnt = 0; }
    if (tid < L) { s_seq[tid] = x[b * L + tid]; s_cinv[tid] = 0; }
    __syncthreads();

    int mypos = 0;
    if (tid < L) {
        int s = s_seq[tid];
        int rep = (s != 0);
        for (int j = 0; j < tid; j++) {
            int sj = s_seq[j];
            if (sj != 0) { mypos++; if (sj == s) rep = 0; }
        }
        s_rep[tid] = rep;
    }
    __syncthreads();

    if (tid < L) {
        int s = s_seq[tid];
        if (s != 0) {
            int rank = 0;
            for (int j = 0; j < L; j++)
                if (s_rep[j] && s_seq[j] < s) rank++;
            if (s_rep[tid]) { s_nodes[rank] = s; atomicAdd(&s_nn, 1); }
            s_cinv[mypos] = rank;
            atomicAdd(&s_cnt, 1);
        }
    }
    __syncthreads();

    const int nn = s_nn, cnt = s_cnt;

    float* Hall = g_blob + OFF_HALL + (size_t)b * L * D;
    for (int idx = tid; idx < L * 32; idx += 256) {
        int r = idx >> 5, q = idx & 31;
        float4 v = make_float4(0.f, 0.f, 0.f, 0.f);
        if (r < nn) v = ((const float4*)(emb + (size_t)s_nodes[r] * D))[q];
        ((float4*)(Hall + r * D))[q] = v;
    }
    if (tid < L) g_cinv[b * L + tid] = s_cinv[tid];
    if (tid == 0) {
        g_nn[b] = nn;
        g_cntv[b] = cnt;
        g_li[b] = (cnt > 0) ? s_cinv[cnt - 1] : 0;
    }
}

// ---------------------------------------------------------------------------
// SGEMM template: C[128-tile] = A @ B^T with packed-f32x2 FFMA2 micro-kernel.
// A = g_blob+AOFF [.][128] row-major, B [N][128] row-major input pointer.
// BM=BN=128, BK=16 double-buffered, 8x(4xf32x2) micro-tile, 256 threads.
// SCORE: A = h_read, C = d_out with cnt>=2 masking + default row.
// ---------------------------------------------------------------------------
template<int AOFF, int COFF, int LDC, bool SCORE>
__global__ __launch_bounds__(256, 2) void gemm128(
    const float* __restrict__ Bmat, float* __restrict__ Cout, int Nvalid)
{
    __shared__ float As[2][16][132];
    __shared__ float Bs[2][16][132];

    const int tid = threadIdx.x;
    const int m0  = blockIdx.x * 128;
    const int n0  = blockIdx.y * 128;
    const float* A = g_blob + AOFF;

    const int rowL = tid >> 2;        // 0..63
    const int cq   = tid & 3;
    const float* pA = A + (size_t)(m0 + rowL) * D + cq * 4;
    const float* pB = Bmat + (size_t)(n0 + rowL) * D + cq * 4;
    const bool bok0 = (n0 + rowL) < Nvalid;
    const bool bok1 = (n0 + rowL + 64) < Nvalid;

    const int tx4 = (tid & 15) << 2;
    const int ty4 = (tid >> 4) << 2;

    // packed accumulators: acc[i][jp], jp = gj*2 + p covers cols gj*64+tx4+2p+{0,1}
    u64 acc[8][4];
    #pragma unroll
    for (int i = 0; i < 8; i++)
        #pragma unroll
        for (int j = 0; j < 4; j++) acc[i][j] = 0ull;

    // stage 0
    {
        float4 va0 = *(const float4*)(pA);
        float4 va1 = *(const float4*)(pA + 64 * D);
        float4 vb0 = bok0 ? *(const float4*)(pB) : make_float4(0.f,0.f,0.f,0.f);
        float4 vb1 = bok1 ? *(const float4*)(pB + 64 * D) : make_float4(0.f,0.f,0.f,0.f);
        As[0][cq*4+0][rowL] = va0.x; As[0][cq*4+1][rowL] = va0.y;
        As[0][cq*4+2][rowL] = va0.z; As[0][cq*4+3][rowL] = va0.w;
        As[0][cq*4+0][rowL+64] = va1.x; As[0][cq*4+1][rowL+64] = va1.y;
        As[0][cq*4+2][rowL+64] = va1.z; As[0][cq*4+3][rowL+64] = va1.w;
        Bs[0][cq*4+0][rowL] = vb0.x; Bs[0][cq*4+1][rowL] = vb0.y;
        Bs[0][cq*4+2][rowL] = vb0.z; Bs[0][cq*4+3][rowL] = vb0.w;
        Bs[0][cq*4+0][rowL+64] = vb1.x; Bs[0][cq*4+1][rowL+64] = vb1.y;
        Bs[0][cq*4+2][rowL+64] = vb1.z; Bs[0][cq*4+3][rowL+64] = vb1.w;
    }
    __syncthreads();

    int buf = 0;
    #pragma unroll
    for (int s = 0; s < 8; s++) {
        float4 na0, na1, nb0, nb1;
        if (s < 7) {
            int k0 = (s + 1) * 16;
            na0 = *(const float4*)(pA + k0);
            na1 = *(const float4*)(pA + 64 * D + k0);
            nb0 = bok0 ? *(const float4*)(pB + k0) : make_float4(0.f,0.f,0.f,0.f);
            nb1 = bok1 ? *(const float4*)(pB + 64 * D + k0) : make_float4(0.f,0.f,0.f,0.f);
        }
        #pragma unroll
        for (int k = 0; k < 16; k++) {
            float4 a0 = *(const float4*)&As[buf][k][ty4];
            float4 a1 = *(const float4*)&As[buf][k][ty4 + 64];
            // B fragments as bit-packed f32x2 pairs straight from SMEM
            double2 q0 = *(const double2*)&Bs[buf][k][tx4];
            double2 q1 = *(const double2*)&Bs[buf][k][tx4 + 64];
            u64 bv[4];
            bv[0] = __double_as_longlong(q0.x);
            bv[1] = __double_as_longlong(q0.y);
            bv[2] = __double_as_longlong(q1.x);
            bv[3] = __double_as_longlong(q1.y);
            float av[8] = {a0.x,a0.y,a0.z,a0.w,a1.x,a1.y,a1.z,a1.w};
            #pragma unroll
            for (int i = 0; i < 8; i++) {
                u64 a2 = pack2(av[i]);
                #pragma unroll
                for (int j = 0; j < 4; j++)
                    ffma2(acc[i][j], a2, bv[j]);
            }
        }
        if (s < 7) {
            int nb = buf ^ 1;
            As[nb][cq*4+0][rowL] = na0.x; As[nb][cq*4+1][rowL] = na0.y;
            As[nb][cq*4+2][rowL] = na0.z; As[nb][cq*4+3][rowL] = na0.w;
            As[nb][cq*4+0][rowL+64] = na1.x; As[nb][cq*4+1][rowL+64] = na1.y;
            As[nb][cq*4+2][rowL+64] = na1.z; As[nb][cq*4+3][rowL+64] = na1.w;
            Bs[nb][cq*4+0][rowL] = nb0.x; Bs[nb][cq*4+1][rowL] = nb0.y;
            Bs[nb][cq*4+2][rowL] = nb0.z; Bs[nb][cq*4+3][rowL] = nb0.w;
            Bs[nb][cq*4+0][rowL+64] = nb1.x; Bs[nb][cq*4+1][rowL+64] = nb1.y;
            Bs[nb][cq*4+2][rowL+64] = nb1.z; Bs[nb][cq*4+3][rowL+64] = nb1.w;
            __syncthreads();
            buf = nb;
        }
    }

    // epilogue
    #pragma unroll
    for (int gi_ = 0; gi_ < 2; gi_++) {
        #pragma unroll
        for (int i = 0; i < 4; i++) {
            int m = m0 + gi_ * 64 + ty4 + i;
            bool ok = true;
            if (SCORE) ok = (g_cntv[m] >= 2);
            #pragma unroll
            for (int gj = 0; gj < 2; gj++) {
                int n = n0 + gj * 64 + tx4;
                u64 p0 = acc[gi_*4+i][gj*2+0];
                u64 p1 = acc[gi_*4+i][gj*2+1];
                float4 v;
                v.x = lo32(p0); v.y = hi32(p0);
                v.z = lo32(p1); v.w = hi32(p1);
                if (SCORE) {
                    if (n < Nvalid) {
                        if (!ok) {
                            v.x = (n == 0) ? 0.0f : NEGV;
                            v.y = NEGV; v.z = NEGV; v.w = NEGV;
                        }
                        *(float4*)&Cout[(size_t)m * NITEMS + n] = v;
                    }
                } else {
                    float* C = g_blob + COFF;
                    *(float4*)&C[(size_t)m * LDC + n] = v;
                }
            }
        }
    }
}

// ---------------------------------------------------------------------------
// K3: per-sample edge aggregation.  X = Hin + agg(Hout[src])/deg
// ---------------------------------------------------------------------------
__global__ __launch_bounds__(256) void agg_kernel()
{
    extern __shared__ float agg[];            // L*D floats
    __shared__ int   cinv[L];
    __shared__ float rdeg[L];
    const int b = blockIdx.x, tid = threadIdx.x;

    if (tid < L) { cinv[tid] = g_cinv[b * L + tid]; rdeg[tid] = 0.f; }
    for (int i = tid; i < L * D / 4; i += 256)
        ((float4*)agg)[i] = make_float4(0.f, 0.f, 0.f, 0.f);
    __syncthreads();

    const int cnt = g_cntv[b];
    if (tid < cnt - 1) atomicAdd(&rdeg[cinv[tid + 1]], 1.0f);
    __syncthreads();
    if (tid < L) rdeg[tid] = 1.0f / fmaxf(rdeg[tid], 1.0f);

    const float* Hio = g_blob + OFF_HIO + (size_t)b * L * 2 * D;
    const int nedge = (cnt >= 1) ? cnt - 1 : 0;
    for (int idx = tid; idx < nedge * D; idx += 256) {
        int t = idx >> 7, k = idx & 127;
        atomicAdd(&agg[cinv[t + 1] * D + k], Hio[(size_t)cinv[t] * 2 * D + D + k]);
    }
    __syncthreads();

    float* X = g_blob + OFF_X + (size_t)b * L * D;
    for (int idx = tid; idx < L * D; idx += 256) {
        int r = idx >> 7;
        X[idx] = Hio[(size_t)r * 2 * D + (idx & 127)] + agg[idx] * rdeg[r];
    }
}

// ---------------------------------------------------------------------------
// K4: elementwise GRU, Hall updated in place
// ---------------------------------------------------------------------------
__global__ __launch_bounds__(256) void gru_kernel(
    const float* __restrict__ b_ih, const float* __restrict__ b_hh)
{
    int idx = blockIdx.x * 256 + threadIdx.x;          // < ROWS*D
    int row = idx >> 7, j = idx & 127;
    const float* gi = g_blob + OFF_GI + (size_t)row * 3 * D;
    const float* gh = g_blob + OFF_GH + (size_t)row * 3 * D;
    float gir = gi[j]         + b_ih[j];
    float giz = gi[D + j]     + b_ih[D + j];
    float gin = gi[2 * D + j] + b_ih[2 * D + j];
    float ghr = gh[j]         + b_hh[j];
    float ghz = gh[D + j]     + b_hh[D + j];
    float ghn = gh[2 * D + j] + b_hh[2 * D + j];
    float h0 = g_blob[OFF_HALL + idx];
    float r = 1.0f / (1.0f + expf(-(gir + ghr)));
    float z = 1.0f / (1.0f + expf(-(giz + ghz)));
    float n = tanhf(gin + r * ghn);
    g_blob[OFF_HALL + idx] = (1.0f - z) * n + z * h0;
}

// ---------------------------------------------------------------------------
// K5: attention readout -> h_read
// ---------------------------------------------------------------------------
__global__ __launch_bounds__(256) void attn_kernel(
    const float* __restrict__ W_read, const float* __restrict__ b_read)
{
    __shared__ float hlast[D], loc[D], sc[L];
    const int b = blockIdx.x, tid = threadIdx.x;
    const int nn = g_nn[b], li = g_li[b];
    const float* H = g_blob + OFF_HALL + (size_t)b * L * D;

    if (tid < D) hlast[tid] = H[(size_t)li * D + tid];
    __syncthreads();

    const int w = tid >> 5, lane = tid & 31;
    for (int r = w; r < nn; r += 8) {
        const float* hr = H + (size_t)r * D;
        float acc = 0.f;
        #pragma unroll
        for (int k = lane; k < D; k += 32) acc = fmaf(hr[k], hlast[k], acc);
        #pragma unroll
        for (int off = 16; off; off >>= 1)
            acc += __shfl_down_sync(0xffffffffu, acc, off);
        if (lane == 0) sc[r] = acc;
    }
    __syncthreads();

    if (tid == 0) {
        float m = -1e30f;
        for (int i = 0; i < nn; i++) m = fmaxf(m, sc[i]);
        float s = 0.f;
        for (int i = 0; i < nn; i++) { float e = expf(sc[i] - m); sc[i] = e; s += e; }
        float inv = (s > 0.f) ? 1.0f / s : 0.f;
        for (int i = 0; i < nn; i++) sc[i] *= inv;
    }
    __syncthreads();

    if (tid < D) {
        float acc = 0.f;
        for (int r = 0; r < nn; r++) acc = fmaf(sc[r], H[(size_t)r * D + tid], acc);
        loc[tid] = acc;
    }
    __syncthreads();

    #pragma unroll
    for (int t = 0; t < 16; t++) {
        int j = w * 16 + t;
        const float* wr = W_read + (size_t)j * (3 * D);
        float acc = 0.f;
        #pragma unroll
        for (int k = lane; k < D; k += 32)
            acc += wr[k] * hlast[k] + wr[D + k] * loc[k];
        #pragma unroll
        for (int off = 16; off; off >>= 1)
            acc += __shfl_down_sync(0xffffffffu, acc, off);
        if (lane == 0) g_blob[OFF_HREAD + b * D + j] = tanhf(acc + b_read[j]);
    }
}

// ---------------------------------------------------------------------------
extern "C" void kernel_launch(void* const* d_in, const int* in_sizes, int n_in,
                              void* d_out, int out_size)
{
    const int*   x      = (const int*)  d_in[0];
    // d_in[1] = attn_mask (unused by reference)
    const float* emb    = (const float*)d_in[2];
    const float* W_in   = (const float*)d_in[3];
    const float* W_out  = (const float*)d_in[4];
    const float* w_ih   = (const float*)d_in[5];
    const float* w_hh   = (const float*)d_in[6];
    const float* b_ih   = (const float*)d_in[7];
    const float* b_hh   = (const float*)d_in[8];
    const float* W_read = (const float*)d_in[9];
    const float* b_read = (const float*)d_in[10];
    float* out = (float*)d_out;

    cudaFuncSetAttribute(agg_kernel,
        cudaFuncAttributeMaxDynamicSharedMemorySize, L * D * (int)sizeof(float));

    // K1: graph build + gather
    build_kernel<<<BATCH, 256>>>(x, emb);

    // G1: Hin | Hout = Hall @ {W_in, W_out}^T
    gemm128<OFF_HALL, OFF_HIO,       2*D, false><<<dim3(ROWS/128, 1), 256>>>(W_in,  nullptr, D);
    gemm128<OFF_HALL, OFF_HIO + D,   2*D, false><<<dim3(ROWS/128, 1), 256>>>(W_out, nullptr, D);

    // G2: gh = Hall @ w_hh^T
    gemm128<OFF_HALL, OFF_GH, 3*D, false><<<dim3(ROWS/128, 3), 256>>>(w_hh, nullptr, 3*D);

    // K3: X = Hin + agg/deg
    agg_kernel<<<BATCH, 256, L * D * sizeof(float)>>>();

    // G3: gi = X @ w_ih^T
    gemm128<OFF_X, OFF_GI, 3*D, false><<<dim3(ROWS/128, 3), 256>>>(w_ih, nullptr, 3*D);

    // K4: GRU elementwise (Hall <- H)
    gru_kernel<<<(ROWS * D) / 256, 256>>>(b_ih, b_hh);

    // K5: attention -> h_read
    attn_kernel<<<BATCH, 256>>>(W_read, b_read);

    // K6: scores = h_read @ emb^T  (with cnt<2 default rows)
    gemm128<OFF_HREAD, 0, 1, true><<<dim3(BATCH/128, (NITEMS + 127)/128), 256>>>(emb, out, NITEMS);
}

// round 10
// speedup vs baseline: 3.4604x; 1.1142x over previous
#include <cuda_runtime.h>
#include <cuda_bf16.h>
#include <math.h>

#define BATCH  512
#define L      100
#define D      128
#define NITEMS 100000
#define NEGV   -1000000000.0f
#define ROWS   (BATCH * L)          // 51200 padded node rows

// ---- scratch blob offsets (floats) ----
#define OFF_HALL  0
#define OFF_HIO   (ROWS * D)                  // [ROWS][256]  Hin | Hout
#define OFF_X     (OFF_HIO + ROWS * 2 * D)    // [ROWS][128]
#define OFF_GI    (OFF_X + ROWS * D)          // [ROWS][384]
#define OFF_GH    (OFF_GI + ROWS * 3 * D)     // [ROWS][384]
#define BLOB_SZ   (OFF_GH + ROWS * 3 * D)

__device__ __align__(128) float g_blob[BLOB_SZ];
__device__ int g_cinv[BATCH * L];
__device__ int g_nn[BATCH];
__device__ int g_cntv[BATCH];
__device__ int g_li[BATCH];

// bf16 hi/lo split operands for the tensor-core score GEMM
__device__ __align__(16) __nv_bfloat16 g_ehi[NITEMS * D];
__device__ __align__(16) __nv_bfloat16 g_elo[NITEMS * D];
__device__ __align__(16) __nv_bfloat16 g_ahi[BATCH * D];
__device__ __align__(16) __nv_bfloat16 g_alo[BATCH * D];

typedef unsigned long long u64;

// packed f32x2 helpers (sm_103a FFMA2 path — not emitted by ptxas from C++)
__device__ __forceinline__ u64 pack2(float v) {
    u64 r;
    asm("mov.b64 %0, {%1, %1};" : "=l"(r) : "f"(v));
    return r;
}
__device__ __forceinline__ void ffma2(u64& d, u64 a, u64 b) {
    asm("fma.rn.f32x2 %0, %1, %2, %0;" : "+l"(d) : "l"(a), "l"(b));
}
__device__ __forceinline__ float lo32(u64 v) { return __uint_as_float((unsigned)v); }
__device__ __forceinline__ float hi32(u64 v) { return __uint_as_float((unsigned)(v >> 32)); }

// ---- smem / warp-mma helpers (arch-generic PTX: sm_80+) ----
__device__ __forceinline__ unsigned smem_u32(const void* p) {
    unsigned a;
    asm("{ .reg .u64 t; cvta.to.shared.u64 t, %1; cvt.u32.u64 %0, t; }" : "=r"(a) : "l"(p));
    return a;
}
__device__ __forceinline__ void sts128(unsigned addr, uint4 v) {
    asm volatile("st.shared.v4.b32 [%0], {%1,%2,%3,%4};"
                 :: "r"(addr), "r"(v.x), "r"(v.y), "r"(v.z), "r"(v.w));
}
__device__ __forceinline__ void ldm4(unsigned& r0, unsigned& r1,
                                     unsigned& r2, unsigned& r3, unsigned addr) {
    asm volatile("ldmatrix.sync.aligned.m8n8.x4.shared.b16 {%0,%1,%2,%3}, [%4];"
                 : "=r"(r0), "=r"(r1), "=r"(r2), "=r"(r3) : "r"(addr));
}
__device__ __forceinline__ void mma16816(float* c, const unsigned* a, const unsigned* b) {
    asm volatile("mma.sync.aligned.m16n8k16.row.col.f32.bf16.bf16.f32 "
                 "{%0,%1,%2,%3}, {%4,%5,%6,%7}, {%8,%9}, {%0,%1,%2,%3};"
                 : "+f"(c[0]), "+f"(c[1]), "+f"(c[2]), "+f"(c[3])
                 : "r"(a[0]), "r"(a[1]), "r"(a[2]), "r"(a[3]),
                   "r"(b[0]), "r"(b[1]));
}

// ---------------------------------------------------------------------------
// K0: emb -> bf16 hi/lo split
// ---------------------------------------------------------------------------
__global__ __launch_bounds__(256) void conv_emb_kernel(const float* __restrict__ emb)
{
    size_t i = (size_t)blockIdx.x * 256 + threadIdx.x;   // one float4 group
    float4 v = ((const float4*)emb)[i];
    __nv_bfloat162 h01 = __floats2bfloat162_rn(v.x, v.y);
    __nv_bfloat162 h23 = __floats2bfloat162_rn(v.z, v.w);
    __nv_bfloat162 l01 = __floats2bfloat162_rn(v.x - __low2float(h01), v.y - __high2float(h01));
    __nv_bfloat162 l23 = __floats2bfloat162_rn(v.z - __low2float(h23), v.w - __high2float(h23));
    ((__nv_bfloat162*)g_ehi)[2 * i]     = h01;
    ((__nv_bfloat162*)g_ehi)[2 * i + 1] = h23;
    ((__nv_bfloat162*)g_elo)[2 * i]     = l01;
    ((__nv_bfloat162*)g_elo)[2 * i + 1] = l23;
}

// ---------------------------------------------------------------------------
// K1: per-sample graph build + gather H0 into Hall (zero-padded to 100 rows)
// ---------------------------------------------------------------------------
__global__ __launch_bounds__(256) void build_kernel(
    const int* __restrict__ x, const float* __restrict__ emb)
{
    __shared__ int s_seq[L], s_rep[L], s_nodes[L], s_cinv[L];
    __shared__ int s_nn, s_cnt;
    const int b = blockIdx.x, tid = threadIdx.x;

    if (tid == 0) { s_nn = 0; s_cnt = 0; }
    if (tid < L) { s_seq[tid] = x[b * L + tid]; s_cinv[tid] = 0; }
    __syncthreads();

    int mypos = 0;
    if (tid < L) {
        int s = s_seq[tid];
        int rep = (s != 0);
        for (int j = 0; j < tid; j++) {
            int sj = s_seq[j];
            if (sj != 0) { mypos++; if (sj == s) rep = 0; }
        }
        s_rep[tid] = rep;
    }
    __syncthreads();

    if (tid < L) {
        int s = s_seq[tid];
        if (s != 0) {
            int rank = 0;
            for (int j = 0; j < L; j++)
                if (s_rep[j] && s_seq[j] < s) rank++;
            if (s_rep[tid]) { s_nodes[rank] = s; atomicAdd(&s_nn, 1); }
            s_cinv[mypos] = rank;
            atomicAdd(&s_cnt, 1);
        }
    }
    __syncthreads();

    const int nn = s_nn, cnt = s_cnt;

    float* Hall = g_blob + OFF_HALL + (size_t)b * L * D;
    for (int idx = tid; idx < L * 32; idx += 256) {
        int r = idx >> 5, q = idx & 31;
        float4 v = make_float4(0.f, 0.f, 0.f, 0.f);
        if (r < nn) v = ((const float4*)(emb + (size_t)s_nodes[r] * D))[q];
        ((float4*)(Hall + r * D))[q] = v;
    }
    if (tid < L) g_cinv[b * L + tid] = s_cinv[tid];
    if (tid == 0) {
        g_nn[b] = nn;
        g_cntv[b] = cnt;
        g_li[b] = (cnt > 0) ? s_cinv[cnt - 1] : 0;
    }
}

// ---------------------------------------------------------------------------
// SGEMM template (FFMA2): C[128-tile] = A @ B^T (internal GEMMs)
// ---------------------------------------------------------------------------
template<int AOFF, int COFF, int LDC>
__global__ __launch_bounds__(256, 2) void gemm128(
    const float* __restrict__ Bmat, float* __restrict__ Cout, int Nvalid)
{
    __shared__ float As[2][16][132];
    __shared__ float Bs[2][16][132];

    const int tid = threadIdx.x;
    const int m0  = blockIdx.x * 128;
    const int n0  = blockIdx.y * 128;
    const float* A = g_blob + AOFF;

    const int rowL = tid >> 2;        // 0..63
    const int cq   = tid & 3;
    const float* pA = A + (size_t)(m0 + rowL) * D + cq * 4;
    const float* pB = Bmat + (size_t)(n0 + rowL) * D + cq * 4;
    const bool bok0 = (n0 + rowL) < Nvalid;
    const bool bok1 = (n0 + rowL + 64) < Nvalid;

    const int tx4 = (tid & 15) << 2;
    const int ty4 = (tid >> 4) << 2;

    u64 acc[8][4];
    #pragma unroll
    for (int i = 0; i < 8; i++)
        #pragma unroll
        for (int j = 0; j < 4; j++) acc[i][j] = 0ull;

    {
        float4 va0 = *(const float4*)(pA);
        float4 va1 = *(const float4*)(pA + 64 * D);
        float4 vb0 = bok0 ? *(const float4*)(pB) : make_float4(0.f,0.f,0.f,0.f);
        float4 vb1 = bok1 ? *(const float4*)(pB + 64 * D) : make_float4(0.f,0.f,0.f,0.f);
        As[0][cq*4+0][rowL] = va0.x; As[0][cq*4+1][rowL] = va0.y;
        As[0][cq*4+2][rowL] = va0.z; As[0][cq*4+3][rowL] = va0.w;
        As[0][cq*4+0][rowL+64] = va1.x; As[0][cq*4+1][rowL+64] = va1.y;
        As[0][cq*4+2][rowL+64] = va1.z; As[0][cq*4+3][rowL+64] = va1.w;
        Bs[0][cq*4+0][rowL] = vb0.x; Bs[0][cq*4+1][rowL] = vb0.y;
        Bs[0][cq*4+2][rowL] = vb0.z; Bs[0][cq*4+3][rowL] = vb0.w;
        Bs[0][cq*4+0][rowL+64] = vb1.x; Bs[0][cq*4+1][rowL+64] = vb1.y;
        Bs[0][cq*4+2][rowL+64] = vb1.z; Bs[0][cq*4+3][rowL+64] = vb1.w;
    }
    __syncthreads();

    int buf = 0;
    #pragma unroll
    for (int s = 0; s < 8; s++) {
        float4 na0, na1, nb0, nb1;
        if (s < 7) {
            int k0 = (s + 1) * 16;
            na0 = *(const float4*)(pA + k0);
            na1 = *(const float4*)(pA + 64 * D + k0);
            nb0 = bok0 ? *(const float4*)(pB + k0) : make_float4(0.f,0.f,0.f,0.f);
            nb1 = bok1 ? *(const float4*)(pB + 64 * D + k0) : make_float4(0.f,0.f,0.f,0.f);
        }
        #pragma unroll
        for (int k = 0; k < 16; k++) {
            float4 a0 = *(const float4*)&As[buf][k][ty4];
            float4 a1 = *(const float4*)&As[buf][k][ty4 + 64];
            double2 q0 = *(const double2*)&Bs[buf][k][tx4];
            double2 q1 = *(const double2*)&Bs[buf][k][tx4 + 64];
            u64 bv[4];
            bv[0] = __double_as_longlong(q0.x);
            bv[1] = __double_as_longlong(q0.y);
            bv[2] = __double_as_longlong(q1.x);
            bv[3] = __double_as_longlong(q1.y);
            float av[8] = {a0.x,a0.y,a0.z,a0.w,a1.x,a1.y,a1.z,a1.w};
            #pragma unroll
            for (int i = 0; i < 8; i++) {
                u64 a2 = pack2(av[i]);
                #pragma unroll
                for (int j = 0; j < 4; j++)
                    ffma2(acc[i][j], a2, bv[j]);
            }
        }
        if (s < 7) {
            int nb = buf ^ 1;
            As[nb][cq*4+0][rowL] = na0.x; As[nb][cq*4+1][rowL] = na0.y;
            As[nb][cq*4+2][rowL] = na0.z; As[nb][cq*4+3][rowL] = na0.w;
            As[nb][cq*4+0][rowL+64] = na1.x; As[nb][cq*4+1][rowL+64] = na1.y;
            As[nb][cq*4+2][rowL+64] = na1.z; As[nb][cq*4+3][rowL+64] = na1.w;
            Bs[nb][cq*4+0][rowL] = nb0.x; Bs[nb][cq*4+1][rowL] = nb0.y;
            Bs[nb][cq*4+2][rowL] = nb0.z; Bs[nb][cq*4+3][rowL] = nb0.w;
            Bs[nb][cq*4+0][rowL+64] = nb1.x; Bs[nb][cq*4+1][rowL+64] = nb1.y;
            Bs[nb][cq*4+2][rowL+64] = nb1.z; Bs[nb][cq*4+3][rowL+64] = nb1.w;
            __syncthreads();
            buf = nb;
        }
    }

    #pragma unroll
    for (int gi_ = 0; gi_ < 2; gi_++) {
        #pragma unroll
        for (int i = 0; i < 4; i++) {
            int m = m0 + gi_ * 64 + ty4 + i;
            #pragma unroll
            for (int gj = 0; gj < 2; gj++) {
                int n = n0 + gj * 64 + tx4;
                u64 p0 = acc[gi_*4+i][gj*2+0];
                u64 p1 = acc[gi_*4+i][gj*2+1];
                float4 v;
                v.x = lo32(p0); v.y = hi32(p0);
                v.z = lo32(p1); v.w = hi32(p1);
                float* C = g_blob + COFF;
                *(float4*)&C[(size_t)m * LDC + n] = v;
            }
        }
    }
}

// ---------------------------------------------------------------------------
// K3: per-sample edge aggregation.  X = Hin + agg(Hout[src])/deg
// ---------------------------------------------------------------------------
__global__ __launch_bounds__(256) void agg_kernel()
{
    extern __shared__ float agg[];            // L*D floats
    __shared__ int   cinv[L];
    __shared__ float rdeg[L];
    const int b = blockIdx.x, tid = threadIdx.x;

    if (tid < L) { cinv[tid] = g_cinv[b * L + tid]; rdeg[tid] = 0.f; }
    for (int i = tid; i < L * D / 4; i += 256)
        ((float4*)agg)[i] = make_float4(0.f, 0.f, 0.f, 0.f);
    __syncthreads();

    const int cnt = g_cntv[b];
    if (tid < cnt - 1) atomicAdd(&rdeg[cinv[tid + 1]], 1.0f);
    __syncthreads();
    if (tid < L) rdeg[tid] = 1.0f / fmaxf(rdeg[tid], 1.0f);

    const float* Hio = g_blob + OFF_HIO + (size_t)b * L * 2 * D;
    const int nedge = (cnt >= 1) ? cnt - 1 : 0;
    for (int idx = tid; idx < nedge * D; idx += 256) {
        int t = idx >> 7, k = idx & 127;
        atomicAdd(&agg[cinv[t + 1] * D + k], Hio[(size_t)cinv[t] * 2 * D + D + k]);
    }
    __syncthreads();

    float* X = g_blob + OFF_X + (size_t)b * L * D;
    for (int idx = tid; idx < L * D; idx += 256) {
        int r = idx >> 7;
        X[idx] = Hio[(size_t)r * 2 * D + (idx & 127)] + agg[idx] * rdeg[r];
    }
}

// ---------------------------------------------------------------------------
// K4: elementwise GRU, Hall updated in place
// ---------------------------------------------------------------------------
__global__ __launch_bounds__(256) void gru_kernel(
    const float* __restrict__ b_ih, const float* __restrict__ b_hh)
{
    int idx = blockIdx.x * 256 + threadIdx.x;          // < ROWS*D
    int row = idx >> 7, j = idx & 127;
    const float* gi = g_blob + OFF_GI + (size_t)row * 3 * D;
    const float* gh = g_blob + OFF_GH + (size_t)row * 3 * D;
    float gir = gi[j]         + b_ih[j];
    float giz = gi[D + j]     + b_ih[D + j];
    float gin = gi[2 * D + j] + b_ih[2 * D + j];
    float ghr = gh[j]         + b_hh[j];
    float ghz = gh[D + j]     + b_hh[D + j];
    float ghn = gh[2 * D + j] + b_hh[2 * D + j];
    float h0 = g_blob[OFF_HALL + idx];
    float r = 1.0f / (1.0f + expf(-(gir + ghr)));
    float z = 1.0f / (1.0f + expf(-(giz + ghz)));
    float n = tanhf(gin + r * ghn);
    g_blob[OFF_HALL + idx] = (1.0f - z) * n + z * h0;
}

// ---------------------------------------------------------------------------
// K5: attention readout -> h_read (bf16 hi/lo split, for tensor score GEMM)
// ---------------------------------------------------------------------------
__global__ __launch_bounds__(256) void attn_kernel(
    const float* __restrict__ W_read, const float* __restrict__ b_read)
{
    __shared__ float hlast[D], loc[D], sc[L];
    const int b = blockIdx.x, tid = threadIdx.x;
    const int nn = g_nn[b], li = g_li[b];
    const float* H = g_blob + OFF_HALL + (size_t)b * L * D;

    if (tid < D) hlast[tid] = H[(size_t)li * D + tid];
    __syncthreads();

    const int w = tid >> 5, lane = tid & 31;
    for (int r = w; r < nn; r += 8) {
        const float* hr = H + (size_t)r * D;
        float acc = 0.f;
        #pragma unroll
        for (int k = lane; k < D; k += 32) acc = fmaf(hr[k], hlast[k], acc);
        #pragma unroll
        for (int off = 16; off; off >>= 1)
            acc += __shfl_down_sync(0xffffffffu, acc, off);
        if (lane == 0) sc[r] = acc;
    }
    __syncthreads();

    if (tid == 0) {
        float m = -1e30f;
        for (int i = 0; i < nn; i++) m = fmaxf(m, sc[i]);
        float s = 0.f;
        for (int i = 0; i < nn; i++) { float e = expf(sc[i] - m); sc[i] = e; s += e; }
        float inv = (s > 0.f) ? 1.0f / s : 0.f;
        for (int i = 0; i < nn; i++) sc[i] *= inv;
    }
    __syncthreads();

    if (tid < D) {
        float acc = 0.f;
        for (int r = 0; r < nn; r++) acc = fmaf(sc[r], H[(size_t)r * D + tid], acc);
        loc[tid] = acc;
    }
    __syncthreads();

    #pragma unroll
    for (int t = 0; t < 16; t++) {
        int j = w * 16 + t;
        const float* wr = W_read + (size_t)j * (3 * D);
        float acc = 0.f;
        #pragma unroll
        for (int k = lane; k < D; k += 32)
            acc += wr[k] * hlast[k] + wr[D + k] * loc[k];
        #pragma unroll
        for (int off = 16; off; off >>= 1)
            acc += __shfl_down_sync(0xffffffffu, acc, off);
        if (lane == 0) {
            float hv = tanhf(acc + b_read[j]);
            __nv_bfloat16 h = __float2bfloat16(hv);
            g_ahi[b * D + j] = h;
            g_alo[b * D + j] = __float2bfloat16(hv - __bfloat162float(h));
        }
    }
}

// ---------------------------------------------------------------------------
// K6: score GEMM on mma.sync (HMMA bf16, fp32 acc), 3-term split:
//     D = Ahi·Bhi + Alo·Bhi + Ahi·Blo
// CTA tile 128x128, 8 warps (4x2), warp tile 32x64, K=128 resident in SMEM
// as two 64-K chunks [128 rows x 128B] with XOR-16B swizzle (ldmatrix
// conflict-free).  B buffer refilled ehi -> elo between passes.
// ---------------------------------------------------------------------------
#define SC_TILE  16384
#define SC_SMEM  (1024 + 6 * SC_TILE)

// stage one [128][128] bf16 tile into two swizzled 64-K chunks (256 threads)
__device__ __forceinline__ void stage_tile(
    unsigned dst0, unsigned dst1, const __nv_bfloat16* gsrc,
    int row0, int maxrow, int tid)
{
    const int r = tid >> 1;            // 0..127
    const int h = tid & 1;
    const int row = row0 + r;
    if (row < maxrow) {
        const uint4* s = (const uint4*)(gsrc + (size_t)row * D);
        #pragma unroll
        for (int jj = 0; jj < 4; jj++) {
            int j = h * 4 + jj;
            unsigned o = r * 128 + ((j ^ (r & 7)) << 4);
            sts128(dst0 + o, s[j]);
            sts128(dst1 + o, s[8 + j]);
        }
    } else {
        uint4 z = make_uint4(0u, 0u, 0u, 0u);
        #pragma unroll
        for (int jj = 0; jj < 4; jj++) {
            int j = h * 4 + jj;
            unsigned o = r * 128 + ((j ^ (r & 7)) << 4);
            sts128(dst0 + o, z);
            sts128(dst1 + o, z);
        }
    }
}

__device__ __forceinline__ unsigned sw_addr(unsigned tile, int row, int kb) {
    return tile + row * 128 + (((unsigned)(kb ^ (row & 7))) << 4);
}

__global__ __launch_bounds__(256, 2) void score_mma_kernel(float* __restrict__ out)
{
    extern __shared__ char dsm[];
    const int tid  = threadIdx.x;
    const int wid  = tid >> 5, lane = tid & 31;
    const int m0   = blockIdx.x * 128;
    const int n0   = blockIdx.y * 128;

    unsigned tb = (smem_u32(dsm) + 1023) & ~1023u;
    // Ahi c0, Ahi c1, Alo c0, Alo c1, B c0, B c1
    unsigned tA[4] = { tb, tb + SC_TILE, tb + 2*SC_TILE, tb + 3*SC_TILE };
    unsigned tB[2] = { tb + 4*SC_TILE, tb + 5*SC_TILE };

    // stage A (hi + lo) and B = ehi
    stage_tile(tA[0], tA[1], g_ahi, m0, BATCH, tid);
    stage_tile(tA[2], tA[3], g_alo, m0, BATCH, tid);
    stage_tile(tB[0], tB[1], g_ehi, n0, NITEMS, tid);
    __syncthreads();

    // warp layout: 4 (m) x 2 (n); warp tile 32x64
    const int m0w = (wid & 3) * 32;
    const int n0w = (wid >> 2) * 64;

    // ldmatrix lane -> row/sub mappings
    const int arow = m0w + (lane & 15);
    const int asub = lane >> 4;
    const int brow0 = n0w + ((lane >> 4) << 3) + (lane & 7);
    const int bsub  = (lane >> 3) & 1;

    float acc[2][8][4];
    #pragma unroll
    for (int i = 0; i < 2; i++)
        #pragma unroll
        for (int j = 0; j < 8; j++)
            #pragma unroll
            for (int q = 0; q < 4; q++) acc[i][j][q] = 0.f;

    // ---- pass 1: (Ahi + Alo) x Bhi ----
    #pragma unroll
    for (int c = 0; c < 2; c++) {
        #pragma unroll
        for (int kq = 0; kq < 4; kq++) {
            const int kbA = kq * 2 + asub;
            const int kbB = kq * 2 + bsub;
            unsigned bf[8][2];
            #pragma unroll
            for (int p = 0; p < 4; p++)
                ldm4(bf[2*p][0], bf[2*p][1], bf[2*p+1][0], bf[2*p+1][1],
                     sw_addr(tB[c], brow0 + p * 16, kbB));
            unsigned af[2][4];
            #pragma unroll
            for (int mf = 0; mf < 2; mf++)
                ldm4(af[mf][0], af[mf][1], af[mf][2], af[mf][3],
                     sw_addr(tA[c], arow + mf * 16, kbA));
            #pragma unroll
            for (int mf = 0; mf < 2; mf++)
                #pragma unroll
                for (int nf = 0; nf < 8; nf++)
                    mma16816(acc[mf][nf], af[mf], bf[nf]);
            #pragma unroll
            for (int mf = 0; mf < 2; mf++)
                ldm4(af[mf][0], af[mf][1], af[mf][2], af[mf][3],
                     sw_addr(tA[2 + c], arow + mf * 16, kbA));
            #pragma unroll
            for (int mf = 0; mf < 2; mf++)
                #pragma unroll
                for (int nf = 0; nf < 8; nf++)
                    mma16816(acc[mf][nf], af[mf], bf[nf]);
        }
    }
    __syncthreads();

    // refill B with elo
    stage_tile(tB[0], tB[1], g_elo, n0, NITEMS, tid);
    __syncthreads();

    // ---- pass 2: Ahi x Blo ----
    #pragma unroll
    for (int c = 0; c < 2; c++) {
        #pragma unroll
        for (int kq = 0; kq < 4; kq++) {
            const int kbA = kq * 2 + asub;
            const int kbB = kq * 2 + bsub;
            unsigned bf[8][2];
            #pragma unroll
            for (int p = 0; p < 4; p++)
                ldm4(bf[2*p][0], bf[2*p][1], bf[2*p+1][0], bf[2*p+1][1],
                     sw_addr(tB[c], brow0 + p * 16, kbB));
            unsigned af[2][4];
            #pragma unroll
            for (int mf = 0; mf < 2; mf++)
                ldm4(af[mf][0], af[mf][1], af[mf][2], af[mf][3],
                     sw_addr(tA[c], arow + mf * 16, kbA));
            #pragma unroll
            for (int mf = 0; mf < 2; mf++)
                #pragma unroll
                for (int nf = 0; nf < 8; nf++)
                    mma16816(acc[mf][nf], af[mf], bf[nf]);
        }
    }

    // ---- epilogue: m16n8 D fragment -> gmem with cnt mask ----
    const int rbase = lane >> 2;             // 0..7
    const int cbase = (lane & 3) * 2;
    #pragma unroll
    for (int mf = 0; mf < 2; mf++) {
        const int mA = m0 + m0w + mf * 16 + rbase;
        const int mB = mA + 8;
        const bool okA = (g_cntv[mA] >= 2);
        const bool okB = (g_cntv[mB] >= 2);
        #pragma unroll
        for (int nf = 0; nf < 8; nf++) {
            const int n = n0 + n0w + nf * 8 + cbase;
            if (n < NITEMS) {
                float2 vA, vB;
                if (okA) { vA.x = acc[mf][nf][0]; vA.y = acc[mf][nf][1]; }
                else     { vA.x = (n == 0) ? 0.0f : NEGV; vA.y = NEGV; }
                if (okB) { vB.x = acc[mf][nf][2]; vB.y = acc[mf][nf][3]; }
                else     { vB.x = (n == 0) ? 0.0f : NEGV; vB.y = NEGV; }
                *(float2*)&out[(size_t)mA * NITEMS + n] = vA;
                *(float2*)&out[(size_t)mB * NITEMS + n] = vB;
            }
        }
    }
}

// ---------------------------------------------------------------------------
extern "C" void kernel_launch(void* const* d_in, const int* in_sizes, int n_in,
                              void* d_out, int out_size)
{
    const int*   x      = (const int*)  d_in[0];
    // d_in[1] = attn_mask (unused by reference)
    const float* emb    = (const float*)d_in[2];
    const float* W_in   = (const float*)d_in[3];
    const float* W_out  = (const float*)d_in[4];
    const float* w_ih   = (const float*)d_in[5];
    const float* w_hh   = (const float*)d_in[6];
    const float* b_ih   = (const float*)d_in[7];
    const float* b_hh   = (const float*)d_in[8];
    const float* W_read = (const float*)d_in[9];
    const float* b_read = (const float*)d_in[10];
    float* out = (float*)d_out;

    cudaFuncSetAttribute(agg_kernel,
        cudaFuncAttributeMaxDynamicSharedMemorySize, L * D * (int)sizeof(float));
    cudaFuncSetAttribute(score_mma_kernel,
        cudaFuncAttributeMaxDynamicSharedMemorySize, SC_SMEM);

    // K0: emb -> bf16 hi/lo
    conv_emb_kernel<<<(NITEMS * D / 4) / 256, 256>>>(emb);

    // K1: graph build + gather
    build_kernel<<<BATCH, 256>>>(x, emb);

    // G1: Hin | Hout = Hall @ {W_in, W_out}^T
    gemm128<OFF_HALL, OFF_HIO,     2*D><<<dim3(ROWS/128, 1), 256>>>(W_in,  nullptr, D);
    gemm128<OFF_HALL, OFF_HIO + D, 2*D><<<dim3(ROWS/128, 1), 256>>>(W_out, nullptr, D);

    // G2: gh = Hall @ w_hh^T
    gemm128<OFF_HALL, OFF_GH, 3*D><<<dim3(ROWS/128, 3), 256>>>(w_hh, nullptr, 3*D);

    // K3: X = Hin + agg/deg
    agg_kernel<<<BATCH, 256, L * D * sizeof(float)>>>();

    // G3: gi = X @ w_ih^T
    gemm128<OFF_X, OFF_GI, 3*D><<<dim3(ROWS/128, 3), 256>>>(w_ih, nullptr, 3*D);

    // K4: GRU elementwise (Hall <- H)
    gru_kernel<<<(ROWS * D) / 256, 256>>>(b_ih, b_hh);

    // K5: attention -> h_read (bf16 hi/lo)
    attn_kernel<<<BATCH, 256>>>(W_read, b_read);

    // K6: tensor-core (mma.sync) score GEMM
    score_mma_kernel<<<dim3(BATCH / 128, (NITEMS + 127) / 128), 256, SC_SMEM>>>(out);
}

// round 11
// speedup vs baseline: 3.7729x; 1.0903x over previous
#include <cuda_runtime.h>
#include <cuda_bf16.h>
#include <math.h>

#define BATCH  512
#define L      100
#define D      128
#define NITEMS 100000
#define NEGV   -1000000000.0f
#define ROWS   (BATCH * L)          // 51200 padded node rows

// ---- scratch blob offsets (floats) ----
#define OFF_HALL  0
#define OFF_HIO   (ROWS * D)                    // [ROWS][256]  Hin | Hout
#define OFF_GI    (OFF_HIO + ROWS * 2 * D)      // [ROWS][384]
#define OFF_GH    (OFF_GI + ROWS * 3 * D)       // [ROWS][384]
#define BLOB_SZ   (OFF_GH + ROWS * 3 * D)

__device__ __align__(128) float g_blob[BLOB_SZ];
__device__ int g_cinv[BATCH * L];
__device__ int g_nn[BATCH];
__device__ int g_cntv[BATCH];
__device__ int g_li[BATCH];

// bf16 hi/lo split operands for tensor-core GEMMs
__device__ __align__(16) __nv_bfloat16 g_ehi[NITEMS * D];
__device__ __align__(16) __nv_bfloat16 g_elo[NITEMS * D];
__device__ __align__(16) __nv_bfloat16 g_ahi[BATCH * D];
__device__ __align__(16) __nv_bfloat16 g_alo[BATCH * D];
__device__ __align__(16) __nv_bfloat16 g_hallhi[ROWS * D];
__device__ __align__(16) __nv_bfloat16 g_halllo[ROWS * D];
__device__ __align__(16) __nv_bfloat16 g_xhi[ROWS * D];
__device__ __align__(16) __nv_bfloat16 g_xlo[ROWS * D];
__device__ __align__(16) __nv_bfloat16 g_wiohi[2 * D * D];   // [W_in; W_out]
__device__ __align__(16) __nv_bfloat16 g_wiolo[2 * D * D];
__device__ __align__(16) __nv_bfloat16 g_whhhi[3 * D * D];
__device__ __align__(16) __nv_bfloat16 g_whhlo[3 * D * D];
__device__ __align__(16) __nv_bfloat16 g_wihhi[3 * D * D];
__device__ __align__(16) __nv_bfloat16 g_wihlo[3 * D * D];

// ---- smem / warp-mma helpers (arch-generic PTX: sm_80+) ----
__device__ __forceinline__ unsigned smem_u32(const void* p) {
    unsigned a;
    asm("{ .reg .u64 t; cvta.to.shared.u64 t, %1; cvt.u32.u64 %0, t; }" : "=r"(a) : "l"(p));
    return a;
}
__device__ __forceinline__ void sts128(unsigned addr, uint4 v) {
    asm volatile("st.shared.v4.b32 [%0], {%1,%2,%3,%4};"
                 :: "r"(addr), "r"(v.x), "r"(v.y), "r"(v.z), "r"(v.w));
}
__device__ __forceinline__ void ldm4(unsigned& r0, unsigned& r1,
                                     unsigned& r2, unsigned& r3, unsigned addr) {
    asm volatile("ldmatrix.sync.aligned.m8n8.x4.shared.b16 {%0,%1,%2,%3}, [%4];"
                 : "=r"(r0), "=r"(r1), "=r"(r2), "=r"(r3) : "r"(addr));
}
__device__ __forceinline__ void mma16816(float* c, const unsigned* a, const unsigned* b) {
    asm volatile("mma.sync.aligned.m16n8k16.row.col.f32.bf16.bf16.f32 "
                 "{%0,%1,%2,%3}, {%4,%5,%6,%7}, {%8,%9}, {%0,%1,%2,%3};"
                 : "+f"(c[0]), "+f"(c[1]), "+f"(c[2]), "+f"(c[3])
                 : "r"(a[0]), "r"(a[1]), "r"(a[2]), "r"(a[3]),
                   "r"(b[0]), "r"(b[1]));
}

// ---------------------------------------------------------------------------
// K0: fp32 -> bf16 hi/lo split (grid covers n/4 float4 groups exactly)
// ---------------------------------------------------------------------------
__global__ __launch_bounds__(256) void conv_split_kernel(
    const float* __restrict__ src,
    __nv_bfloat16* __restrict__ dhi, __nv_bfloat16* __restrict__ dlo)
{
    size_t i = (size_t)blockIdx.x * 256 + threadIdx.x;   // one float4 group
    float4 v = ((const float4*)src)[i];
    __nv_bfloat162 h01 = __floats2bfloat162_rn(v.x, v.y);
    __nv_bfloat162 h23 = __floats2bfloat162_rn(v.z, v.w);
    __nv_bfloat162 l01 = __floats2bfloat162_rn(v.x - __low2float(h01), v.y - __high2float(h01));
    __nv_bfloat162 l23 = __floats2bfloat162_rn(v.z - __low2float(h23), v.w - __high2float(h23));
    ((__nv_bfloat162*)dhi)[2 * i]     = h01;
    ((__nv_bfloat162*)dhi)[2 * i + 1] = h23;
    ((__nv_bfloat162*)dlo)[2 * i]     = l01;
    ((__nv_bfloat162*)dlo)[2 * i + 1] = l23;
}

// ---------------------------------------------------------------------------
// K1: per-sample graph build + gather H0 (fp32 + bf16 hi/lo, zero-padded)
// ---------------------------------------------------------------------------
__global__ __launch_bounds__(256) void build_kernel(
    const int* __restrict__ x, const float* __restrict__ emb)
{
    __shared__ int s_seq[L], s_rep[L], s_nodes[L], s_cinv[L];
    __shared__ int s_nn, s_cnt;
    const int b = blockIdx.x, tid = threadIdx.x;

    if (tid == 0) { s_nn = 0; s_cnt = 0; }
    if (tid < L) { s_seq[tid] = x[b * L + tid]; s_cinv[tid] = 0; }
    __syncthreads();

    int mypos = 0;
    if (tid < L) {
        int s = s_seq[tid];
        int rep = (s != 0);
        for (int j = 0; j < tid; j++) {
            int sj = s_seq[j];
            if (sj != 0) { mypos++; if (sj == s) rep = 0; }
        }
        s_rep[tid] = rep;
    }
    __syncthreads();

    if (tid < L) {
        int s = s_seq[tid];
        if (s != 0) {
            int rank = 0;
            for (int j = 0; j < L; j++)
                if (s_rep[j] && s_seq[j] < s) rank++;
            if (s_rep[tid]) { s_nodes[rank] = s; atomicAdd(&s_nn, 1); }
            s_cinv[mypos] = rank;
            atomicAdd(&s_cnt, 1);
        }
    }
    __syncthreads();

    const int nn = s_nn, cnt = s_cnt;

    float* Hall = g_blob + OFF_HALL + (size_t)b * L * D;
    for (int idx = tid; idx < L * 32; idx += 256) {
        int r = idx >> 5, q = idx & 31;
        float4 v = make_float4(0.f, 0.f, 0.f, 0.f);
        if (r < nn) v = ((const float4*)(emb + (size_t)s_nodes[r] * D))[q];
        ((float4*)(Hall + r * D))[q] = v;
    }
    // bf16 hi/lo gather from pre-split emb
    for (int idx = tid; idx < L * 16; idx += 256) {
        int r = idx >> 4, q = idx & 15;
        uint4 vh = make_uint4(0u, 0u, 0u, 0u), vl = vh;
        if (r < nn) {
            vh = ((const uint4*)(g_ehi + (size_t)s_nodes[r] * D))[q];
            vl = ((const uint4*)(g_elo + (size_t)s_nodes[r] * D))[q];
        }
        ((uint4*)(g_hallhi + ((size_t)b * L + r) * D))[q] = vh;
        ((uint4*)(g_halllo + ((size_t)b * L + r) * D))[q] = vl;
    }
    if (tid < L) g_cinv[b * L + tid] = s_cinv[tid];
    if (tid == 0) {
        g_nn[b] = nn;
        g_cntv[b] = cnt;
        g_li[b] = (cnt > 0) ? s_cinv[cnt - 1] : 0;
    }
}

// ---------------------------------------------------------------------------
// Unified tensor-core GEMM (mma.sync bf16, fp32 acc), 3-term split:
//     C = Ahi·Bhi^T + Alo·Bhi^T + Ahi·Blo^T
// CTA tile 128x128, 8 warps (4m x 2n), warp tile 32x64, K=128 in SMEM as
// two 64-K chunks [128 rows x 128B], XOR-16B swizzle (ldmatrix conflict-free).
// B refilled hi -> lo between passes (96KB SMEM, 2 CTA/SM).
// SCORE: C = out with cnt>=2 masking + default row; else C = g_blob + coff.
// ---------------------------------------------------------------------------
#define SC_TILE  16384
#define SC_SMEM  (1024 + 6 * SC_TILE)

__device__ __forceinline__ void stage_tile(
    unsigned dst0, unsigned dst1, const __nv_bfloat16* gsrc,
    int row0, int maxrow, int tid)
{
    const int r = tid >> 1;            // 0..127
    const int h = tid & 1;
    const int row = row0 + r;
    if (row < maxrow) {
        const uint4* s = (const uint4*)(gsrc + (size_t)row * D);
        #pragma unroll
        for (int jj = 0; jj < 4; jj++) {
            int j = h * 4 + jj;
            unsigned o = r * 128 + ((j ^ (r & 7)) << 4);
            sts128(dst0 + o, s[j]);
            sts128(dst1 + o, s[8 + j]);
        }
    } else {
        uint4 z = make_uint4(0u, 0u, 0u, 0u);
        #pragma unroll
        for (int jj = 0; jj < 4; jj++) {
            int j = h * 4 + jj;
            unsigned o = r * 128 + ((j ^ (r & 7)) << 4);
            sts128(dst0 + o, z);
            sts128(dst1 + o, z);
        }
    }
}

__device__ __forceinline__ unsigned sw_addr(unsigned tile, int row, int kb) {
    return tile + row * 128 + (((unsigned)(kb ^ (row & 7))) << 4);
}

template<bool SCORE>
__global__ __launch_bounds__(256, 2) void mma_gemm_kernel(
    const __nv_bfloat16* __restrict__ Ahi, const __nv_bfloat16* __restrict__ Alo,
    const __nv_bfloat16* __restrict__ Bhi, const __nv_bfloat16* __restrict__ Blo,
    float* __restrict__ outp, int coff, int ldc, int nvalid)
{
    extern __shared__ char dsm[];
    const int tid  = threadIdx.x;
    const int wid  = tid >> 5, lane = tid & 31;
    const int m0   = blockIdx.x * 128;
    const int n0   = blockIdx.y * 128;

    unsigned tb = (smem_u32(dsm) + 1023) & ~1023u;
    unsigned tA[4] = { tb, tb + SC_TILE, tb + 2*SC_TILE, tb + 3*SC_TILE };
    unsigned tB[2] = { tb + 4*SC_TILE, tb + 5*SC_TILE };

    stage_tile(tA[0], tA[1], Ahi, m0, 0x7fffffff, tid);
    stage_tile(tA[2], tA[3], Alo, m0, 0x7fffffff, tid);
    stage_tile(tB[0], tB[1], Bhi, n0, nvalid, tid);
    __syncthreads();

    const int m0w = (wid & 3) * 32;
    const int n0w = (wid >> 2) * 64;

    const int arow = m0w + (lane & 15);
    const int asub = lane >> 4;
    const int brow0 = n0w + ((lane >> 4) << 3) + (lane & 7);
    const int bsub  = (lane >> 3) & 1;

    float acc[2][8][4];
    #pragma unroll
    for (int i = 0; i < 2; i++)
        #pragma unroll
        for (int j = 0; j < 8; j++)
            #pragma unroll
            for (int q = 0; q < 4; q++) acc[i][j][q] = 0.f;

    // ---- pass 1: (Ahi + Alo) x Bhi ----
    #pragma unroll
    for (int c = 0; c < 2; c++) {
        #pragma unroll
        for (int kq = 0; kq < 4; kq++) {
            const int kbA = kq * 2 + asub;
            const int kbB = kq * 2 + bsub;
            unsigned bf[8][2];
            #pragma unroll
            for (int p = 0; p < 4; p++)
                ldm4(bf[2*p][0], bf[2*p][1], bf[2*p+1][0], bf[2*p+1][1],
                     sw_addr(tB[c], brow0 + p * 16, kbB));
            unsigned af[2][4];
            #pragma unroll
            for (int mf = 0; mf < 2; mf++)
                ldm4(af[mf][0], af[mf][1], af[mf][2], af[mf][3],
                     sw_addr(tA[c], arow + mf * 16, kbA));
            #pragma unroll
            for (int mf = 0; mf < 2; mf++)
                #pragma unroll
                for (int nf = 0; nf < 8; nf++)
                    mma16816(acc[mf][nf], af[mf], bf[nf]);
            #pragma unroll
            for (int mf = 0; mf < 2; mf++)
                ldm4(af[mf][0], af[mf][1], af[mf][2], af[mf][3],
                     sw_addr(tA[2 + c], arow + mf * 16, kbA));
            #pragma unroll
            for (int mf = 0; mf < 2; mf++)
                #pragma unroll
                for (int nf = 0; nf < 8; nf++)
                    mma16816(acc[mf][nf], af[mf], bf[nf]);
        }
    }
    __syncthreads();

    stage_tile(tB[0], tB[1], Blo, n0, nvalid, tid);
    __syncthreads();

    // ---- pass 2: Ahi x Blo ----
    #pragma unroll
    for (int c = 0; c < 2; c++) {
        #pragma unroll
        for (int kq = 0; kq < 4; kq++) {
            const int kbA = kq * 2 + asub;
            const int kbB = kq * 2 + bsub;
            unsigned bf[8][2];
            #pragma unroll
            for (int p = 0; p < 4; p++)
                ldm4(bf[2*p][0], bf[2*p][1], bf[2*p+1][0], bf[2*p+1][1],
                     sw_addr(tB[c], brow0 + p * 16, kbB));
            unsigned af[2][4];
            #pragma unroll
            for (int mf = 0; mf < 2; mf++)
                ldm4(af[mf][0], af[mf][1], af[mf][2], af[mf][3],
                     sw_addr(tA[c], arow + mf * 16, kbA));
            #pragma unroll
            for (int mf = 0; mf < 2; mf++)
                #pragma unroll
                for (int nf = 0; nf < 8; nf++)
                    mma16816(acc[mf][nf], af[mf], bf[nf]);
        }
    }

    // ---- epilogue ----
    float* C = SCORE ? outp : (g_blob + coff);
    const int rbase = lane >> 2;
    const int cbase = (lane & 3) * 2;
    #pragma unroll
    for (int mf = 0; mf < 2; mf++) {
        const int mA = m0 + m0w + mf * 16 + rbase;
        const int mB = mA + 8;
        bool okA = true, okB = true;
        if (SCORE) { okA = (g_cntv[mA] >= 2); okB = (g_cntv[mB] >= 2); }
        #pragma unroll
        for (int nf = 0; nf < 8; nf++) {
            const int n = n0 + n0w + nf * 8 + cbase;
            if (n < nvalid) {
                float2 vA, vB;
                vA.x = acc[mf][nf][0]; vA.y = acc[mf][nf][1];
                vB.x = acc[mf][nf][2]; vB.y = acc[mf][nf][3];
                if (SCORE) {
                    if (!okA) { vA.x = (n == 0) ? 0.0f : NEGV; vA.y = NEGV; }
                    if (!okB) { vB.x = (n == 0) ? 0.0f : NEGV; vB.y = NEGV; }
                }
                *(float2*)&C[(size_t)mA * ldc + n] = vA;
                *(float2*)&C[(size_t)mB * ldc + n] = vB;
            }
        }
    }
}

// ---------------------------------------------------------------------------
// K3: per-sample edge aggregation.  X = Hin + agg(Hout[src])/deg -> bf16 hi/lo
// ---------------------------------------------------------------------------
__global__ __launch_bounds__(256) void agg_kernel()
{
    extern __shared__ float agg[];            // L*D floats
    __shared__ int   cinv[L];
    __shared__ float rdeg[L];
    const int b = blockIdx.x, tid = threadIdx.x;

    if (tid < L) { cinv[tid] = g_cinv[b * L + tid]; rdeg[tid] = 0.f; }
    for (int i = tid; i < L * D / 4; i += 256)
        ((float4*)agg)[i] = make_float4(0.f, 0.f, 0.f, 0.f);
    __syncthreads();

    const int cnt = g_cntv[b];
    if (tid < cnt - 1) atomicAdd(&rdeg[cinv[tid + 1]], 1.0f);
    __syncthreads();
    if (tid < L) rdeg[tid] = 1.0f / fmaxf(rdeg[tid], 1.0f);

    const float* Hio = g_blob + OFF_HIO + (size_t)b * L * 2 * D;
    const int nedge = (cnt >= 1) ? cnt - 1 : 0;
    for (int idx = tid; idx < nedge * D; idx += 256) {
        int t = idx >> 7, k = idx & 127;
        atomicAdd(&agg[cinv[t + 1] * D + k], Hio[(size_t)cinv[t] * 2 * D + D + k]);
    }
    __syncthreads();

    for (int idx = tid; idx < L * D; idx += 256) {
        int r = idx >> 7;
        float v = Hio[(size_t)r * 2 * D + (idx & 127)] + agg[idx] * rdeg[r];
        __nv_bfloat16 h = __float2bfloat16(v);
        g_xhi[(size_t)b * L * D + idx] = h;
        g_xlo[(size_t)b * L * D + idx] = __float2bfloat16(v - __bfloat162float(h));
    }
}

// ---------------------------------------------------------------------------
// K4: elementwise GRU, Hall updated in place
// ---------------------------------------------------------------------------
__global__ __launch_bounds__(256) void gru_kernel(
    const float* __restrict__ b_ih, const float* __restrict__ b_hh)
{
    int idx = blockIdx.x * 256 + threadIdx.x;          // < ROWS*D
    int row = idx >> 7, j = idx & 127;
    const float* gi = g_blob + OFF_GI + (size_t)row * 3 * D;
    const float* gh = g_blob + OFF_GH + (size_t)row * 3 * D;
    float gir = gi[j]         + b_ih[j];
    float giz = gi[D + j]     + b_ih[D + j];
    float gin = gi[2 * D + j] + b_ih[2 * D + j];
    float ghr = gh[j]         + b_hh[j];
    float ghz = gh[D + j]     + b_hh[D + j];
    float ghn = gh[2 * D + j] + b_hh[2 * D + j];
    float h0 = g_blob[OFF_HALL + idx];
    float r = 1.0f / (1.0f + expf(-(gir + ghr)));
    float z = 1.0f / (1.0f + expf(-(giz + ghz)));
    float n = tanhf(gin + r * ghn);
    g_blob[OFF_HALL + idx] = (1.0f - z) * n + z * h0;
}

// ---------------------------------------------------------------------------
// K5: attention readout -> h_read (bf16 hi/lo split)
// ---------------------------------------------------------------------------
__global__ __launch_bounds__(256) void attn_kernel(
    const float* __restrict__ W_read, const float* __restrict__ b_read)
{
    __shared__ float hlast[D], loc[D], sc[L];
    const int b = blockIdx.x, tid = threadIdx.x;
    const int nn = g_nn[b], li = g_li[b];
    const float* H = g_blob + OFF_HALL + (size_t)b * L * D;

    if (tid < D) hlast[tid] = H[(size_t)li * D + tid];
    __syncthreads();

    const int w = tid >> 5, lane = tid & 31;
    for (int r = w; r < nn; r += 8) {
        const float* hr = H + (size_t)r * D;
        float acc = 0.f;
        #pragma unroll
        for (int k = lane; k < D; k += 32) acc = fmaf(hr[k], hlast[k], acc);
        #pragma unroll
        for (int off = 16; off; off >>= 1)
            acc += __shfl_down_sync(0xffffffffu, acc, off);
        if (lane == 0) sc[r] = acc;
    }
    __syncthreads();

    if (tid == 0) {
        float m = -1e30f;
        for (int i = 0; i < nn; i++) m = fmaxf(m, sc[i]);
        float s = 0.f;
        for (int i = 0; i < nn; i++) { float e = expf(sc[i] - m); sc[i] = e; s += e; }
        float inv = (s > 0.f) ? 1.0f / s : 0.f;
        for (int i = 0; i < nn; i++) sc[i] *= inv;
    }
    __syncthreads();

    if (tid < D) {
        float acc = 0.f;
        for (int r = 0; r < nn; r++) acc = fmaf(sc[r], H[(size_t)r * D + tid], acc);
        loc[tid] = acc;
    }
    __syncthreads();

    #pragma unroll
    for (int t = 0; t < 16; t++) {
        int j = w * 16 + t;
        const float* wr = W_read + (size_t)j * (3 * D);
        float acc = 0.f;
        #pragma unroll
        for (int k = lane; k < D; k += 32)
            acc += wr[k] * hlast[k] + wr[D + k] * loc[k];
        #pragma unroll
        for (int off = 16; off; off >>= 1)
            acc += __shfl_down_sync(0xffffffffu, acc, off);
        if (lane == 0) {
            float hv = tanhf(acc + b_read[j]);
            __nv_bfloat16 h = __float2bfloat16(hv);
            g_ahi[b * D + j] = h;
            g_alo[b * D + j] = __float2bfloat16(hv - __bfloat162float(h));
        }
    }
}

// ---------------------------------------------------------------------------
extern "C" void kernel_launch(void* const* d_in, const int* in_sizes, int n_in,
                              void* d_out, int out_size)
{
    const int*   x      = (const int*)  d_in[0];
    // d_in[1] = attn_mask (unused by reference)
    const float* emb    = (const float*)d_in[2];
    const float* W_in   = (const float*)d_in[3];
    const float* W_out  = (const float*)d_in[4];
    const float* w_ih   = (const float*)d_in[5];
    const float* w_hh   = (const float*)d_in[6];
    const float* b_ih   = (const float*)d_in[7];
    const float* b_hh   = (const float*)d_in[8];
    const float* W_read = (const float*)d_in[9];
    const float* b_read = (const float*)d_in[10];
    float* out = (float*)d_out;

    cudaFuncSetAttribute(agg_kernel,
        cudaFuncAttributeMaxDynamicSharedMemorySize, L * D * (int)sizeof(float));
    cudaFuncSetAttribute(mma_gemm_kernel<false>,
        cudaFuncAttributeMaxDynamicSharedMemorySize, SC_SMEM);
    cudaFuncSetAttribute(mma_gemm_kernel<true>,
        cudaFuncAttributeMaxDynamicSharedMemorySize, SC_SMEM);

    // device symbol addresses (host-side queries; no allocation)
    __nv_bfloat16 *ehi, *elo, *ahi, *alo, *hallhi, *halllo, *xhi, *xlo;
    __nv_bfloat16 *wiohi, *wiolo, *whhhi, *whhlo, *wihhi, *wihlo;
    cudaGetSymbolAddress((void**)&ehi,    g_ehi);
    cudaGetSymbolAddress((void**)&elo,    g_elo);
    cudaGetSymbolAddress((void**)&ahi,    g_ahi);
    cudaGetSymbolAddress((void**)&alo,    g_alo);
    cudaGetSymbolAddress((void**)&hallhi, g_hallhi);
    cudaGetSymbolAddress((void**)&halllo, g_halllo);
    cudaGetSymbolAddress((void**)&xhi,    g_xhi);
    cudaGetSymbolAddress((void**)&xlo,    g_xlo);
    cudaGetSymbolAddress((void**)&wiohi,  g_wiohi);
    cudaGetSymbolAddress((void**)&wiolo,  g_wiolo);
    cudaGetSymbolAddress((void**)&whhhi,  g_whhhi);
    cudaGetSymbolAddress((void**)&whhlo,  g_whhlo);
    cudaGetSymbolAddress((void**)&wihhi,  g_wihhi);
    cudaGetSymbolAddress((void**)&wihlo,  g_wihlo);

    // K0: hi/lo splits (emb + weights)
    conv_split_kernel<<<(NITEMS * D / 4) / 256, 256>>>(emb, ehi, elo);
    conv_split_kernel<<<(D * D / 4) / 256, 256>>>(W_in,  wiohi,          wiolo);
    conv_split_kernel<<<(D * D / 4) / 256, 256>>>(W_out, wiohi + D * D,  wiolo + D * D);
    conv_split_kernel<<<(3 * D * D / 4) / 256, 256>>>(w_hh, whhhi, whhlo);
    conv_split_kernel<<<(3 * D * D / 4) / 256, 256>>>(w_ih, wihhi, wihlo);

    // K1: graph build + gather (fp32 + bf16 hi/lo)
    build_kernel<<<BATCH, 256>>>(x, emb);

    // G1: Hin | Hout = Hall @ [W_in; W_out]^T   (tensor core)
    mma_gemm_kernel<false><<<dim3(ROWS / 128, 2), 256, SC_SMEM>>>(
        hallhi, halllo, wiohi, wiolo, nullptr, OFF_HIO, 2 * D, 2 * D);

    // G2: gh = Hall @ w_hh^T
    mma_gemm_kernel<false><<<dim3(ROWS / 128, 3), 256, SC_SMEM>>>(
        hallhi, halllo, whhhi, whhlo, nullptr, OFF_GH, 3 * D, 3 * D);

    // K3: X = Hin + agg/deg  -> bf16 hi/lo
    agg_kernel<<<BATCH, 256, L * D * sizeof(float)>>>();

    // G3: gi = X @ w_ih^T
    mma_gemm_kernel<false><<<dim3(ROWS / 128, 3), 256, SC_SMEM>>>(
        xhi, xlo, wihhi, wihlo, nullptr, OFF_GI, 3 * D, 3 * D);

    // K4: GRU elementwise (Hall <- H)
    gru_kernel<<<(ROWS * D) / 256, 256>>>(b_ih, b_hh);

    // K5: attention -> h_read (bf16 hi/lo)
    attn_kernel<<<BATCH, 256>>>(W_read, b_read);

    // K6: tensor-core score GEMM
    mma_gemm_kernel<true><<<dim3(BATCH / 128, (NITEMS + 127) / 128), 256, SC_SMEM>>>(
        ahi, alo, ehi, elo, out, 0, NITEMS, NITEMS);
}

// round 12
// speedup vs baseline: 3.9369x; 1.0435x over previous
#include <cuda_runtime.h>
#include <cuda_bf16.h>
#include <math.h>

#define BATCH  512
#define L      100
#define D      128
#define NITEMS 100000
#define NEGV   -1000000000.0f
#define ROWS   (BATCH * L)          // 51200 padded node rows

// ---- scratch blob offsets (floats) ----
#define OFF_HIO   0                         // [ROWS][256]  Hin | Hout
#define OFF_SRZ   (ROWS * 2 * D)            // [ROWS][256]  gi_r+gh_r | gi_z+gh_z
#define OFF_GIN   (OFF_SRZ + ROWS * 2 * D)  // [ROWS][128]
#define OFF_GHN   (OFF_GIN + ROWS * D)      // [ROWS][128]
#define BLOB_SZ   (OFF_GHN + ROWS * D)

__device__ __align__(128) float g_blob[BLOB_SZ];
__device__ int g_cinv[BATCH * L];
__device__ int g_nn[BATCH];
__device__ int g_cntv[BATCH];
__device__ int g_li[BATCH];

// bf16 hi/lo split operands for tensor-core GEMMs
__device__ __align__(16) __nv_bfloat16 g_ehi[NITEMS * D];
__device__ __align__(16) __nv_bfloat16 g_elo[NITEMS * D];
__device__ __align__(16) __nv_bfloat16 g_ahi[BATCH * D];
__device__ __align__(16) __nv_bfloat16 g_alo[BATCH * D];
__device__ __align__(16) __nv_bfloat16 g_hallhi[ROWS * D];
__device__ __align__(16) __nv_bfloat16 g_halllo[ROWS * D];
__device__ __align__(16) __nv_bfloat16 g_xhi[ROWS * D];
__device__ __align__(16) __nv_bfloat16 g_xlo[ROWS * D];
__device__ __align__(16) __nv_bfloat16 g_wiohi[2 * D * D];   // [W_in; W_out]
__device__ __align__(16) __nv_bfloat16 g_wiolo[2 * D * D];
__device__ __align__(16) __nv_bfloat16 g_whhhi[3 * D * D];
__device__ __align__(16) __nv_bfloat16 g_whhlo[3 * D * D];
__device__ __align__(16) __nv_bfloat16 g_wihhi[3 * D * D];
__device__ __align__(16) __nv_bfloat16 g_wihlo[3 * D * D];

// ---- smem / warp-mma helpers (arch-generic PTX: sm_80+) ----
__device__ __forceinline__ unsigned smem_u32(const void* p) {
    unsigned a;
    asm("{ .reg .u64 t; cvta.to.shared.u64 t, %1; cvt.u32.u64 %0, t; }" : "=r"(a) : "l"(p));
    return a;
}
__device__ __forceinline__ void sts128(unsigned addr, uint4 v) {
    asm volatile("st.shared.v4.b32 [%0], {%1,%2,%3,%4};"
                 :: "r"(addr), "r"(v.x), "r"(v.y), "r"(v.z), "r"(v.w));
}
__device__ __forceinline__ void ldm4(unsigned& r0, unsigned& r1,
                                     unsigned& r2, unsigned& r3, unsigned addr) {
    asm volatile("ldmatrix.sync.aligned.m8n8.x4.shared.b16 {%0,%1,%2,%3}, [%4];"
                 : "=r"(r0), "=r"(r1), "=r"(r2), "=r"(r3) : "r"(addr));
}
__device__ __forceinline__ void mma16816(float* c, const unsigned* a, const unsigned* b) {
    asm volatile("mma.sync.aligned.m16n8k16.row.col.f32.bf16.bf16.f32 "
                 "{%0,%1,%2,%3}, {%4,%5,%6,%7}, {%8,%9}, {%0,%1,%2,%3};"
                 : "+f"(c[0]), "+f"(c[1]), "+f"(c[2]), "+f"(c[3])
                 : "r"(a[0]), "r"(a[1]), "r"(a[2]), "r"(a[3]),
                   "r"(b[0]), "r"(b[1]));
}

// ---------------------------------------------------------------------------
// K0: ALL fp32 -> bf16 hi/lo splits in one launch (emb + 4 weight matrices)
// ---------------------------------------------------------------------------
#define E4   (NITEMS * D / 4)     // 3,200,000 float4 groups
#define W4   (D * D / 4)          // 4,096
#define W34  (3 * D * D / 4)      // 12,288
#define CONV_GROUPS (E4 + 2 * W4 + 2 * W34)   // 3,232,768 (/256 = 12,628)

__global__ __launch_bounds__(256) void conv_all_kernel(
    const float* __restrict__ emb,  const float* __restrict__ W_in,
    const float* __restrict__ W_out, const float* __restrict__ w_hh,
    const float* __restrict__ w_ih)
{
    size_t i = (size_t)blockIdx.x * 256 + threadIdx.x;
    const float* src; __nv_bfloat16 *dhi, *dlo; size_t off;
    if (i < E4)                    { src = emb;   off = i;                 dhi = g_ehi;            dlo = g_elo; }
    else if (i < E4 + W4)          { src = W_in;  off = i - E4;            dhi = g_wiohi;          dlo = g_wiolo; }
    else if (i < E4 + 2 * W4)      { src = W_out; off = i - E4 - W4;       dhi = g_wiohi + D * D;  dlo = g_wiolo + D * D; }
    else if (i < E4 + 2 * W4 + W34){ src = w_hh;  off = i - E4 - 2 * W4;   dhi = g_whhhi;          dlo = g_whhlo; }
    else                           { src = w_ih;  off = i - E4 - 2*W4 - W34; dhi = g_wihhi;        dlo = g_wihlo; }

    float4 v = ((const float4*)src)[off];
    __nv_bfloat162 h01 = __floats2bfloat162_rn(v.x, v.y);
    __nv_bfloat162 h23 = __floats2bfloat162_rn(v.z, v.w);
    __nv_bfloat162 l01 = __floats2bfloat162_rn(v.x - __low2float(h01), v.y - __high2float(h01));
    __nv_bfloat162 l23 = __floats2bfloat162_rn(v.z - __low2float(h23), v.w - __high2float(h23));
    ((__nv_bfloat162*)dhi)[2 * off]     = h01;
    ((__nv_bfloat162*)dhi)[2 * off + 1] = h23;
    ((__nv_bfloat162*)dlo)[2 * off]     = l01;
    ((__nv_bfloat162*)dlo)[2 * off + 1] = l23;
}

// ---------------------------------------------------------------------------
// K1: per-sample graph build + gather H0 (bf16 hi/lo only, zero-padded)
// ---------------------------------------------------------------------------
__global__ __launch_bounds__(256) void build_kernel(const int* __restrict__ x)
{
    __shared__ int s_seq[L], s_rep[L], s_nodes[L], s_cinv[L];
    __shared__ int s_nn, s_cnt;
    const int b = blockIdx.x, tid = threadIdx.x;

    if (tid == 0) { s_nn = 0; s_cnt = 0; }
    if (tid < L) { s_seq[tid] = x[b * L + tid]; s_cinv[tid] = 0; }
    __syncthreads();

    int mypos = 0;
    if (tid < L) {
        int s = s_seq[tid];
        int rep = (s != 0);
        for (int j = 0; j < tid; j++) {
            int sj = s_seq[j];
            if (sj != 0) { mypos++; if (sj == s) rep = 0; }
        }
        s_rep[tid] = rep;
    }
    __syncthreads();

    if (tid < L) {
        int s = s_seq[tid];
        if (s != 0) {
            int rank = 0;
            for (int j = 0; j < L; j++)
                if (s_rep[j] && s_seq[j] < s) rank++;
            if (s_rep[tid]) { s_nodes[rank] = s; atomicAdd(&s_nn, 1); }
            s_cinv[mypos] = rank;
            atomicAdd(&s_cnt, 1);
        }
    }
    __syncthreads();

    const int nn = s_nn, cnt = s_cnt;

    for (int idx = tid; idx < L * 16; idx += 256) {
        int r = idx >> 4, q = idx & 15;
        uint4 vh = make_uint4(0u, 0u, 0u, 0u), vl = vh;
        if (r < nn) {
            vh = ((const uint4*)(g_ehi + (size_t)s_nodes[r] * D))[q];
            vl = ((const uint4*)(g_elo + (size_t)s_nodes[r] * D))[q];
        }
        ((uint4*)(g_hallhi + ((size_t)b * L + r) * D))[q] = vh;
        ((uint4*)(g_halllo + ((size_t)b * L + r) * D))[q] = vl;
    }
    if (tid < L) g_cinv[b * L + tid] = s_cinv[tid];
    if (tid == 0) {
        g_nn[b] = nn;
        g_cntv[b] = cnt;
        g_li[b] = (cnt > 0) ? s_cinv[cnt - 1] : 0;
    }
}

// ---------------------------------------------------------------------------
// Unified tensor-core GEMM (mma.sync bf16, fp32 acc), 3-term split per pair:
//     C = sum_pairs ( Ahi·Bhi^T + Alo·Bhi^T + Ahi·Blo^T )
// NPAIR=2 accumulates two (A,B) products into the same output (rz fusion).
// CTA tile 128x128, 8 warps (4m x 2n), warp tile 32x64, K=128 per pair as
// two 64-K SMEM chunks with XOR-16B swizzle.  96KB SMEM -> 2 CTA/SM.
// ---------------------------------------------------------------------------
#define SC_TILE  16384
#define SC_SMEM  (1024 + 6 * SC_TILE)

__device__ __forceinline__ void stage_tile(
    unsigned dst0, unsigned dst1, const __nv_bfloat16* gsrc,
    int row0, int maxrow, int tid)
{
    const int r = tid >> 1;            // 0..127
    const int h = tid & 1;
    const int row = row0 + r;
    if (row < maxrow) {
        const uint4* s = (const uint4*)(gsrc + (size_t)row * D);
        #pragma unroll
        for (int jj = 0; jj < 4; jj++) {
            int j = h * 4 + jj;
            unsigned o = r * 128 + ((j ^ (r & 7)) << 4);
            sts128(dst0 + o, s[j]);
            sts128(dst1 + o, s[8 + j]);
        }
    } else {
        uint4 z = make_uint4(0u, 0u, 0u, 0u);
        #pragma unroll
        for (int jj = 0; jj < 4; jj++) {
            int j = h * 4 + jj;
            unsigned o = r * 128 + ((j ^ (r & 7)) << 4);
            sts128(dst0 + o, z);
            sts128(dst1 + o, z);
        }
    }
}

__device__ __forceinline__ unsigned sw_addr(unsigned tile, int row, int kb) {
    return tile + row * 128 + (((unsigned)(kb ^ (row & 7))) << 4);
}

template<bool SCORE, int NPAIR>
__global__ __launch_bounds__(256, 2) void mma_gemm_kernel(
    const __nv_bfloat16* __restrict__ A0hi, const __nv_bfloat16* __restrict__ A0lo,
    const __nv_bfloat16* __restrict__ B0hi, const __nv_bfloat16* __restrict__ B0lo,
    const __nv_bfloat16* __restrict__ A1hi, const __nv_bfloat16* __restrict__ A1lo,
    const __nv_bfloat16* __restrict__ B1hi, const __nv_bfloat16* __restrict__ B1lo,
    float* __restrict__ outp, int coff, int ldc, int nvalid)
{
    extern __shared__ char dsm[];
    const int tid  = threadIdx.x;
    const int wid  = tid >> 5, lane = tid & 31;
    const int m0   = blockIdx.x * 128;
    const int n0   = blockIdx.y * 128;

    unsigned tb = (smem_u32(dsm) + 1023) & ~1023u;
    unsigned tA[4] = { tb, tb + SC_TILE, tb + 2*SC_TILE, tb + 3*SC_TILE };
    unsigned tB[2] = { tb + 4*SC_TILE, tb + 5*SC_TILE };

    const int m0w = (wid & 3) * 32;
    const int n0w = (wid >> 2) * 64;
    const int arow = m0w + (lane & 15);
    const int asub = lane >> 4;
    const int brow0 = n0w + ((lane >> 4) << 3) + (lane & 7);
    const int bsub  = (lane >> 3) & 1;

    float acc[2][8][4];
    #pragma unroll
    for (int i = 0; i < 2; i++)
        #pragma unroll
        for (int j = 0; j < 8; j++)
            #pragma unroll
            for (int q = 0; q < 4; q++) acc[i][j][q] = 0.f;

    #pragma unroll
    for (int pr = 0; pr < NPAIR; pr++) {
        const __nv_bfloat16* Ahi = (pr == 0) ? A0hi : A1hi;
        const __nv_bfloat16* Alo = (pr == 0) ? A0lo : A1lo;
        const __nv_bfloat16* Bhi = (pr == 0) ? B0hi : B1hi;
        const __nv_bfloat16* Blo = (pr == 0) ? B0lo : B1lo;

        if (pr > 0) __syncthreads();           // protect prior pass reads
        stage_tile(tA[0], tA[1], Ahi, m0, 0x7fffffff, tid);
        stage_tile(tA[2], tA[3], Alo, m0, 0x7fffffff, tid);
        stage_tile(tB[0], tB[1], Bhi, n0, nvalid, tid);
        __syncthreads();

        // ---- pass 1: (Ahi + Alo) x Bhi ----
        #pragma unroll
        for (int c = 0; c < 2; c++) {
            #pragma unroll
            for (int kq = 0; kq < 4; kq++) {
                const int kbA = kq * 2 + asub;
                const int kbB = kq * 2 + bsub;
                unsigned bf[8][2];
                #pragma unroll
                for (int p = 0; p < 4; p++)
                    ldm4(bf[2*p][0], bf[2*p][1], bf[2*p+1][0], bf[2*p+1][1],
                         sw_addr(tB[c], brow0 + p * 16, kbB));
                unsigned af[2][4];
                #pragma unroll
                for (int mf = 0; mf < 2; mf++)
                    ldm4(af[mf][0], af[mf][1], af[mf][2], af[mf][3],
                         sw_addr(tA[c], arow + mf * 16, kbA));
                #pragma unroll
                for (int mf = 0; mf < 2; mf++)
                    #pragma unroll
                    for (int nf = 0; nf < 8; nf++)
                        mma16816(acc[mf][nf], af[mf], bf[nf]);
                #pragma unroll
                for (int mf = 0; mf < 2; mf++)
                    ldm4(af[mf][0], af[mf][1], af[mf][2], af[mf][3],
                         sw_addr(tA[2 + c], arow + mf * 16, kbA));
                #pragma unroll
                for (int mf = 0; mf < 2; mf++)
                    #pragma unroll
                    for (int nf = 0; nf < 8; nf++)
                        mma16816(acc[mf][nf], af[mf], bf[nf]);
            }
        }
        __syncthreads();

        stage_tile(tB[0], tB[1], Blo, n0, nvalid, tid);
        __syncthreads();

        // ---- pass 2: Ahi x Blo ----
        #pragma unroll
        for (int c = 0; c < 2; c++) {
            #pragma unroll
            for (int kq = 0; kq < 4; kq++) {
                const int kbA = kq * 2 + asub;
                const int kbB = kq * 2 + bsub;
                unsigned bf[8][2];
                #pragma unroll
                for (int p = 0; p < 4; p++)
                    ldm4(bf[2*p][0], bf[2*p][1], bf[2*p+1][0], bf[2*p+1][1],
                         sw_addr(tB[c], brow0 + p * 16, kbB));
                unsigned af[2][4];
                #pragma unroll
                for (int mf = 0; mf < 2; mf++)
                    ldm4(af[mf][0], af[mf][1], af[mf][2], af[mf][3],
                         sw_addr(tA[c], arow + mf * 16, kbA));
                #pragma unroll
                for (int mf = 0; mf < 2; mf++)
                    #pragma unroll
                    for (int nf = 0; nf < 8; nf++)
                        mma16816(acc[mf][nf], af[mf], bf[nf]);
            }
        }
    }

    // ---- epilogue ----
    float* C = SCORE ? outp : (g_blob + coff);
    const int rbase = lane >> 2;
    const int cbase = (lane & 3) * 2;
    #pragma unroll
    for (int mf = 0; mf < 2; mf++) {
        const int mA = m0 + m0w + mf * 16 + rbase;
        const int mB = mA + 8;
        bool okA = true, okB = true;
        if (SCORE) { okA = (g_cntv[mA] >= 2); okB = (g_cntv[mB] >= 2); }
        #pragma unroll
        for (int nf = 0; nf < 8; nf++) {
            const int n = n0 + n0w + nf * 8 + cbase;
            if (n < nvalid) {
                float2 vA, vB;
                vA.x = acc[mf][nf][0]; vA.y = acc[mf][nf][1];
                vB.x = acc[mf][nf][2]; vB.y = acc[mf][nf][3];
                if (SCORE) {
                    if (!okA) { vA.x = (n == 0) ? 0.0f : NEGV; vA.y = NEGV; }
                    if (!okB) { vB.x = (n == 0) ? 0.0f : NEGV; vB.y = NEGV; }
                }
                *(float2*)&C[(size_t)mA * ldc + n] = vA;
                *(float2*)&C[(size_t)mB * ldc + n] = vB;
            }
        }
    }
}

// ---------------------------------------------------------------------------
// K3: per-sample edge aggregation.  X = Hin + agg(Hout[src])/deg -> bf16 hi/lo
// ---------------------------------------------------------------------------
__global__ __launch_bounds__(256) void agg_kernel()
{
    extern __shared__ float agg[];            // L*D floats
    __shared__ int   cinv[L];
    __shared__ float rdeg[L];
    const int b = blockIdx.x, tid = threadIdx.x;

    if (tid < L) { cinv[tid] = g_cinv[b * L + tid]; rdeg[tid] = 0.f; }
    for (int i = tid; i < L * D / 4; i += 256)
        ((float4*)agg)[i] = make_float4(0.f, 0.f, 0.f, 0.f);
    __syncthreads();

    const int cnt = g_cntv[b];
    if (tid < cnt - 1) atomicAdd(&rdeg[cinv[tid + 1]], 1.0f);
    __syncthreads();
    if (tid < L) rdeg[tid] = 1.0f / fmaxf(rdeg[tid], 1.0f);

    const float* Hio = g_blob + OFF_HIO + (size_t)b * L * 2 * D;
    const int nedge = (cnt >= 1) ? cnt - 1 : 0;
    for (int idx = tid; idx < nedge * D; idx += 256) {
        int t = idx >> 7, k = idx & 127;
        atomicAdd(&agg[cinv[t + 1] * D + k], Hio[(size_t)cinv[t] * 2 * D + D + k]);
    }
    __syncthreads();

    for (int idx = tid; idx < L * D; idx += 256) {
        int r = idx >> 7;
        float v = Hio[(size_t)r * 2 * D + (idx & 127)] + agg[idx] * rdeg[r];
        __nv_bfloat16 h = __float2bfloat16(v);
        g_xhi[(size_t)b * L * D + idx] = h;
        g_xlo[(size_t)b * L * D + idx] = __float2bfloat16(v - __bfloat162float(h));
    }
}

// ---------------------------------------------------------------------------
// K4: fused GRU + attention readout (one CTA per sample, H in SMEM)
// ---------------------------------------------------------------------------
__global__ __launch_bounds__(256) void gru_attn_kernel(
    const float* __restrict__ b_ih, const float* __restrict__ b_hh,
    const float* __restrict__ W_read, const float* __restrict__ b_read)
{
    extern __shared__ float H[];              // L*D floats
    __shared__ float hlast[D], loc[D], sc[L];
    const int b = blockIdx.x, tid = threadIdx.x;
    const int nn = g_nn[b], li = g_li[b];

    // GRU elementwise: H = (1-z)*nct + z*h0
    for (int idx = tid; idx < L * D; idx += 256) {
        int row = idx >> 7, j = idx & 127;
        size_t base = (size_t)b * L + row;
        float sr  = g_blob[OFF_SRZ + base * 256 + j];
        float sz  = g_blob[OFF_SRZ + base * 256 + 128 + j];
        float gin = g_blob[OFF_GIN + base * 128 + j];
        float ghn = g_blob[OFF_GHN + base * 128 + j];
        float h0  = __bfloat162float(g_hallhi[base * 128 + j])
                  + __bfloat162float(g_halllo[base * 128 + j]);
        float r = 1.0f / (1.0f + expf(-(sr + b_ih[j] + b_hh[j])));
        float z = 1.0f / (1.0f + expf(-(sz + b_ih[D + j] + b_hh[D + j])));
        float n = tanhf(gin + b_ih[2 * D + j] + r * (ghn + b_hh[2 * D + j]));
        H[idx] = (1.0f - z) * n + z * h0;
    }
    __syncthreads();

    if (tid < D) hlast[tid] = H[li * D + tid];
    __syncthreads();

    const int w = tid >> 5, lane = tid & 31;
    for (int r = w; r < nn; r += 8) {
        const float* hr = H + r * D;
        float acc = 0.f;
        #pragma unroll
        for (int k = lane; k < D; k += 32) acc = fmaf(hr[k], hlast[k], acc);
        #pragma unroll
        for (int off = 16; off; off >>= 1)
            acc += __shfl_down_sync(0xffffffffu, acc, off);
        if (lane == 0) sc[r] = acc;
    }
    __syncthreads();

    if (tid == 0) {
        float m = -1e30f;
        for (int i = 0; i < nn; i++) m = fmaxf(m, sc[i]);
        float s = 0.f;
        for (int i = 0; i < nn; i++) { float e = expf(sc[i] - m); sc[i] = e; s += e; }
        float inv = (s > 0.f) ? 1.0f / s : 0.f;
        for (int i = 0; i < nn; i++) sc[i] *= inv;
    }
    __syncthreads();

    if (tid < D) {
        float acc = 0.f;
        for (int r = 0; r < nn; r++) acc = fmaf(sc[r], H[r * D + tid], acc);
        loc[tid] = acc;
    }
    __syncthreads();

    #pragma unroll
    for (int t = 0; t < 16; t++) {
        int j = w * 16 + t;
        const float* wr = W_read + (size_t)j * (3 * D);
        float acc = 0.f;
        #pragma unroll
        for (int k = lane; k < D; k += 32)
            acc += wr[k] * hlast[k] + wr[D + k] * loc[k];
        #pragma unroll
        for (int off = 16; off; off >>= 1)
            acc += __shfl_down_sync(0xffffffffu, acc, off);
        if (lane == 0) {
            float hv = tanhf(acc + b_read[j]);
            __nv_bfloat16 h = __float2bfloat16(hv);
            g_ahi[b * D + j] = h;
            g_alo[b * D + j] = __float2bfloat16(hv - __bfloat162float(h));
        }
    }
}

// ---------------------------------------------------------------------------
extern "C" void kernel_launch(void* const* d_in, const int* in_sizes, int n_in,
                              void* d_out, int out_size)
{
    const int*   x      = (const int*)  d_in[0];
    // d_in[1] = attn_mask (unused by reference)
    const float* emb    = (const float*)d_in[2];
    const float* W_in   = (const float*)d_in[3];
    const float* W_out  = (const float*)d_in[4];
    const float* w_ih   = (const float*)d_in[5];
    const float* w_hh   = (const float*)d_in[6];
    const float* b_ih   = (const float*)d_in[7];
    const float* b_hh   = (const float*)d_in[8];
    const float* W_read = (const float*)d_in[9];
    const float* b_read = (const float*)d_in[10];
    float* out = (float*)d_out;

    cudaFuncSetAttribute(agg_kernel,
        cudaFuncAttributeMaxDynamicSharedMemorySize, L * D * (int)sizeof(float));
    cudaFuncSetAttribute(gru_attn_kernel,
        cudaFuncAttributeMaxDynamicSharedMemorySize, L * D * (int)sizeof(float));
    cudaFuncSetAttribute(mma_gemm_kernel<false, 1>,
        cudaFuncAttributeMaxDynamicSharedMemorySize, SC_SMEM);
    cudaFuncSetAttribute(mma_gemm_kernel<false, 2>,
        cudaFuncAttributeMaxDynamicSharedMemorySize, SC_SMEM);
    cudaFuncSetAttribute(mma_gemm_kernel<true, 1>,
        cudaFuncAttributeMaxDynamicSharedMemorySize, SC_SMEM);

    __nv_bfloat16 *ehi, *elo, *ahi, *alo, *hallhi, *halllo, *xhi, *xlo;
    __nv_bfloat16 *wiohi, *wiolo, *whhhi, *whhlo, *wihhi, *wihlo;
    cudaGetSymbolAddress((void**)&ehi,    g_ehi);
    cudaGetSymbolAddress((void**)&elo,    g_elo);
    cudaGetSymbolAddress((void**)&ahi,    g_ahi);
    cudaGetSymbolAddress((void**)&alo,    g_alo);
    cudaGetSymbolAddress((void**)&hallhi, g_hallhi);
    cudaGetSymbolAddress((void**)&halllo, g_halllo);
    cudaGetSymbolAddress((void**)&xhi,    g_xhi);
    cudaGetSymbolAddress((void**)&xlo,    g_xlo);
    cudaGetSymbolAddress((void**)&wiohi,  g_wiohi);
    cudaGetSymbolAddress((void**)&wiolo,  g_wiolo);
    cudaGetSymbolAddress((void**)&whhhi,  g_whhhi);
    cudaGetSymbolAddress((void**)&whhlo,  g_whhlo);
    cudaGetSymbolAddress((void**)&wihhi,  g_wihhi);
    cudaGetSymbolAddress((void**)&wihlo,  g_wihlo);

    // K0: all fp32 -> bf16 hi/lo conversions in one launch
    conv_all_kernel<<<CONV_GROUPS / 256, 256>>>(emb, W_in, W_out, w_hh, w_ih);

    // K1: graph build + bf16 hi/lo gather
    build_kernel<<<BATCH, 256>>>(x);

    // G1: Hin | Hout = Hall @ [W_in; W_out]^T
    mma_gemm_kernel<false, 1><<<dim3(ROWS / 128, 2), 256, SC_SMEM>>>(
        hallhi, halllo, wiohi, wiolo, nullptr, nullptr, nullptr, nullptr,
        nullptr, OFF_HIO, 2 * D, 2 * D);

    // G_ghn: gh_n = Hall @ w_hh_n^T  (independent of agg)
    mma_gemm_kernel<false, 1><<<dim3(ROWS / 128, 1), 256, SC_SMEM>>>(
        hallhi, halllo, whhhi + 2 * D * D, whhlo + 2 * D * D,
        nullptr, nullptr, nullptr, nullptr,
        nullptr, OFF_GHN, D, D);

    // K3: X = Hin + agg/deg -> bf16 hi/lo
    agg_kernel<<<BATCH, 256, L * D * sizeof(float)>>>();

    // G_rz: s_rz = X @ w_ih_rz^T + Hall @ w_hh_rz^T   (dual-A fusion)
    mma_gemm_kernel<false, 2><<<dim3(ROWS / 128, 2), 256, SC_SMEM>>>(
        xhi, xlo, wihhi, wihlo,
        hallhi, halllo, whhhi, whhlo,
        nullptr, OFF_SRZ, 2 * D, 2 * D);

    // G_gin: gi_n = X @ w_ih_n^T
    mma_gemm_kernel<false, 1><<<dim3(ROWS / 128, 1), 256, SC_SMEM>>>(
        xhi, xlo, wihhi + 2 * D * D, wihlo + 2 * D * D,
        nullptr, nullptr, nullptr, nullptr,
        nullptr, OFF_GIN, D, D);

    // K4: fused GRU + attention -> h_read hi/lo
    gru_attn_kernel<<<BATCH, 256, L * D * sizeof(float)>>>(b_ih, b_hh, W_read, b_read);

    // K6: tensor-core score GEMM
    mma_gemm_kernel<true, 1><<<dim3(BATCH / 128, (NITEMS + 127) / 128), 256, SC_SMEM>>>(
        ahi, alo, ehi, elo,
        nullptr, nullptr, nullptr, nullptr,
        out, 0, NITEMS, NITEMS);
}

// round 13
// speedup vs baseline: 4.2703x; 1.0847x over previous
#include <cuda_runtime.h>
#include <cuda_bf16.h>
#include <math.h>

#define BATCH  512
#define L      100
#define D      128
#define NITEMS 100000
#define NEGV   -1000000000.0f
#define ROWS   (BATCH * L)          // 51200 padded node rows

// ---- scratch blob offsets (floats) ----
#define OFF_HIO   0                         // [ROWS][256]  Hin | Hout
#define OFF_SRZ   (ROWS * 2 * D)            // [ROWS][256]  gi_r+gh_r | gi_z+gh_z
#define OFF_GIN   (OFF_SRZ + ROWS * 2 * D)  // [ROWS][128]
#define OFF_GHN   (OFF_GIN + ROWS * D)      // [ROWS][128]
#define BLOB_SZ   (OFF_GHN + ROWS * D)

__device__ __align__(128) float g_blob[BLOB_SZ];
__device__ int g_cinv[BATCH * L];
__device__ int g_nn[BATCH];
__device__ int g_cntv[BATCH];
__device__ int g_li[BATCH];

// bf16 hi/lo split operands for tensor-core GEMMs
__device__ __align__(16) __nv_bfloat16 g_ehi[NITEMS * D];
__device__ __align__(16) __nv_bfloat16 g_elo[NITEMS * D];
__device__ __align__(16) __nv_bfloat16 g_ahi[BATCH * D];
__device__ __align__(16) __nv_bfloat16 g_alo[BATCH * D];
__device__ __align__(16) __nv_bfloat16 g_hallhi[ROWS * D];
__device__ __align__(16) __nv_bfloat16 g_halllo[ROWS * D];
__device__ __align__(16) __nv_bfloat16 g_xhi[ROWS * D];
__device__ __align__(16) __nv_bfloat16 g_xlo[ROWS * D];
__device__ __align__(16) __nv_bfloat16 g_wiohi[2 * D * D];   // [W_in; W_out]
__device__ __align__(16) __nv_bfloat16 g_wiolo[2 * D * D];
__device__ __align__(16) __nv_bfloat16 g_whhhi[3 * D * D];
__device__ __align__(16) __nv_bfloat16 g_whhlo[3 * D * D];
__device__ __align__(16) __nv_bfloat16 g_wihhi[3 * D * D];
__device__ __align__(16) __nv_bfloat16 g_wihlo[3 * D * D];

// ---- smem / warp-mma / cp.async helpers (arch-generic PTX: sm_80+) ----
__device__ __forceinline__ unsigned smem_u32(const void* p) {
    unsigned a;
    asm("{ .reg .u64 t; cvta.to.shared.u64 t, %1; cvt.u32.u64 %0, t; }" : "=r"(a) : "l"(p));
    return a;
}
__device__ __forceinline__ void sts128(unsigned addr, uint4 v) {
    asm volatile("st.shared.v4.b32 [%0], {%1,%2,%3,%4};"
                 :: "r"(addr), "r"(v.x), "r"(v.y), "r"(v.z), "r"(v.w));
}
__device__ __forceinline__ void ldm4(unsigned& r0, unsigned& r1,
                                     unsigned& r2, unsigned& r3, unsigned addr) {
    asm volatile("ldmatrix.sync.aligned.m8n8.x4.shared.b16 {%0,%1,%2,%3}, [%4];"
                 : "=r"(r0), "=r"(r1), "=r"(r2), "=r"(r3) : "r"(addr));
}
__device__ __forceinline__ void mma16816(float* c, const unsigned* a, const unsigned* b) {
    asm volatile("mma.sync.aligned.m16n8k16.row.col.f32.bf16.bf16.f32 "
                 "{%0,%1,%2,%3}, {%4,%5,%6,%7}, {%8,%9}, {%0,%1,%2,%3};"
                 : "+f"(c[0]), "+f"(c[1]), "+f"(c[2]), "+f"(c[3])
                 : "r"(a[0]), "r"(a[1]), "r"(a[2]), "r"(a[3]),
                   "r"(b[0]), "r"(b[1]));
}
__device__ __forceinline__ void cp16(unsigned dst, const void* src) {
    asm volatile("cp.async.cg.shared.global [%0], [%1], 16;" :: "r"(dst), "l"(src));
}
#define CP_COMMIT()  asm volatile("cp.async.commit_group;" ::: "memory")
#define CP_WAIT(n)   asm volatile("cp.async.wait_group %0;" :: "n"(n) : "memory")

#define TILE 16384
#define PS_SMEM (1024 + 12 * TILE)    // 197,632 B -> 1 CTA/SM

// ---------------------------------------------------------------------------
// staging: one [128][128B] x2 chunk pair, XOR-16B swizzle
// ---------------------------------------------------------------------------
__device__ __forceinline__ void stage_tile(
    unsigned dst0, unsigned dst1, const __nv_bfloat16* gsrc,
    int row0, int maxrow, int tid)
{
    const int r = tid >> 1;            // 0..127
    const int h = tid & 1;
    const int row = row0 + r;
    if (row < maxrow) {
        const uint4* s = (const uint4*)(gsrc + (size_t)row * D);
        #pragma unroll
        for (int jj = 0; jj < 4; jj++) {
            int j = h * 4 + jj;
            unsigned o = r * 128 + ((j ^ (r & 7)) << 4);
            sts128(dst0 + o, s[j]);
            sts128(dst1 + o, s[8 + j]);
        }
    } else {
        uint4 z = make_uint4(0u, 0u, 0u, 0u);
        #pragma unroll
        for (int jj = 0; jj < 4; jj++) {
            int j = h * 4 + jj;
            unsigned o = r * 128 + ((j ^ (r & 7)) << 4);
            sts128(dst0 + o, z);
            sts128(dst1 + o, z);
        }
    }
}

__device__ __forceinline__ void stage_tile_async(
    unsigned dst0, unsigned dst1, const __nv_bfloat16* gsrc,
    int row0, int maxrow, int tid)
{
    const int r = tid >> 1;
    const int h = tid & 1;
    const int row = row0 + r;
    if (row < maxrow) {
        const char* base = (const char*)(gsrc + (size_t)row * D);
        #pragma unroll
        for (int jj = 0; jj < 4; jj++) {
            int j = h * 4 + jj;
            unsigned o = r * 128 + ((j ^ (r & 7)) << 4);
            cp16(dst0 + o, base + j * 16);
            cp16(dst1 + o, base + 128 + j * 16);
        }
    } else {
        uint4 z = make_uint4(0u, 0u, 0u, 0u);
        #pragma unroll
        for (int jj = 0; jj < 4; jj++) {
            int j = h * 4 + jj;
            unsigned o = r * 128 + ((j ^ (r & 7)) << 4);
            sts128(dst0 + o, z);
            sts128(dst1 + o, z);
        }
    }
}

__device__ __forceinline__ unsigned sw_addr(unsigned tile, int row, int kb) {
    return tile + row * 128 + (((unsigned)(kb ^ (row & 7))) << 4);
}

// fused single-pass 3-term: acc += Ahi·Bhi + Alo·Bhi + Ahi·Blo
__device__ __forceinline__ void compute_3term(
    float (&acc)[2][8][4],
    const unsigned* tAhi, const unsigned* tAlo,
    const unsigned* tBhi, const unsigned* tBlo,
    int arow, int asub, int brow0, int bsub)
{
    #pragma unroll
    for (int c = 0; c < 2; c++) {
        #pragma unroll
        for (int kq = 0; kq < 4; kq++) {
            const int kbA = kq * 2 + asub;
            const int kbB = kq * 2 + bsub;
            unsigned bfh[8][2];
            #pragma unroll
            for (int p = 0; p < 4; p++)
                ldm4(bfh[2*p][0], bfh[2*p][1], bfh[2*p+1][0], bfh[2*p+1][1],
                     sw_addr(tBhi[c], brow0 + p * 16, kbB));
            unsigned afh[2][4];
            #pragma unroll
            for (int mf = 0; mf < 2; mf++)
                ldm4(afh[mf][0], afh[mf][1], afh[mf][2], afh[mf][3],
                     sw_addr(tAhi[c], arow + mf * 16, kbA));
            #pragma unroll
            for (int mf = 0; mf < 2; mf++)
                #pragma unroll
                for (int nf = 0; nf < 8; nf++)
                    mma16816(acc[mf][nf], afh[mf], bfh[nf]);
            unsigned afl[2][4];
            #pragma unroll
            for (int mf = 0; mf < 2; mf++)
                ldm4(afl[mf][0], afl[mf][1], afl[mf][2], afl[mf][3],
                     sw_addr(tAlo[c], arow + mf * 16, kbA));
            #pragma unroll
            for (int mf = 0; mf < 2; mf++)
                #pragma unroll
                for (int nf = 0; nf < 8; nf++)
                    mma16816(acc[mf][nf], afl[mf], bfh[nf]);
            unsigned bfl[8][2];
            #pragma unroll
            for (int p = 0; p < 4; p++)
                ldm4(bfl[2*p][0], bfl[2*p][1], bfl[2*p+1][0], bfl[2*p+1][1],
                     sw_addr(tBlo[c], brow0 + p * 16, kbB));
            #pragma unroll
            for (int mf = 0; mf < 2; mf++)
                #pragma unroll
                for (int nf = 0; nf < 8; nf++)
                    mma16816(acc[mf][nf], afh[mf], bfl[nf]);
        }
    }
}

// ---------------------------------------------------------------------------
// K0: ALL fp32 -> bf16 hi/lo splits in one launch
// ---------------------------------------------------------------------------
#define E4   (NITEMS * D / 4)
#define W4   (D * D / 4)
#define W34  (3 * D * D / 4)
#define CONV_GROUPS (E4 + 2 * W4 + 2 * W34)

__global__ __launch_bounds__(256) void conv_all_kernel(
    const float* __restrict__ emb,  const float* __restrict__ W_in,
    const float* __restrict__ W_out, const float* __restrict__ w_hh,
    const float* __restrict__ w_ih)
{
    size_t i = (size_t)blockIdx.x * 256 + threadIdx.x;
    const float* src; __nv_bfloat16 *dhi, *dlo; size_t off;
    if (i < E4)                    { src = emb;   off = i;                 dhi = g_ehi;            dlo = g_elo; }
    else if (i < E4 + W4)          { src = W_in;  off = i - E4;            dhi = g_wiohi;          dlo = g_wiolo; }
    else if (i < E4 + 2 * W4)      { src = W_out; off = i - E4 - W4;       dhi = g_wiohi + D * D;  dlo = g_wiolo + D * D; }
    else if (i < E4 + 2 * W4 + W34){ src = w_hh;  off = i - E4 - 2 * W4;   dhi = g_whhhi;          dlo = g_whhlo; }
    else                           { src = w_ih;  off = i - E4 - 2*W4 - W34; dhi = g_wihhi;        dlo = g_wihlo; }

    float4 v = ((const float4*)src)[off];
    __nv_bfloat162 h01 = __floats2bfloat162_rn(v.x, v.y);
    __nv_bfloat162 h23 = __floats2bfloat162_rn(v.z, v.w);
    __nv_bfloat162 l01 = __floats2bfloat162_rn(v.x - __low2float(h01), v.y - __high2float(h01));
    __nv_bfloat162 l23 = __floats2bfloat162_rn(v.z - __low2float(h23), v.w - __high2float(h23));
    ((__nv_bfloat162*)dhi)[2 * off]     = h01;
    ((__nv_bfloat162*)dhi)[2 * off + 1] = h23;
    ((__nv_bfloat162*)dlo)[2 * off]     = l01;
    ((__nv_bfloat162*)dlo)[2 * off + 1] = l23;
}

// ---------------------------------------------------------------------------
// K1: per-sample graph build + bf16 hi/lo gather
// ---------------------------------------------------------------------------
__global__ __launch_bounds__(256) void build_kernel(const int* __restrict__ x)
{
    __shared__ int s_seq[L], s_rep[L], s_nodes[L], s_cinv[L];
    __shared__ int s_nn, s_cnt;
    const int b = blockIdx.x, tid = threadIdx.x;

    if (tid == 0) { s_nn = 0; s_cnt = 0; }
    if (tid < L) { s_seq[tid] = x[b * L + tid]; s_cinv[tid] = 0; }
    __syncthreads();

    int mypos = 0;
    if (tid < L) {
        int s = s_seq[tid];
        int rep = (s != 0);
        for (int j = 0; j < tid; j++) {
            int sj = s_seq[j];
            if (sj != 0) { mypos++; if (sj == s) rep = 0; }
        }
        s_rep[tid] = rep;
    }
    __syncthreads();

    if (tid < L) {
        int s = s_seq[tid];
        if (s != 0) {
            int rank = 0;
            for (int j = 0; j < L; j++)
                if (s_rep[j] && s_seq[j] < s) rank++;
            if (s_rep[tid]) { s_nodes[rank] = s; atomicAdd(&s_nn, 1); }
            s_cinv[mypos] = rank;
            atomicAdd(&s_cnt, 1);
        }
    }
    __syncthreads();

    const int nn = s_nn, cnt = s_cnt;

    for (int idx = tid; idx < L * 16; idx += 256) {
        int r = idx >> 4, q = idx & 15;
        uint4 vh = make_uint4(0u, 0u, 0u, 0u), vl = vh;
        if (r < nn) {
            vh = ((const uint4*)(g_ehi + (size_t)s_nodes[r] * D))[q];
            vl = ((const uint4*)(g_elo + (size_t)s_nodes[r] * D))[q];
        }
        ((uint4*)(g_hallhi + ((size_t)b * L + r) * D))[q] = vh;
        ((uint4*)(g_halllo + ((size_t)b * L + r) * D))[q] = vl;
    }
    if (tid < L) g_cinv[b * L + tid] = s_cinv[tid];
    if (tid == 0) {
        g_nn[b] = nn;
        g_cntv[b] = cnt;
        g_li[b] = (cnt > 0) ? s_cinv[cnt - 1] : 0;
    }
}

// ---------------------------------------------------------------------------
// Persistent internal GEMM: weights resident, A streamed (double-buffered
// cp.async for NPAIR=1; sequential pair staging for NPAIR=2).
// C(m-tile, n0) = sum_pairs 3-term(A_pair, B_pair)
// ---------------------------------------------------------------------------
template<int NPAIR>
__global__ void __launch_bounds__(256) internal_persist_kernel(
    const __nv_bfloat16* __restrict__ A0hi, const __nv_bfloat16* __restrict__ A0lo,
    const __nv_bfloat16* __restrict__ B0hi, const __nv_bfloat16* __restrict__ B0lo,
    const __nv_bfloat16* __restrict__ A1hi, const __nv_bfloat16* __restrict__ A1lo,
    const __nv_bfloat16* __restrict__ B1hi, const __nv_bfloat16* __restrict__ B1lo,
    int coff, int ldc, int mtiles)
{
    extern __shared__ char dsm[];
    const int tid = threadIdx.x, wid = tid >> 5, lane = tid & 31;
    const int n0 = blockIdx.y * 128;
    unsigned tb = (smem_u32(dsm) + 1023) & ~1023u;

    unsigned b0hi[2] = { tb,            tb + TILE };
    unsigned b0lo[2] = { tb + 2*TILE,   tb + 3*TILE };
    unsigned b1hi[2] = { tb + 4*TILE,   tb + 5*TILE };
    unsigned b1lo[2] = { tb + 6*TILE,   tb + 7*TILE };

    // resident weights
    stage_tile(b0hi[0], b0hi[1], B0hi, n0, 0x7fffffff, tid);
    stage_tile(b0lo[0], b0lo[1], B0lo, n0, 0x7fffffff, tid);
    if (NPAIR == 2) {
        stage_tile(b1hi[0], b1hi[1], B1hi, n0, 0x7fffffff, tid);
        stage_tile(b1lo[0], b1lo[1], B1lo, n0, 0x7fffffff, tid);
    }

    const int m0w = (wid & 3) * 32;
    const int n0w = (wid >> 2) * 64;
    const int arow = m0w + (lane & 15);
    const int asub = lane >> 4;
    const int brow0 = n0w + ((lane >> 4) << 3) + (lane & 7);
    const int bsub  = (lane >> 3) & 1;
    const int rbase = lane >> 2;
    const int cbase = (lane & 3) * 2;
    float* C = g_blob + coff;

    if (NPAIR == 1) {
        // A double-buffered: buf b at tb + (4 + 4b)*TILE
        unsigned ab[2][4];
        #pragma unroll
        for (int b = 0; b < 2; b++)
            #pragma unroll
            for (int t = 0; t < 4; t++)
                ab[b][t] = tb + (4 + 4 * b + t) * TILE;   // hi0,hi1,lo0,lo1

        int buf = 0;
        int mt = blockIdx.x;
        if (mt < mtiles) {
            stage_tile_async(ab[0][0], ab[0][1], A0hi, mt * 128, 0x7fffffff, tid);
            stage_tile_async(ab[0][2], ab[0][3], A0lo, mt * 128, 0x7fffffff, tid);
            CP_COMMIT();
        }
        for (; mt < mtiles; mt += gridDim.x) {
            int mtn = mt + gridDim.x;
            bool pf = mtn < mtiles;
            if (pf) {
                stage_tile_async(ab[buf^1][0], ab[buf^1][1], A0hi, mtn * 128, 0x7fffffff, tid);
                stage_tile_async(ab[buf^1][2], ab[buf^1][3], A0lo, mtn * 128, 0x7fffffff, tid);
                CP_COMMIT();
            }
            if (pf) { CP_WAIT(1); } else { CP_WAIT(0); }
            __syncthreads();

            float acc[2][8][4];
            #pragma unroll
            for (int i = 0; i < 2; i++)
                #pragma unroll
                for (int j = 0; j < 8; j++)
                    #pragma unroll
                    for (int q = 0; q < 4; q++) acc[i][j][q] = 0.f;

            unsigned ahi[2] = { ab[buf][0], ab[buf][1] };
            unsigned alo[2] = { ab[buf][2], ab[buf][3] };
            compute_3term(acc, ahi, alo, b0hi, b0lo, arow, asub, brow0, bsub);

            const int m0 = mt * 128;
            #pragma unroll
            for (int mf = 0; mf < 2; mf++) {
                const int mA = m0 + m0w + mf * 16 + rbase;
                #pragma unroll
                for (int nf = 0; nf < 8; nf++) {
                    const int n = n0 + n0w + nf * 8 + cbase;
                    float2 vA = { acc[mf][nf][0], acc[mf][nf][1] };
                    float2 vB = { acc[mf][nf][2], acc[mf][nf][3] };
                    *(float2*)&C[(size_t)mA * ldc + n] = vA;
                    *(float2*)&C[(size_t)(mA + 8) * ldc + n] = vB;
                }
            }
            __syncthreads();
            buf ^= 1;
        }
    } else {
        // NPAIR == 2: single A buffer at tb + 8*TILE, sequential pairs
        unsigned as_[4] = { tb + 8*TILE, tb + 9*TILE, tb + 10*TILE, tb + 11*TILE };
        unsigned ahi[2] = { as_[0], as_[1] };
        unsigned alo[2] = { as_[2], as_[3] };
        __syncthreads();   // resident B visible

        for (int mt = blockIdx.x; mt < mtiles; mt += gridDim.x) {
            stage_tile_async(as_[0], as_[1], A0hi, mt * 128, 0x7fffffff, tid);
            stage_tile_async(as_[2], as_[3], A0lo, mt * 128, 0x7fffffff, tid);
            CP_COMMIT(); CP_WAIT(0);
            __syncthreads();

            float acc[2][8][4];
            #pragma unroll
            for (int i = 0; i < 2; i++)
                #pragma unroll
                for (int j = 0; j < 8; j++)
                    #pragma unroll
                    for (int q = 0; q < 4; q++) acc[i][j][q] = 0.f;

            compute_3term(acc, ahi, alo, b0hi, b0lo, arow, asub, brow0, bsub);
            __syncthreads();

            stage_tile_async(as_[0], as_[1], A1hi, mt * 128, 0x7fffffff, tid);
            stage_tile_async(as_[2], as_[3], A1lo, mt * 128, 0x7fffffff, tid);
            CP_COMMIT(); CP_WAIT(0);
            __syncthreads();

            compute_3term(acc, ahi, alo, b1hi, b1lo, arow, asub, brow0, bsub);

            const int m0 = mt * 128;
            #pragma unroll
            for (int mf = 0; mf < 2; mf++) {
                const int mA = m0 + m0w + mf * 16 + rbase;
                #pragma unroll
                for (int nf = 0; nf < 8; nf++) {
                    const int n = n0 + n0w + nf * 8 + cbase;
                    float2 vA = { acc[mf][nf][0], acc[mf][nf][1] };
                    float2 vB = { acc[mf][nf][2], acc[mf][nf][3] };
                    *(float2*)&C[(size_t)mA * ldc + n] = vA;
                    *(float2*)&C[(size_t)(mA + 8) * ldc + n] = vB;
                }
            }
            __syncthreads();
        }
    }
}

// ---------------------------------------------------------------------------
// Persistent score GEMM: A (h_read) resident, emb tiles streamed with
// double-buffered cp.async; epilogue with cnt>=2 masking.
// ---------------------------------------------------------------------------
__global__ void __launch_bounds__(256) score_persist_kernel(
    const __nv_bfloat16* __restrict__ Ahi, const __nv_bfloat16* __restrict__ Alo,
    const __nv_bfloat16* __restrict__ Bhi, const __nv_bfloat16* __restrict__ Blo,
    float* __restrict__ out)
{
    extern __shared__ char dsm[];
    const int tid = threadIdx.x, wid = tid >> 5, lane = tid & 31;
    const int m0 = blockIdx.x * 128;
    unsigned tb = (smem_u32(dsm) + 1023) & ~1023u;

    unsigned tahi[2] = { tb,          tb + TILE };
    unsigned talo[2] = { tb + 2*TILE, tb + 3*TILE };
    unsigned bb[2][4];
    #pragma unroll
    for (int b = 0; b < 2; b++)
        #pragma unroll
        for (int t = 0; t < 4; t++)
            bb[b][t] = tb + (4 + 4 * b + t) * TILE;     // hi0,hi1,lo0,lo1

    stage_tile(tahi[0], tahi[1], Ahi, m0, BATCH, tid);
    stage_tile(talo[0], talo[1], Alo, m0, BATCH, tid);

    const int m0w = (wid & 3) * 32;
    const int n0w = (wid >> 2) * 64;
    const int arow = m0w + (lane & 15);
    const int asub = lane >> 4;
    const int brow0 = n0w + ((lane >> 4) << 3) + (lane & 7);
    const int bsub  = (lane >> 3) & 1;
    const int rbase = lane >> 2;
    const int cbase = (lane & 3) * 2;

    // per-CTA-invariant mask bits (hoisted out of the n loop)
    const int mA0 = m0 + m0w + rbase;
    const bool ok[4] = { g_cntv[mA0] >= 2,      g_cntv[mA0 + 8] >= 2,
                         g_cntv[mA0 + 16] >= 2, g_cntv[mA0 + 24] >= 2 };

    const int NT = (NITEMS + 127) / 128;     // 782
    int buf = 0;
    int nt = blockIdx.y;
    if (nt < NT) {
        stage_tile_async(bb[0][0], bb[0][1], Bhi, nt * 128, NITEMS, tid);
        stage_tile_async(bb[0][2], bb[0][3], Blo, nt * 128, NITEMS, tid);
        CP_COMMIT();
    }
    for (; nt < NT; nt += gridDim.y) {
        int ntn = nt + gridDim.y;
        bool pf = ntn < NT;
        if (pf) {
            stage_tile_async(bb[buf^1][0], bb[buf^1][1], Bhi, ntn * 128, NITEMS, tid);
            stage_tile_async(bb[buf^1][2], bb[buf^1][3], Blo, ntn * 128, NITEMS, tid);
            CP_COMMIT();
        }
        if (pf) { CP_WAIT(1); } else { CP_WAIT(0); }
        __syncthreads();

        float acc[2][8][4];
        #pragma unroll
        for (int i = 0; i < 2; i++)
            #pragma unroll
            for (int j = 0; j < 8; j++)
                #pragma unroll
                for (int q = 0; q < 4; q++) acc[i][j][q] = 0.f;

        unsigned bhi[2] = { bb[buf][0], bb[buf][1] };
        unsigned blo[2] = { bb[buf][2], bb[buf][3] };
        compute_3term(acc, tahi, talo, bhi, blo, arow, asub, brow0, bsub);

        const int n0 = nt * 128;
        #pragma unroll
        for (int mf = 0; mf < 2; mf++) {
            const int mA = mA0 + mf * 16;
            const bool okA = ok[mf * 2], okB = ok[mf * 2 + 1];
            #pragma unroll
            for (int nf = 0; nf < 8; nf++) {
                const int n = n0 + n0w + nf * 8 + cbase;
                if (n < NITEMS) {
                    float2 vA, vB;
                    if (okA) { vA.x = acc[mf][nf][0]; vA.y = acc[mf][nf][1]; }
                    else     { vA.x = (n == 0) ? 0.0f : NEGV; vA.y = NEGV; }
                    if (okB) { vB.x = acc[mf][nf][2]; vB.y = acc[mf][nf][3]; }
                    else     { vB.x = (n == 0) ? 0.0f : NEGV; vB.y = NEGV; }
                    *(float2*)&out[(size_t)mA * NITEMS + n] = vA;
                    *(float2*)&out[(size_t)(mA + 8) * NITEMS + n] = vB;
                }
            }
        }
        __syncthreads();
        buf ^= 1;
    }
}

// ---------------------------------------------------------------------------
// K3: per-sample edge aggregation.  X = Hin + agg(Hout[src])/deg -> bf16 hi/lo
// ---------------------------------------------------------------------------
__global__ __launch_bounds__(256) void agg_kernel()
{
    extern __shared__ float agg[];            // L*D floats
    __shared__ int   cinv[L];
    __shared__ float rdeg[L];
    const int b = blockIdx.x, tid = threadIdx.x;

    if (tid < L) { cinv[tid] = g_cinv[b * L + tid]; rdeg[tid] = 0.f; }
    for (int i = tid; i < L * D / 4; i += 256)
        ((float4*)agg)[i] = make_float4(0.f, 0.f, 0.f, 0.f);
    __syncthreads();

    const int cnt = g_cntv[b];
    if (tid < cnt - 1) atomicAdd(&rdeg[cinv[tid + 1]], 1.0f);
    __syncthreads();
    if (tid < L) rdeg[tid] = 1.0f / fmaxf(rdeg[tid], 1.0f);

    const float* Hio = g_blob + OFF_HIO + (size_t)b * L * 2 * D;
    const int nedge = (cnt >= 1) ? cnt - 1 : 0;
    for (int idx = tid; idx < nedge * D; idx += 256) {
        int t = idx >> 7, k = idx & 127;
        atomicAdd(&agg[cinv[t + 1] * D + k], Hio[(size_t)cinv[t] * 2 * D + D + k]);
    }
    __syncthreads();

    for (int idx = tid; idx < L * D; idx += 256) {
        int r = idx >> 7;
        float v = Hio[(size_t)r * 2 * D + (idx & 127)] + agg[idx] * rdeg[r];
        __nv_bfloat16 h = __float2bfloat16(v);
        g_xhi[(size_t)b * L * D + idx] = h;
        g_xlo[(size_t)b * L * D + idx] = __float2bfloat16(v - __bfloat162float(h));
    }
}

// ---------------------------------------------------------------------------
// K4: fused GRU + attention readout (one CTA per sample, H in SMEM)
// ---------------------------------------------------------------------------
__global__ __launch_bounds__(256) void gru_attn_kernel(
    const float* __restrict__ b_ih, const float* __restrict__ b_hh,
    const float* __restrict__ W_read, const float* __restrict__ b_read)
{
    extern __shared__ float H[];              // L*D floats
    __shared__ float hlast[D], loc[D], sc[L];
    const int b = blockIdx.x, tid = threadIdx.x;
    const int nn = g_nn[b], li = g_li[b];

    for (int idx = tid; idx < L * D; idx += 256) {
        int row = idx >> 7, j = idx & 127;
        size_t base = (size_t)b * L + row;
        float sr  = g_blob[OFF_SRZ + base * 256 + j];
        float sz  = g_blob[OFF_SRZ + base * 256 + 128 + j];
        float gin = g_blob[OFF_GIN + base * 128 + j];
        float ghn = g_blob[OFF_GHN + base * 128 + j];
        float h0  = __bfloat162float(g_hallhi[base * 128 + j])
                  + __bfloat162float(g_halllo[base * 128 + j]);
        float r = 1.0f / (1.0f + expf(-(sr + b_ih[j] + b_hh[j])));
        float z = 1.0f / (1.0f + expf(-(sz + b_ih[D + j] + b_hh[D + j])));
        float n = tanhf(gin + b_ih[2 * D + j] + r * (ghn + b_hh[2 * D + j]));
        H[idx] = (1.0f - z) * n + z * h0;
    }
    __syncthreads();

    if (tid < D) hlast[tid] = H[li * D + tid];
    __syncthreads();

    const int w = tid >> 5, lane = tid & 31;
    for (int r = w; r < nn; r += 8) {
        const float* hr = H + r * D;
        float acc = 0.f;
        #pragma unroll
        for (int k = lane; k < D; k += 32) acc = fmaf(hr[k], hlast[k], acc);
        #pragma unroll
        for (int off = 16; off; off >>= 1)
            acc += __shfl_down_sync(0xffffffffu, acc, off);
        if (lane == 0) sc[r] = acc;
    }
    __syncthreads();

    if (tid == 0) {
        float m = -1e30f;
        for (int i = 0; i < nn; i++) m = fmaxf(m, sc[i]);
        float s = 0.f;
        for (int i = 0; i < nn; i++) { float e = expf(sc[i] - m); sc[i] = e; s += e; }
        float inv = (s > 0.f) ? 1.0f / s : 0.f;
        for (int i = 0; i < nn; i++) sc[i] *= inv;
    }
    __syncthreads();

    if (tid < D) {
        float acc = 0.f;
        for (int r = 0; r < nn; r++) acc = fmaf(sc[r], H[r * D + tid], acc);
        loc[tid] = acc;
    }
    __syncthreads();

    #pragma unroll
    for (int t = 0; t < 16; t++) {
        int j = w * 16 + t;
        const float* wr = W_read + (size_t)j * (3 * D);
        float acc = 0.f;
        #pragma unroll
        for (int k = lane; k < D; k += 32)
            acc += wr[k] * hlast[k] + wr[D + k] * loc[k];
        #pragma unroll
        for (int off = 16; off; off >>= 1)
            acc += __shfl_down_sync(0xffffffffu, acc, off);
        if (lane == 0) {
            float hv = tanhf(acc + b_read[j]);
            __nv_bfloat16 h = __float2bfloat16(hv);
            g_ahi[b * D + j] = h;
            g_alo[b * D + j] = __float2bfloat16(hv - __bfloat162float(h));
        }
    }
}

// ---------------------------------------------------------------------------
extern "C" void kernel_launch(void* const* d_in, const int* in_sizes, int n_in,
                              void* d_out, int out_size)
{
    const int*   x      = (const int*)  d_in[0];
    // d_in[1] = attn_mask (unused by reference)
    const float* emb    = (const float*)d_in[2];
    const float* W_in   = (const float*)d_in[3];
    const float* W_out  = (const float*)d_in[4];
    const float* w_ih   = (const float*)d_in[5];
    const float* w_hh   = (const float*)d_in[6];
    const float* b_ih   = (const float*)d_in[7];
    const float* b_hh   = (const float*)d_in[8];
    const float* W_read = (const float*)d_in[9];
    const float* b_read = (const float*)d_in[10];
    float* out = (float*)d_out;

    cudaFuncSetAttribute(agg_kernel,
        cudaFuncAttributeMaxDynamicSharedMemorySize, L * D * (int)sizeof(float));
    cudaFuncSetAttribute(gru_attn_kernel,
        cudaFuncAttributeMaxDynamicSharedMemorySize, L * D * (int)sizeof(float));
    cudaFuncSetAttribute(internal_persist_kernel<1>,
        cudaFuncAttributeMaxDynamicSharedMemorySize, PS_SMEM);
    cudaFuncSetAttribute(internal_persist_kernel<2>,
        cudaFuncAttributeMaxDynamicSharedMemorySize, PS_SMEM);
    cudaFuncSetAttribute(score_persist_kernel,
        cudaFuncAttributeMaxDynamicSharedMemorySize, PS_SMEM);

    __nv_bfloat16 *ehi, *elo, *ahi, *alo, *hallhi, *halllo, *xhi, *xlo;
    __nv_bfloat16 *wiohi, *wiolo, *whhhi, *whhlo, *wihhi, *wihlo;
    cudaGetSymbolAddress((void**)&ehi,    g_ehi);
    cudaGetSymbolAddress((void**)&elo,    g_elo);
    cudaGetSymbolAddress((void**)&ahi,    g_ahi);
    cudaGetSymbolAddress((void**)&alo,    g_alo);
    cudaGetSymbolAddress((void**)&hallhi, g_hallhi);
    cudaGetSymbolAddress((void**)&halllo, g_halllo);
    cudaGetSymbolAddress((void**)&xhi,    g_xhi);
    cudaGetSymbolAddress((void**)&xlo,    g_xlo);
    cudaGetSymbolAddress((void**)&wiohi,  g_wiohi);
    cudaGetSymbolAddress((void**)&wiolo,  g_wiolo);
    cudaGetSymbolAddress((void**)&whhhi,  g_whhhi);
    cudaGetSymbolAddress((void**)&whhlo,  g_whhlo);
    cudaGetSymbolAddress((void**)&wihhi,  g_wihhi);
    cudaGetSymbolAddress((void**)&wihlo,  g_wihlo);

    // K0: all fp32 -> bf16 hi/lo conversions in one launch
    conv_all_kernel<<<CONV_GROUPS / 256, 256>>>(emb, W_in, W_out, w_hh, w_ih);

    // K1: graph build + bf16 hi/lo gather
    build_kernel<<<BATCH, 256>>>(x);

    // G1: Hin | Hout = Hall @ [W_in; W_out]^T  (persistent, weights resident)
    internal_persist_kernel<1><<<dim3(74, 2), 256, PS_SMEM>>>(
        hallhi, halllo, wiohi, wiolo,
        nullptr, nullptr, nullptr, nullptr, OFF_HIO, 2 * D, ROWS / 128);

    // G_ghn: gh_n = Hall @ w_hh_n^T
    internal_persist_kernel<1><<<dim3(148, 1), 256, PS_SMEM>>>(
        hallhi, halllo, whhhi + 2 * D * D, whhlo + 2 * D * D,
        nullptr, nullptr, nullptr, nullptr, OFF_GHN, D, ROWS / 128);

    // K3: X = Hin + agg/deg -> bf16 hi/lo
    agg_kernel<<<BATCH, 256, L * D * sizeof(float)>>>();

    // G_rz: s_rz = X @ w_ih_rz^T + Hall @ w_hh_rz^T   (dual-pair, B resident)
    internal_persist_kernel<2><<<dim3(74, 2), 256, PS_SMEM>>>(
        xhi, xlo, wihhi, wihlo,
        hallhi, halllo, whhhi, whhlo, OFF_SRZ, 2 * D, ROWS / 128);

    // G_gin: gi_n = X @ w_ih_n^T
    internal_persist_kernel<1><<<dim3(148, 1), 256, PS_SMEM>>>(
        xhi, xlo, wihhi + 2 * D * D, wihlo + 2 * D * D,
        nullptr, nullptr, nullptr, nullptr, OFF_GIN, D, ROWS / 128);

    // K4: fused GRU + attention -> h_read hi/lo
    gru_attn_kernel<<<BATCH, 256, L * D * sizeof(float)>>>(b_ih, b_hh, W_read, b_read);

    // K6: persistent tensor-core score GEMM (A resident, emb streamed)
    score_persist_kernel<<<dim3(BATCH / 128, 37), 256, PS_SMEM>>>(
        ahi, alo, ehi, elo, out);
}

// round 15
// speedup vs baseline: 4.2789x; 1.0020x over previous
#include <cuda_runtime.h>
#include <cuda_bf16.h>
#include <math.h>

#define BATCH  512
#define L      100
#define D      128
#define NITEMS 100000
#define NEGV   -1000000000.0f
#define ROWS   (BATCH * L)          // 51200 padded node rows

// ---- scratch blob offsets (floats) ----
#define OFF_HIO   0                         // [ROWS][256]  Hin | Hout
#define OFF_SRZ   (ROWS * 2 * D)            // [ROWS][256]  gi_r+gh_r | gi_z+gh_z
#define OFF_GIN   (OFF_SRZ + ROWS * 2 * D)  // [ROWS][128]
#define OFF_GHN   (OFF_GIN + ROWS * D)      // [ROWS][128]
#define BLOB_SZ   (OFF_GHN + ROWS * D)

__device__ __align__(128) float g_blob[BLOB_SZ];
__device__ int g_cinv[BATCH * L];
__device__ int g_nn[BATCH];
__device__ int g_cntv[BATCH];
__device__ int g_li[BATCH];

// bf16 hi/lo split operands for tensor-core GEMMs
__device__ __align__(16) __nv_bfloat16 g_ehi[NITEMS * D];
__device__ __align__(16) __nv_bfloat16 g_elo[NITEMS * D];
__device__ __align__(16) __nv_bfloat16 g_ahi[BATCH * D];
__device__ __align__(16) __nv_bfloat16 g_alo[BATCH * D];
__device__ __align__(16) __nv_bfloat16 g_hallhi[ROWS * D];
__device__ __align__(16) __nv_bfloat16 g_halllo[ROWS * D];
__device__ __align__(16) __nv_bfloat16 g_xhi[ROWS * D];
__device__ __align__(16) __nv_bfloat16 g_xlo[ROWS * D];
__device__ __align__(16) __nv_bfloat16 g_wiohi[2 * D * D];   // [W_in; W_out]
__device__ __align__(16) __nv_bfloat16 g_wiolo[2 * D * D];
__device__ __align__(16) __nv_bfloat16 g_whhhi[3 * D * D];
__device__ __align__(16) __nv_bfloat16 g_whhlo[3 * D * D];
__device__ __align__(16) __nv_bfloat16 g_wihhi[3 * D * D];
__device__ __align__(16) __nv_bfloat16 g_wihlo[3 * D * D];

// ---- smem / warp-mma / cp.async helpers (arch-generic PTX: sm_80+) ----
__device__ __forceinline__ unsigned smem_u32(const void* p) {
    unsigned a;
    asm("{ .reg .u64 t; cvta.to.shared.u64 t, %1; cvt.u32.u64 %0, t; }" : "=r"(a) : "l"(p));
    return a;
}
__device__ __forceinline__ void sts128(unsigned addr, uint4 v) {
    asm volatile("st.shared.v4.b32 [%0], {%1,%2,%3,%4};"
                 :: "r"(addr), "r"(v.x), "r"(v.y), "r"(v.z), "r"(v.w));
}
__device__ __forceinline__ void ldm4(unsigned& r0, unsigned& r1,
                                     unsigned& r2, unsigned& r3, unsigned addr) {
    asm volatile("ldmatrix.sync.aligned.m8n8.x4.shared.b16 {%0,%1,%2,%3}, [%4];"
                 : "=r"(r0), "=r"(r1), "=r"(r2), "=r"(r3) : "r"(addr));
}
__device__ __forceinline__ void mma16816(float* c, const unsigned* a, const unsigned* b) {
    asm volatile("mma.sync.aligned.m16n8k16.row.col.f32.bf16.bf16.f32 "
                 "{%0,%1,%2,%3}, {%4,%5,%6,%7}, {%8,%9}, {%0,%1,%2,%3};"
                 : "+f"(c[0]), "+f"(c[1]), "+f"(c[2]), "+f"(c[3])
                 : "r"(a[0]), "r"(a[1]), "r"(a[2]), "r"(a[3]),
                   "r"(b[0]), "r"(b[1]));
}
__device__ __forceinline__ void cp16(unsigned dst, const void* src) {
    asm volatile("cp.async.cg.shared.global [%0], [%1], 16;" :: "r"(dst), "l"(src));
}
#define CP_COMMIT()  asm volatile("cp.async.commit_group;" ::: "memory")
#define CP_WAIT(n)   asm volatile("cp.async.wait_group %0;" :: "n"(n) : "memory")

#define TILE 16384
#define PS_SMEM (1024 + 12 * TILE)    // 197,632 B -> 1 CTA/SM

// ---------------------------------------------------------------------------
// staging: one [128][128B] x2 chunk pair, XOR-16B swizzle
// ---------------------------------------------------------------------------
__device__ __forceinline__ void stage_tile(
    unsigned dst0, unsigned dst1, const __nv_bfloat16* gsrc,
    int row0, int maxrow, int tid)
{
    const int r = tid >> 1;            // 0..127
    const int h = tid & 1;
    const int row = row0 + r;
    if (row < maxrow) {
        const uint4* s = (const uint4*)(gsrc + (size_t)row * D);
        #pragma unroll
        for (int jj = 0; jj < 4; jj++) {
            int j = h * 4 + jj;
            unsigned o = r * 128 + ((j ^ (r & 7)) << 4);
            sts128(dst0 + o, s[j]);
            sts128(dst1 + o, s[8 + j]);
        }
    } else {
        uint4 z = make_uint4(0u, 0u, 0u, 0u);
        #pragma unroll
        for (int jj = 0; jj < 4; jj++) {
            int j = h * 4 + jj;
            unsigned o = r * 128 + ((j ^ (r & 7)) << 4);
            sts128(dst0 + o, z);
            sts128(dst1 + o, z);
        }
    }
}

__device__ __forceinline__ void stage_tile_async(
    unsigned dst0, unsigned dst1, const __nv_bfloat16* gsrc,
    int row0, int maxrow, int tid)
{
    const int r = tid >> 1;
    const int h = tid & 1;
    const int row = row0 + r;
    if (row < maxrow) {
        const char* base = (const char*)(gsrc + (size_t)row * D);
        #pragma unroll
        for (int jj = 0; jj < 4; jj++) {
            int j = h * 4 + jj;
            unsigned o = r * 128 + ((j ^ (r & 7)) << 4);
            cp16(dst0 + o, base + j * 16);
            cp16(dst1 + o, base + 128 + j * 16);
        }
    } else {
        uint4 z = make_uint4(0u, 0u, 0u, 0u);
        #pragma unroll
        for (int jj = 0; jj < 4; jj++) {
            int j = h * 4 + jj;
            unsigned o = r * 128 + ((j ^ (r & 7)) << 4);
            sts128(dst0 + o, z);
            sts128(dst1 + o, z);
        }
    }
}

__device__ __forceinline__ unsigned sw_addr(unsigned tile, int row, int kb) {
    return tile + row * 128 + (((unsigned)(kb ^ (row & 7))) << 4);
}

// fused single-pass 3-term: acc += Ahi·Bhi + Alo·Bhi + Ahi·Blo
__device__ __forceinline__ void compute_3term(
    float (&acc)[2][8][4],
    const unsigned* tAhi, const unsigned* tAlo,
    const unsigned* tBhi, const unsigned* tBlo,
    int arow, int asub, int brow0, int bsub)
{
    #pragma unroll
    for (int c = 0; c < 2; c++) {
        #pragma unroll
        for (int kq = 0; kq < 4; kq++) {
            const int kbA = kq * 2 + asub;
            const int kbB = kq * 2 + bsub;
            unsigned bfh[8][2];
            #pragma unroll
            for (int p = 0; p < 4; p++)
                ldm4(bfh[2*p][0], bfh[2*p][1], bfh[2*p+1][0], bfh[2*p+1][1],
                     sw_addr(tBhi[c], brow0 + p * 16, kbB));
            unsigned afh[2][4];
            #pragma unroll
            for (int mf = 0; mf < 2; mf++)
                ldm4(afh[mf][0], afh[mf][1], afh[mf][2], afh[mf][3],
                     sw_addr(tAhi[c], arow + mf * 16, kbA));
            #pragma unroll
            for (int mf = 0; mf < 2; mf++)
                #pragma unroll
                for (int nf = 0; nf < 8; nf++)
                    mma16816(acc[mf][nf], afh[mf], bfh[nf]);
            unsigned afl[2][4];
            #pragma unroll
            for (int mf = 0; mf < 2; mf++)
                ldm4(afl[mf][0], afl[mf][1], afl[mf][2], afl[mf][3],
                     sw_addr(tAlo[c], arow + mf * 16, kbA));
            #pragma unroll
            for (int mf = 0; mf < 2; mf++)
                #pragma unroll
                for (int nf = 0; nf < 8; nf++)
                    mma16816(acc[mf][nf], afl[mf], bfh[nf]);
            unsigned bfl[8][2];
            #pragma unroll
            for (int p = 0; p < 4; p++)
                ldm4(bfl[2*p][0], bfl[2*p][1], bfl[2*p+1][0], bfl[2*p+1][1],
                     sw_addr(tBlo[c], brow0 + p * 16, kbB));
            #pragma unroll
            for (int mf = 0; mf < 2; mf++)
                #pragma unroll
                for (int nf = 0; nf < 8; nf++)
                    mma16816(acc[mf][nf], afh[mf], bfl[nf]);
        }
    }
}

// ---------------------------------------------------------------------------
// K0: ALL fp32 -> bf16 hi/lo splits in one launch
// ---------------------------------------------------------------------------
#define E4   (NITEMS * D / 4)
#define W4   (D * D / 4)
#define W34  (3 * D * D / 4)
#define CONV_GROUPS (E4 + 2 * W4 + 2 * W34)

__global__ __launch_bounds__(256) void conv_all_kernel(
    const float* __restrict__ emb,  const float* __restrict__ W_in,
    const float* __restrict__ W_out, const float* __restrict__ w_hh,
    const float* __restrict__ w_ih)
{
    size_t i = (size_t)blockIdx.x * 256 + threadIdx.x;
    const float* src; __nv_bfloat16 *dhi, *dlo; size_t off;
    if (i < E4)                    { src = emb;   off = i;                 dhi = g_ehi;            dlo = g_elo; }
    else if (i < E4 + W4)          { src = W_in;  off = i - E4;            dhi = g_wiohi;          dlo = g_wiolo; }
    else if (i < E4 + 2 * W4)      { src = W_out; off = i - E4 - W4;       dhi = g_wiohi + D * D;  dlo = g_wiolo + D * D; }
    else if (i < E4 + 2 * W4 + W34){ src = w_hh;  off = i - E4 - 2 * W4;   dhi = g_whhhi;          dlo = g_whhlo; }
    else                           { src = w_ih;  off = i - E4 - 2*W4 - W34; dhi = g_wihhi;        dlo = g_wihlo; }

    float4 v = ((const float4*)src)[off];
    __nv_bfloat162 h01 = __floats2bfloat162_rn(v.x, v.y);
    __nv_bfloat162 h23 = __floats2bfloat162_rn(v.z, v.w);
    __nv_bfloat162 l01 = __floats2bfloat162_rn(v.x - __low2float(h01), v.y - __high2float(h01));
    __nv_bfloat162 l23 = __floats2bfloat162_rn(v.z - __low2float(h23), v.w - __high2float(h23));
    ((__nv_bfloat162*)dhi)[2 * off]     = h01;
    ((__nv_bfloat162*)dhi)[2 * off + 1] = h23;
    ((__nv_bfloat162*)dlo)[2 * off]     = l01;
    ((__nv_bfloat162*)dlo)[2 * off + 1] = l23;
}

// ---------------------------------------------------------------------------
// K1: per-sample graph build + bf16 hi/lo gather
// ---------------------------------------------------------------------------
__global__ __launch_bounds__(256) void build_kernel(const int* __restrict__ x)
{
    __shared__ int s_seq[L], s_rep[L], s_nodes[L], s_cinv[L];
    __shared__ int s_nn, s_cnt;
    const int b = blockIdx.x, tid = threadIdx.x;

    if (tid == 0) { s_nn = 0; s_cnt = 0; }
    if (tid < L) { s_seq[tid] = x[b * L + tid]; s_cinv[tid] = 0; }
    __syncthreads();

    int mypos = 0;
    if (tid < L) {
        int s = s_seq[tid];
        int rep = (s != 0);
        for (int j = 0; j < tid; j++) {
            int sj = s_seq[j];
            if (sj != 0) { mypos++; if (sj == s) rep = 0; }
        }
        s_rep[tid] = rep;
    }
    __syncthreads();

    if (tid < L) {
        int s = s_seq[tid];
        if (s != 0) {
            int rank = 0;
            for (int j = 0; j < L; j++)
                if (s_rep[j] && s_seq[j] < s) rank++;
            if (s_rep[tid]) { s_nodes[rank] = s; atomicAdd(&s_nn, 1); }
            s_cinv[mypos] = rank;
            atomicAdd(&s_cnt, 1);
        }
    }
    __syncthreads();

    const int nn = s_nn, cnt = s_cnt;

    for (int idx = tid; idx < L * 16; idx += 256) {
        int r = idx >> 4, q = idx & 15;
        uint4 vh = make_uint4(0u, 0u, 0u, 0u), vl = vh;
        if (r < nn) {
            vh = ((const uint4*)(g_ehi + (size_t)s_nodes[r] * D))[q];
            vl = ((const uint4*)(g_elo + (size_t)s_nodes[r] * D))[q];
        }
        ((uint4*)(g_hallhi + ((size_t)b * L + r) * D))[q] = vh;
        ((uint4*)(g_halllo + ((size_t)b * L + r) * D))[q] = vl;
    }
    if (tid < L) g_cinv[b * L + tid] = s_cinv[tid];
    if (tid == 0) {
        g_nn[b] = nn;
        g_cntv[b] = cnt;
        g_li[b] = (cnt > 0) ? s_cinv[cnt - 1] : 0;
    }
}

// ---------------------------------------------------------------------------
// Persistent internal GEMM: weights resident, A streamed (double-buffered
// cp.async for NPAIR=1; sequential pair staging for NPAIR=2).
// C(m-tile, n0) = sum_pairs 3-term(A_pair, B_pair)
// ---------------------------------------------------------------------------
template<int NPAIR>
__global__ void __launch_bounds__(256) internal_persist_kernel(
    const __nv_bfloat16* __restrict__ A0hi, const __nv_bfloat16* __restrict__ A0lo,
    const __nv_bfloat16* __restrict__ B0hi, const __nv_bfloat16* __restrict__ B0lo,
    const __nv_bfloat16* __restrict__ A1hi, const __nv_bfloat16* __restrict__ A1lo,
    const __nv_bfloat16* __restrict__ B1hi, const __nv_bfloat16* __restrict__ B1lo,
    int coff, int ldc, int mtiles)
{
    extern __shared__ char dsm[];
    const int tid = threadIdx.x, wid = tid >> 5, lane = tid & 31;
    const int n0 = blockIdx.y * 128;
    unsigned tb = (smem_u32(dsm) + 1023) & ~1023u;

    unsigned b0hi[2] = { tb,            tb + TILE };
    unsigned b0lo[2] = { tb + 2*TILE,   tb + 3*TILE };
    unsigned b1hi[2] = { tb + 4*TILE,   tb + 5*TILE };
    unsigned b1lo[2] = { tb + 6*TILE,   tb + 7*TILE };

    // resident weights
    stage_tile(b0hi[0], b0hi[1], B0hi, n0, 0x7fffffff, tid);
    stage_tile(b0lo[0], b0lo[1], B0lo, n0, 0x7fffffff, tid);
    if (NPAIR == 2) {
        stage_tile(b1hi[0], b1hi[1], B1hi, n0, 0x7fffffff, tid);
        stage_tile(b1lo[0], b1lo[1], B1lo, n0, 0x7fffffff, tid);
    }

    const int m0w = (wid & 3) * 32;
    const int n0w = (wid >> 2) * 64;
    const int arow = m0w + (lane & 15);
    const int asub = lane >> 4;
    const int brow0 = n0w + ((lane >> 4) << 3) + (lane & 7);
    const int bsub  = (lane >> 3) & 1;
    const int rbase = lane >> 2;
    const int cbase = (lane & 3) * 2;
    float* C = g_blob + coff;

    if (NPAIR == 1) {
        // A double-buffered: buf b at tb + (4 + 4b)*TILE
        unsigned ab[2][4];
        #pragma unroll
        for (int b = 0; b < 2; b++)
            #pragma unroll
            for (int t = 0; t < 4; t++)
                ab[b][t] = tb + (4 + 4 * b + t) * TILE;   // hi0,hi1,lo0,lo1

        int buf = 0;
        int mt = blockIdx.x;
        if (mt < mtiles) {
            stage_tile_async(ab[0][0], ab[0][1], A0hi, mt * 128, 0x7fffffff, tid);
            stage_tile_async(ab[0][2], ab[0][3], A0lo, mt * 128, 0x7fffffff, tid);
            CP_COMMIT();
        }
        for (; mt < mtiles; mt += gridDim.x) {
            int mtn = mt + gridDim.x;
            bool pf = mtn < mtiles;
            if (pf) {
                stage_tile_async(ab[buf^1][0], ab[buf^1][1], A0hi, mtn * 128, 0x7fffffff, tid);
                stage_tile_async(ab[buf^1][2], ab[buf^1][3], A0lo, mtn * 128, 0x7fffffff, tid);
                CP_COMMIT();
            }
            if (pf) { CP_WAIT(1); } else { CP_WAIT(0); }
            __syncthreads();

            float acc[2][8][4];
            #pragma unroll
            for (int i = 0; i < 2; i++)
                #pragma unroll
                for (int j = 0; j < 8; j++)
                    #pragma unroll
                    for (int q = 0; q < 4; q++) acc[i][j][q] = 0.f;

            unsigned ahi[2] = { ab[buf][0], ab[buf][1] };
            unsigned alo[2] = { ab[buf][2], ab[buf][3] };
            compute_3term(acc, ahi, alo, b0hi, b0lo, arow, asub, brow0, bsub);

            const int m0 = mt * 128;
            #pragma unroll
            for (int mf = 0; mf < 2; mf++) {
                const int mA = m0 + m0w + mf * 16 + rbase;
                #pragma unroll
                for (int nf = 0; nf < 8; nf++) {
                    const int n = n0 + n0w + nf * 8 + cbase;
                    float2 vA = { acc[mf][nf][0], acc[mf][nf][1] };
                    float2 vB = { acc[mf][nf][2], acc[mf][nf][3] };
                    *(float2*)&C[(size_t)mA * ldc + n] = vA;
                    *(float2*)&C[(size_t)(mA + 8) * ldc + n] = vB;
                }
            }
            __syncthreads();
            buf ^= 1;
        }
    } else {
        // NPAIR == 2: single A buffer at tb + 8*TILE, sequential pairs
        unsigned as_[4] = { tb + 8*TILE, tb + 9*TILE, tb + 10*TILE, tb + 11*TILE };
        unsigned ahi[2] = { as_[0], as_[1] };
        unsigned alo[2] = { as_[2], as_[3] };
        __syncthreads();   // resident B visible

        for (int mt = blockIdx.x; mt < mtiles; mt += gridDim.x) {
            stage_tile_async(as_[0], as_[1], A0hi, mt * 128, 0x7fffffff, tid);
            stage_tile_async(as_[2], as_[3], A0lo, mt * 128, 0x7fffffff, tid);
            CP_COMMIT(); CP_WAIT(0);
            __syncthreads();

            float acc[2][8][4];
            #pragma unroll
            for (int i = 0; i < 2; i++)
                #pragma unroll
                for (int j = 0; j < 8; j++)
                    #pragma unroll
                    for (int q = 0; q < 4; q++) acc[i][j][q] = 0.f;

            compute_3term(acc, ahi, alo, b0hi, b0lo, arow, asub, brow0, bsub);
            __syncthreads();

            stage_tile_async(as_[0], as_[1], A1hi, mt * 128, 0x7fffffff, tid);
            stage_tile_async(as_[2], as_[3], A1lo, mt * 128, 0x7fffffff, tid);
            CP_COMMIT(); CP_WAIT(0);
            __syncthreads();

            compute_3term(acc, ahi, alo, b1hi, b1lo, arow, asub, brow0, bsub);

            const int m0 = mt * 128;
            #pragma unroll
            for (int mf = 0; mf < 2; mf++) {
                const int mA = m0 + m0w + mf * 16 + rbase;
                #pragma unroll
                for (int nf = 0; nf < 8; nf++) {
                    const int n = n0 + n0w + nf * 8 + cbase;
                    float2 vA = { acc[mf][nf][0], acc[mf][nf][1] };
                    float2 vB = { acc[mf][nf][2], acc[mf][nf][3] };
                    *(float2*)&C[(size_t)mA * ldc + n] = vA;
                    *(float2*)&C[(size_t)(mA + 8) * ldc + n] = vB;
                }
            }
            __syncthreads();
        }
    }
}

// ---------------------------------------------------------------------------
// Persistent score GEMM: A (h_read) resident, emb tiles streamed with
// double-buffered cp.async; epilogue with cnt>=2 masking.
// ---------------------------------------------------------------------------
__global__ void __launch_bounds__(256) score_persist_kernel(
    const __nv_bfloat16* __restrict__ Ahi, const __nv_bfloat16* __restrict__ Alo,
    const __nv_bfloat16* __restrict__ Bhi, const __nv_bfloat16* __restrict__ Blo,
    float* __restrict__ out)
{
    extern __shared__ char dsm[];
    const int tid = threadIdx.x, wid = tid >> 5, lane = tid & 31;
    const int m0 = blockIdx.x * 128;
    unsigned tb = (smem_u32(dsm) + 1023) & ~1023u;

    unsigned tahi[2] = { tb,          tb + TILE };
    unsigned talo[2] = { tb + 2*TILE, tb + 3*TILE };
    unsigned bb[2][4];
    #pragma unroll
    for (int b = 0; b < 2; b++)
        #pragma unroll
        for (int t = 0; t < 4; t++)
            bb[b][t] = tb + (4 + 4 * b + t) * TILE;     // hi0,hi1,lo0,lo1

    stage_tile(tahi[0], tahi[1], Ahi, m0, BATCH, tid);
    stage_tile(talo[0], talo[1], Alo, m0, BATCH, tid);

    const int m0w = (wid & 3) * 32;
    const int n0w = (wid >> 2) * 64;
    const int arow = m0w + (lane & 15);
    const int asub = lane >> 4;
    const int brow0 = n0w + ((lane >> 4) << 3) + (lane & 7);
    const int bsub  = (lane >> 3) & 1;
    const int rbase = lane >> 2;
    const int cbase = (lane & 3) * 2;

    // per-CTA-invariant mask bits (hoisted out of the n loop)
    const int mA0 = m0 + m0w + rbase;
    const bool ok[4] = { g_cntv[mA0] >= 2,      g_cntv[mA0 + 8] >= 2,
                         g_cntv[mA0 + 16] >= 2, g_cntv[mA0 + 24] >= 2 };

    const int NT = (NITEMS + 127) / 128;     // 782
    int buf = 0;
    int nt = blockIdx.y;
    if (nt < NT) {
        stage_tile_async(bb[0][0], bb[0][1], Bhi, nt * 128, NITEMS, tid);
        stage_tile_async(bb[0][2], bb[0][3], Blo, nt * 128, NITEMS, tid);
        CP_COMMIT();
    }
    for (; nt < NT; nt += gridDim.y) {
        int ntn = nt + gridDim.y;
        bool pf = ntn < NT;
        if (pf) {
            stage_tile_async(bb[buf^1][0], bb[buf^1][1], Bhi, ntn * 128, NITEMS, tid);
            stage_tile_async(bb[buf^1][2], bb[buf^1][3], Blo, ntn * 128, NITEMS, tid);
            CP_COMMIT();
        }
        if (pf) { CP_WAIT(1); } else { CP_WAIT(0); }
        __syncthreads();

        float acc[2][8][4];
        #pragma unroll
        for (int i = 0; i < 2; i++)
            #pragma unroll
            for (int j = 0; j < 8; j++)
                #pragma unroll
                for (int q = 0; q < 4; q++) acc[i][j][q] = 0.f;

        unsigned bhi[2] = { bb[buf][0], bb[buf][1] };
        unsigned blo[2] = { bb[buf][2], bb[buf][3] };
        compute_3term(acc, tahi, talo, bhi, blo, arow, asub, brow0, bsub);

        const int n0 = nt * 128;
        #pragma unroll
        for (int mf = 0; mf < 2; mf++) {
            const int mA = mA0 + mf * 16;
            const bool okA = ok[mf * 2], okB = ok[mf * 2 + 1];
            #pragma unroll
            for (int nf = 0; nf < 8; nf++) {
                const int n = n0 + n0w + nf * 8 + cbase;
                if (n < NITEMS) {
                    float2 vA, vB;
                    if (okA) { vA.x = acc[mf][nf][0]; vA.y = acc[mf][nf][1]; }
                    else     { vA.x = (n == 0) ? 0.0f : NEGV; vA.y = NEGV; }
                    if (okB) { vB.x = acc[mf][nf][2]; vB.y = acc[mf][nf][3]; }
                    else     { vB.x = (n == 0) ? 0.0f : NEGV; vB.y = NEGV; }
                    *(float2*)&out[(size_t)mA * NITEMS + n] = vA;
                    *(float2*)&out[(size_t)(mA + 8) * NITEMS + n] = vB;
                }
            }
        }
        __syncthreads();
        buf ^= 1;
    }
}

// ---------------------------------------------------------------------------
// K3: per-sample edge aggregation.  X = Hin + agg(Hout[src])/deg -> bf16 hi/lo
// ---------------------------------------------------------------------------
__global__ __launch_bounds__(256) void agg_kernel()
{
    extern __shared__ float agg[];            // L*D floats
    __shared__ int   cinv[L];
    __shared__ float rdeg[L];
    const int b = blockIdx.x, tid = threadIdx.x;

    if (tid < L) { cinv[tid] = g_cinv[b * L + tid]; rdeg[tid] = 0.f; }
    for (int i = tid; i < L * D / 4; i += 256)
        ((float4*)agg)[i] = make_float4(0.f, 0.f, 0.f, 0.f);
    __syncthreads();

    const int cnt = g_cntv[b];
    if (tid < cnt - 1) atomicAdd(&rdeg[cinv[tid + 1]], 1.0f);
    __syncthreads();
    if (tid < L) rdeg[tid] = 1.0f / fmaxf(rdeg[tid], 1.0f);

    const float* Hio = g_blob + OFF_HIO + (size_t)b * L * 2 * D;
    const int nedge = (cnt >= 1) ? cnt - 1 : 0;
    for (int idx = tid; idx < nedge * D; idx += 256) {
        int t = idx >> 7, k = idx & 127;
        atomicAdd(&agg[cinv[t + 1] * D + k], Hio[(size_t)cinv[t] * 2 * D + D + k]);
    }
    __syncthreads();

    for (int idx = tid; idx < L * D; idx += 256) {
        int r = idx >> 7;
        float v = Hio[(size_t)r * 2 * D + (idx & 127)] + agg[idx] * rdeg[r];
        __nv_bfloat16 h = __float2bfloat16(v);
        g_xhi[(size_t)b * L * D + idx] = h;
        g_xlo[(size_t)b * L * D + idx] = __float2bfloat16(v - __bfloat162float(h));
    }
}

// ---------------------------------------------------------------------------
// K4: fused GRU + attention readout (one CTA per sample, H in SMEM)
// ---------------------------------------------------------------------------
__global__ __launch_bounds__(256) void gru_attn_kernel(
    const float* __restrict__ b_ih, const float* __restrict__ b_hh,
    const float* __restrict__ W_read, const float* __restrict__ b_read)
{
    extern __shared__ float H[];              // L*D floats
    __shared__ float hlast[D], loc[D], sc[L];
    const int b = blockIdx.x, tid = threadIdx.x;
    const int nn = g_nn[b], li = g_li[b];

    for (int idx = tid; idx < L * D; idx += 256) {
        int row = idx >> 7, j = idx & 127;
        size_t base = (size_t)b * L + row;
        float sr  = g_blob[OFF_SRZ + base * 256 + j];
        float sz  = g_blob[OFF_SRZ + base * 256 + 128 + j];
        float gin = g_blob[OFF_GIN + base * 128 + j];
        float ghn = g_blob[OFF_GHN + base * 128 + j];
        float h0  = __bfloat162float(g_hallhi[base * 128 + j])
                  + __bfloat162float(g_halllo[base * 128 + j]);
        float r = 1.0f / (1.0f + expf(-(sr + b_ih[j] + b_hh[j])));
        float z = 1.0f / (1.0f + expf(-(sz + b_ih[D + j] + b_hh[D + j])));
        float n = tanhf(gin + b_ih[2 * D + j] + r * (ghn + b_hh[2 * D + j]));
        H[idx] = (1.0f - z) * n + z * h0;
    }
    __syncthreads();

    if (tid < D) hlast[tid] = H[li * D + tid];
    __syncthreads();

    const int w = tid >> 5, lane = tid & 31;
    for (int r = w; r < nn; r += 8) {
        const float* hr = H + r * D;
        float acc = 0.f;
        #pragma unroll
        for (int k = lane; k < D; k += 32) acc = fmaf(hr[k], hlast[k], acc);
        #pragma unroll
        for (int off = 16; off; off >>= 1)
            acc += __shfl_down_sync(0xffffffffu, acc, off);
        if (lane == 0) sc[r] = acc;
    }
    __syncthreads();

    if (tid == 0) {
        float m = -1e30f;
        for (int i = 0; i < nn; i++) m = fmaxf(m, sc[i]);
        float s = 0.f;
        for (int i = 0; i < nn; i++) { float e = expf(sc[i] - m); sc[i] = e; s += e; }
        float inv = (s > 0.f) ? 1.0f / s : 0.f;
        for (int i = 0; i < nn; i++) sc[i] *= inv;
    }
    __syncthreads();

    if (tid < D) {
        float acc = 0.f;
        for (int r = 0; r < nn; r++) acc = fmaf(sc[r], H[r * D + tid], acc);
        loc[tid] = acc;
    }
    __syncthreads();

    #pragma unroll
    for (int t = 0; t < 16; t++) {
        int j = w * 16 + t;
        const float* wr = W_read + (size_t)j * (3 * D);
        float acc = 0.f;
        #pragma unroll
        for (int k = lane; k < D; k += 32)
            acc += wr[k] * hlast[k] + wr[D + k] * loc[k];
        #pragma unroll
        for (int off = 16; off; off >>= 1)
            acc += __shfl_down_sync(0xffffffffu, acc, off);
        if (lane == 0) {
            float hv = tanhf(acc + b_read[j]);
            __nv_bfloat16 h = __float2bfloat16(hv);
            g_ahi[b * D + j] = h;
            g_alo[b * D + j] = __float2bfloat16(hv - __bfloat162float(h));
        }
    }
}

// ---------------------------------------------------------------------------
extern "C" void kernel_launch(void* const* d_in, const int* in_sizes, int n_in,
                              void* d_out, int out_size)
{
    const int*   x      = (const int*)  d_in[0];
    // d_in[1] = attn_mask (unused by reference)
    const float* emb    = (const float*)d_in[2];
    const float* W_in   = (const float*)d_in[3];
    const float* W_out  = (const float*)d_in[4];
    const float* w_ih   = (const float*)d_in[5];
    const float* w_hh   = (const float*)d_in[6];
    const float* b_ih   = (const float*)d_in[7];
    const float* b_hh   = (const float*)d_in[8];
    const float* W_read = (const float*)d_in[9];
    const float* b_read = (const float*)d_in[10];
    float* out = (float*)d_out;

    cudaFuncSetAttribute(agg_kernel,
        cudaFuncAttributeMaxDynamicSharedMemorySize, L * D * (int)sizeof(float));
    cudaFuncSetAttribute(gru_attn_kernel,
        cudaFuncAttributeMaxDynamicSharedMemorySize, L * D * (int)sizeof(float));
    cudaFuncSetAttribute(internal_persist_kernel<1>,
        cudaFuncAttributeMaxDynamicSharedMemorySize, PS_SMEM);
    cudaFuncSetAttribute(internal_persist_kernel<2>,
        cudaFuncAttributeMaxDynamicSharedMemorySize, PS_SMEM);
    cudaFuncSetAttribute(score_persist_kernel,
        cudaFuncAttributeMaxDynamicSharedMemorySize, PS_SMEM);

    __nv_bfloat16 *ehi, *elo, *ahi, *alo, *hallhi, *halllo, *xhi, *xlo;
    __nv_bfloat16 *wiohi, *wiolo, *whhhi, *whhlo, *wihhi, *wihlo;
    cudaGetSymbolAddress((void**)&ehi,    g_ehi);
    cudaGetSymbolAddress((void**)&elo,    g_elo);
    cudaGetSymbolAddress((void**)&ahi,    g_ahi);
    cudaGetSymbolAddress((void**)&alo,    g_alo);
    cudaGetSymbolAddress((void**)&hallhi, g_hallhi);
    cudaGetSymbolAddress((void**)&halllo, g_halllo);
    cudaGetSymbolAddress((void**)&xhi,    g_xhi);
    cudaGetSymbolAddress((void**)&xlo,    g_xlo);
    cudaGetSymbolAddress((void**)&wiohi,  g_wiohi);
    cudaGetSymbolAddress((void**)&wiolo,  g_wiolo);
    cudaGetSymbolAddress((void**)&whhhi,  g_whhhi);
    cudaGetSymbolAddress((void**)&whhlo,  g_whhlo);
    cudaGetSymbolAddress((void**)&wihhi,  g_wihhi);
    cudaGetSymbolAddress((void**)&wihlo,  g_wihlo);

    // K0: all fp32 -> bf16 hi/lo conversions in one launch
    conv_all_kernel<<<CONV_GROUPS / 256, 256>>>(emb, W_in, W_out, w_hh, w_ih);

    // K1: graph build + bf16 hi/lo gather
    build_kernel<<<BATCH, 256>>>(x);

    // G1: Hin | Hout = Hall @ [W_in; W_out]^T  (persistent, weights resident)
    internal_persist_kernel<1><<<dim3(74, 2), 256, PS_SMEM>>>(
        hallhi, halllo, wiohi, wiolo,
        nullptr, nullptr, nullptr, nullptr, OFF_HIO, 2 * D, ROWS / 128);

    // G_ghn: gh_n = Hall @ w_hh_n^T
    internal_persist_kernel<1><<<dim3(148, 1), 256, PS_SMEM>>>(
        hallhi, halllo, whhhi + 2 * D * D, whhlo + 2 * D * D,
        nullptr, nullptr, nullptr, nullptr, OFF_GHN, D, ROWS / 128);

    // K3: X = Hin + agg/deg -> bf16 hi/lo
    agg_kernel<<<BATCH, 256, L * D * sizeof(float)>>>();

    // G_rz: s_rz = X @ w_ih_rz^T + Hall @ w_hh_rz^T   (dual-pair, B resident)
    internal_persist_kernel<2><<<dim3(74, 2), 256, PS_SMEM>>>(
        xhi, xlo, wihhi, wihlo,
        hallhi, halllo, whhhi, whhlo, OFF_SRZ, 2 * D, ROWS / 128);

    // G_gin: gi_n = X @ w_ih_n^T
    internal_persist_kernel<1><<<dim3(148, 1), 256, PS_SMEM>>>(
        xhi, xlo, wihhi + 2 * D * D, wihlo + 2 * D * D,
        nullptr, nullptr, nullptr, nullptr, OFF_GIN, D, ROWS / 128);

    // K4: fused GRU + attention -> h_read hi/lo
    gru_attn_kernel<<<BATCH, 256, L * D * sizeof(float)>>>(b_ih, b_hh, W_read, b_read);

    // K6: persistent tensor-core score GEMM (A resident, emb streamed)
    score_persist_kernel<<<dim3(BATCH / 128, 37), 256, PS_SMEM>>>(
        ahi, alo, ehi, elo, out);
}

// round 16
// speedup vs baseline: 4.2834x; 1.0011x over previous
#include <cuda_runtime.h>
#include <cuda_bf16.h>
#include <math.h>

#define BATCH  512
#define L      100
#define D      128
#define NITEMS 100000
#define NEGV   -1000000000.0f
#define ROWS   (BATCH * L)          // 51200 padded node rows

// ---- scratch blob offsets (floats) ----
#define OFF_HIO   0                         // [ROWS][256]  Hin | Hout
#define OFF_SRZ   (ROWS * 2 * D)            // [ROWS][256]  gi_r+gh_r | gi_z+gh_z
#define OFF_GIN   (OFF_SRZ + ROWS * 2 * D)  // [ROWS][128]
#define OFF_GHN   (OFF_GIN + ROWS * D)      // [ROWS][128]
#define BLOB_SZ   (OFF_GHN + ROWS * D)

__device__ __align__(128) float g_blob[BLOB_SZ];
__device__ int g_cinv[BATCH * L];
__device__ int g_nn[BATCH];
__device__ int g_cntv[BATCH];
__device__ int g_li[BATCH];

// bf16 hi/lo split operands for tensor-core GEMMs
__device__ __align__(16) __nv_bfloat16 g_ehi[NITEMS * D];
__device__ __align__(16) __nv_bfloat16 g_elo[NITEMS * D];
__device__ __align__(16) __nv_bfloat16 g_ahi[BATCH * D];
__device__ __align__(16) __nv_bfloat16 g_alo[BATCH * D];
__device__ __align__(16) __nv_bfloat16 g_hallhi[ROWS * D];
__device__ __align__(16) __nv_bfloat16 g_halllo[ROWS * D];
__device__ __align__(16) __nv_bfloat16 g_xhi[ROWS * D];
__device__ __align__(16) __nv_bfloat16 g_xlo[ROWS * D];
__device__ __align__(16) __nv_bfloat16 g_wiohi[2 * D * D];   // [W_in; W_out]
__device__ __align__(16) __nv_bfloat16 g_wiolo[2 * D * D];
__device__ __align__(16) __nv_bfloat16 g_whhhi[3 * D * D];
__device__ __align__(16) __nv_bfloat16 g_whhlo[3 * D * D];
__device__ __align__(16) __nv_bfloat16 g_wihhi[3 * D * D];
__device__ __align__(16) __nv_bfloat16 g_wihlo[3 * D * D];

// ---- smem / warp-mma / cp.async helpers (arch-generic PTX: sm_80+) ----
__device__ __forceinline__ unsigned smem_u32(const void* p) {
    unsigned a;
    asm("{ .reg .u64 t; cvta.to.shared.u64 t, %1; cvt.u32.u64 %0, t; }" : "=r"(a) : "l"(p));
    return a;
}
__device__ __forceinline__ void sts128(unsigned addr, uint4 v) {
    asm volatile("st.shared.v4.b32 [%0], {%1,%2,%3,%4};"
                 :: "r"(addr), "r"(v.x), "r"(v.y), "r"(v.z), "r"(v.w));
}
__device__ __forceinline__ void ldm4(unsigned& r0, unsigned& r1,
                                     unsigned& r2, unsigned& r3, unsigned addr) {
    asm volatile("ldmatrix.sync.aligned.m8n8.x4.shared.b16 {%0,%1,%2,%3}, [%4];"
                 : "=r"(r0), "=r"(r1), "=r"(r2), "=r"(r3) : "r"(addr));
}
__device__ __forceinline__ void mma16816(float* c, const unsigned* a, const unsigned* b) {
    asm volatile("mma.sync.aligned.m16n8k16.row.col.f32.bf16.bf16.f32 "
                 "{%0,%1,%2,%3}, {%4,%5,%6,%7}, {%8,%9}, {%0,%1,%2,%3};"
                 : "+f"(c[0]), "+f"(c[1]), "+f"(c[2]), "+f"(c[3])
                 : "r"(a[0]), "r"(a[1]), "r"(a[2]), "r"(a[3]),
                   "r"(b[0]), "r"(b[1]));
}
__device__ __forceinline__ void cp16(unsigned dst, const void* src) {
    asm volatile("cp.async.cg.shared.global [%0], [%1], 16;" :: "r"(dst), "l"(src));
}
#define CP_COMMIT()  asm volatile("cp.async.commit_group;" ::: "memory")
#define CP_WAIT(n)   asm volatile("cp.async.wait_group %0;" :: "n"(n) : "memory")

#define TILE 16384
#define PS_SMEM (1024 + 12 * TILE)    // 197,632 B -> 1 CTA/SM

// ---------------------------------------------------------------------------
// staging: one [128][128B] x2 chunk pair, XOR-16B swizzle
// ---------------------------------------------------------------------------
__device__ __forceinline__ void stage_tile(
    unsigned dst0, unsigned dst1, const __nv_bfloat16* gsrc,
    int row0, int maxrow, int tid)
{
    const int r = tid >> 1;            // 0..127
    const int h = tid & 1;
    const int row = row0 + r;
    if (row < maxrow) {
        const uint4* s = (const uint4*)(gsrc + (size_t)row * D);
        #pragma unroll
        for (int jj = 0; jj < 4; jj++) {
            int j = h * 4 + jj;
            unsigned o = r * 128 + ((j ^ (r & 7)) << 4);
            sts128(dst0 + o, s[j]);
            sts128(dst1 + o, s[8 + j]);
        }
    } else {
        uint4 z = make_uint4(0u, 0u, 0u, 0u);
        #pragma unroll
        for (int jj = 0; jj < 4; jj++) {
            int j = h * 4 + jj;
            unsigned o = r * 128 + ((j ^ (r & 7)) << 4);
            sts128(dst0 + o, z);
            sts128(dst1 + o, z);
        }
    }
}

__device__ __forceinline__ void stage_tile_async(
    unsigned dst0, unsigned dst1, const __nv_bfloat16* gsrc,
    int row0, int maxrow, int tid)
{
    const int r = tid >> 1;
    const int h = tid & 1;
    const int row = row0 + r;
    if (row < maxrow) {
        const char* base = (const char*)(gsrc + (size_t)row * D);
        #pragma unroll
        for (int jj = 0; jj < 4; jj++) {
            int j = h * 4 + jj;
            unsigned o = r * 128 + ((j ^ (r & 7)) << 4);
            cp16(dst0 + o, base + j * 16);
            cp16(dst1 + o, base + 128 + j * 16);
        }
    } else {
        uint4 z = make_uint4(0u, 0u, 0u, 0u);
        #pragma unroll
        for (int jj = 0; jj < 4; jj++) {
            int j = h * 4 + jj;
            unsigned o = r * 128 + ((j ^ (r & 7)) << 4);
            sts128(dst0 + o, z);
            sts128(dst1 + o, z);
        }
    }
}

__device__ __forceinline__ unsigned sw_addr(unsigned tile, int row, int kb) {
    return tile + row * 128 + (((unsigned)(kb ^ (row & 7))) << 4);
}

// fused single-pass 3-term: acc += Ahi·Bhi + Alo·Bhi + Ahi·Blo
__device__ __forceinline__ void compute_3term(
    float (&acc)[2][8][4],
    const unsigned* tAhi, const unsigned* tAlo,
    const unsigned* tBhi, const unsigned* tBlo,
    int arow, int asub, int brow0, int bsub)
{
    #pragma unroll
    for (int c = 0; c < 2; c++) {
        #pragma unroll
        for (int kq = 0; kq < 4; kq++) {
            const int kbA = kq * 2 + asub;
            const int kbB = kq * 2 + bsub;
            unsigned bfh[8][2];
            #pragma unroll
            for (int p = 0; p < 4; p++)
                ldm4(bfh[2*p][0], bfh[2*p][1], bfh[2*p+1][0], bfh[2*p+1][1],
                     sw_addr(tBhi[c], brow0 + p * 16, kbB));
            unsigned afh[2][4];
            #pragma unroll
            for (int mf = 0; mf < 2; mf++)
                ldm4(afh[mf][0], afh[mf][1], afh[mf][2], afh[mf][3],
                     sw_addr(tAhi[c], arow + mf * 16, kbA));
            #pragma unroll
            for (int mf = 0; mf < 2; mf++)
                #pragma unroll
                for (int nf = 0; nf < 8; nf++)
                    mma16816(acc[mf][nf], afh[mf], bfh[nf]);
            unsigned afl[2][4];
            #pragma unroll
            for (int mf = 0; mf < 2; mf++)
                ldm4(afl[mf][0], afl[mf][1], afl[mf][2], afl[mf][3],
                     sw_addr(tAlo[c], arow + mf * 16, kbA));
            #pragma unroll
            for (int mf = 0; mf < 2; mf++)
                #pragma unroll
                for (int nf = 0; nf < 8; nf++)
                    mma16816(acc[mf][nf], afl[mf], bfh[nf]);
            unsigned bfl[8][2];
            #pragma unroll
            for (int p = 0; p < 4; p++)
                ldm4(bfl[2*p][0], bfl[2*p][1], bfl[2*p+1][0], bfl[2*p+1][1],
                     sw_addr(tBlo[c], brow0 + p * 16, kbB));
            #pragma unroll
            for (int mf = 0; mf < 2; mf++)
                #pragma unroll
                for (int nf = 0; nf < 8; nf++)
                    mma16816(acc[mf][nf], afh[mf], bfl[nf]);
        }
    }
}

// ---------------------------------------------------------------------------
// K0: ALL fp32 -> bf16 hi/lo splits in one launch
// ---------------------------------------------------------------------------
#define E4   (NITEMS * D / 4)
#define W4   (D * D / 4)
#define W34  (3 * D * D / 4)
#define CONV_GROUPS (E4 + 2 * W4 + 2 * W34)

__global__ __launch_bounds__(256) void conv_all_kernel(
    const float* __restrict__ emb,  const float* __restrict__ W_in,
    const float* __restrict__ W_out, const float* __restrict__ w_hh,
    const float* __restrict__ w_ih)
{
    size_t i = (size_t)blockIdx.x * 256 + threadIdx.x;
    const float* src; __nv_bfloat16 *dhi, *dlo; size_t off;
    if (i < E4)                    { src = emb;   off = i;                 dhi = g_ehi;            dlo = g_elo; }
    else if (i < E4 + W4)          { src = W_in;  off = i - E4;            dhi = g_wiohi;          dlo = g_wiolo; }
    else if (i < E4 + 2 * W4)      { src = W_out; off = i - E4 - W4;       dhi = g_wiohi + D * D;  dlo = g_wiolo + D * D; }
    else if (i < E4 + 2 * W4 + W34){ src = w_hh;  off = i - E4 - 2 * W4;   dhi = g_whhhi;          dlo = g_whhlo; }
    else                           { src = w_ih;  off = i - E4 - 2*W4 - W34; dhi = g_wihhi;        dlo = g_wihlo; }

    float4 v = ((const float4*)src)[off];
    __nv_bfloat162 h01 = __floats2bfloat162_rn(v.x, v.y);
    __nv_bfloat162 h23 = __floats2bfloat162_rn(v.z, v.w);
    __nv_bfloat162 l01 = __floats2bfloat162_rn(v.x - __low2float(h01), v.y - __high2float(h01));
    __nv_bfloat162 l23 = __floats2bfloat162_rn(v.z - __low2float(h23), v.w - __high2float(h23));
    ((__nv_bfloat162*)dhi)[2 * off]     = h01;
    ((__nv_bfloat162*)dhi)[2 * off + 1] = h23;
    ((__nv_bfloat162*)dlo)[2 * off]     = l01;
    ((__nv_bfloat162*)dlo)[2 * off + 1] = l23;
}

// ---------------------------------------------------------------------------
// K1: per-sample graph build + bf16 hi/lo gather
// ---------------------------------------------------------------------------
__global__ __launch_bounds__(256) void build_kernel(const int* __restrict__ x)
{
    __shared__ int s_seq[L], s_rep[L], s_nodes[L], s_cinv[L];
    __shared__ int s_nn, s_cnt;
    const int b = blockIdx.x, tid = threadIdx.x;

    if (tid == 0) { s_nn = 0; s_cnt = 0; }
    if (tid < L) { s_seq[tid] = x[b * L + tid]; s_cinv[tid] = 0; }
    __syncthreads();

    int mypos = 0;
    if (tid < L) {
        int s = s_seq[tid];
        int rep = (s != 0);
        for (int j = 0; j < tid; j++) {
            int sj = s_seq[j];
            if (sj != 0) { mypos++; if (sj == s) rep = 0; }
        }
        s_rep[tid] = rep;
    }
    __syncthreads();

    if (tid < L) {
        int s = s_seq[tid];
        if (s != 0) {
            int rank = 0;
            for (int j = 0; j < L; j++)
                if (s_rep[j] && s_seq[j] < s) rank++;
            if (s_rep[tid]) { s_nodes[rank] = s; atomicAdd(&s_nn, 1); }
            s_cinv[mypos] = rank;
            atomicAdd(&s_cnt, 1);
        }
    }
    __syncthreads();

    const int nn = s_nn, cnt = s_cnt;

    for (int idx = tid; idx < L * 16; idx += 256) {
        int r = idx >> 4, q = idx & 15;
        uint4 vh = make_uint4(0u, 0u, 0u, 0u), vl = vh;
        if (r < nn) {
            vh = ((const uint4*)(g_ehi + (size_t)s_nodes[r] * D))[q];
            vl = ((const uint4*)(g_elo + (size_t)s_nodes[r] * D))[q];
        }
        ((uint4*)(g_hallhi + ((size_t)b * L + r) * D))[q] = vh;
        ((uint4*)(g_halllo + ((size_t)b * L + r) * D))[q] = vl;
    }
    if (tid < L) g_cinv[b * L + tid] = s_cinv[tid];
    if (tid == 0) {
        g_nn[b] = nn;
        g_cntv[b] = cnt;
        g_li[b] = (cnt > 0) ? s_cinv[cnt - 1] : 0;
    }
}

// ---------------------------------------------------------------------------
// Persistent internal GEMM: weights resident, A streamed (double-buffered
// cp.async for NPAIR=1; sequential pair staging for NPAIR=2).
// C(m-tile, n0) = sum_pairs 3-term(A_pair, B_pair)
// ---------------------------------------------------------------------------
template<int NPAIR>
__global__ void __launch_bounds__(256) internal_persist_kernel(
    const __nv_bfloat16* __restrict__ A0hi, const __nv_bfloat16* __restrict__ A0lo,
    const __nv_bfloat16* __restrict__ B0hi, const __nv_bfloat16* __restrict__ B0lo,
    const __nv_bfloat16* __restrict__ A1hi, const __nv_bfloat16* __restrict__ A1lo,
    const __nv_bfloat16* __restrict__ B1hi, const __nv_bfloat16* __restrict__ B1lo,
    int coff, int ldc, int mtiles)
{
    extern __shared__ char dsm[];
    const int tid = threadIdx.x, wid = tid >> 5, lane = tid & 31;
    const int n0 = blockIdx.y * 128;
    unsigned tb = (smem_u32(dsm) + 1023) & ~1023u;

    unsigned b0hi[2] = { tb,            tb + TILE };
    unsigned b0lo[2] = { tb + 2*TILE,   tb + 3*TILE };
    unsigned b1hi[2] = { tb + 4*TILE,   tb + 5*TILE };
    unsigned b1lo[2] = { tb + 6*TILE,   tb + 7*TILE };

    // resident weights
    stage_tile(b0hi[0], b0hi[1], B0hi, n0, 0x7fffffff, tid);
    stage_tile(b0lo[0], b0lo[1], B0lo, n0, 0x7fffffff, tid);
    if (NPAIR == 2) {
        stage_tile(b1hi[0], b1hi[1], B1hi, n0, 0x7fffffff, tid);
        stage_tile(b1lo[0], b1lo[1], B1lo, n0, 0x7fffffff, tid);
    }

    const int m0w = (wid & 3) * 32;
    const int n0w = (wid >> 2) * 64;
    const int arow = m0w + (lane & 15);
    const int asub = lane >> 4;
    const int brow0 = n0w + ((lane >> 4) << 3) + (lane & 7);
    const int bsub  = (lane >> 3) & 1;
    const int rbase = lane >> 2;
    const int cbase = (lane & 3) * 2;
    float* C = g_blob + coff;

    if (NPAIR == 1) {
        // A double-buffered: buf b at tb + (4 + 4b)*TILE
        unsigned ab[2][4];
        #pragma unroll
        for (int b = 0; b < 2; b++)
            #pragma unroll
            for (int t = 0; t < 4; t++)
                ab[b][t] = tb + (4 + 4 * b + t) * TILE;   // hi0,hi1,lo0,lo1

        int buf = 0;
        int mt = blockIdx.x;
        if (mt < mtiles) {
            stage_tile_async(ab[0][0], ab[0][1], A0hi, mt * 128, 0x7fffffff, tid);
            stage_tile_async(ab[0][2], ab[0][3], A0lo, mt * 128, 0x7fffffff, tid);
            CP_COMMIT();
        }
        for (; mt < mtiles; mt += gridDim.x) {
            int mtn = mt + gridDim.x;
            bool pf = mtn < mtiles;
            if (pf) {
                stage_tile_async(ab[buf^1][0], ab[buf^1][1], A0hi, mtn * 128, 0x7fffffff, tid);
                stage_tile_async(ab[buf^1][2], ab[buf^1][3], A0lo, mtn * 128, 0x7fffffff, tid);
                CP_COMMIT();
            }
            if (pf) { CP_WAIT(1); } else { CP_WAIT(0); }
            __syncthreads();

            float acc[2][8][4];
            #pragma unroll
            for (int i = 0; i < 2; i++)
                #pragma unroll
                for (int j = 0; j < 8; j++)
                    #pragma unroll
                    for (int q = 0; q < 4; q++) acc[i][j][q] = 0.f;

            unsigned ahi[2] = { ab[buf][0], ab[buf][1] };
            unsigned alo[2] = { ab[buf][2], ab[buf][3] };
            compute_3term(acc, ahi, alo, b0hi, b0lo, arow, asub, brow0, bsub);

            const int m0 = mt * 128;
            #pragma unroll
            for (int mf = 0; mf < 2; mf++) {
                const int mA = m0 + m0w + mf * 16 + rbase;
                #pragma unroll
                for (int nf = 0; nf < 8; nf++) {
                    const int n = n0 + n0w + nf * 8 + cbase;
                    float2 vA = { acc[mf][nf][0], acc[mf][nf][1] };
                    float2 vB = { acc[mf][nf][2], acc[mf][nf][3] };
                    *(float2*)&C[(size_t)mA * ldc + n] = vA;
                    *(float2*)&C[(size_t)(mA + 8) * ldc + n] = vB;
                }
            }
            __syncthreads();
            buf ^= 1;
        }
    } else {
        // NPAIR == 2: single A buffer at tb + 8*TILE, sequential pairs
        unsigned as_[4] = { tb + 8*TILE, tb + 9*TILE, tb + 10*TILE, tb + 11*TILE };
        unsigned ahi[2] = { as_[0], as_[1] };
        unsigned alo[2] = { as_[2], as_[3] };
        __syncthreads();   // resident B visible

        for (int mt = blockIdx.x; mt < mtiles; mt += gridDim.x) {
            stage_tile_async(as_[0], as_[1], A0hi, mt * 128, 0x7fffffff, tid);
            stage_tile_async(as_[2], as_[3], A0lo, mt * 128, 0x7fffffff, tid);
            CP_COMMIT(); CP_WAIT(0);
            __syncthreads();

            float acc[2][8][4];
            #pragma unroll
            for (int i = 0; i < 2; i++)
                #pragma unroll
                for (int j = 0; j < 8; j++)
                    #pragma unroll
                    for (int q = 0; q < 4; q++) acc[i][j][q] = 0.f;

            compute_3term(acc, ahi, alo, b0hi, b0lo, arow, asub, brow0, bsub);
            __syncthreads();

            stage_tile_async(as_[0], as_[1], A1hi, mt * 128, 0x7fffffff, tid);
            stage_tile_async(as_[2], as_[3], A1lo, mt * 128, 0x7fffffff, tid);
            CP_COMMIT(); CP_WAIT(0);
            __syncthreads();

            compute_3term(acc, ahi, alo, b1hi, b1lo, arow, asub, brow0, bsub);

            const int m0 = mt * 128;
            #pragma unroll
            for (int mf = 0; mf < 2; mf++) {
                const int mA = m0 + m0w + mf * 16 + rbase;
                #pragma unroll
                for (int nf = 0; nf < 8; nf++) {
                    const int n = n0 + n0w + nf * 8 + cbase;
                    float2 vA = { acc[mf][nf][0], acc[mf][nf][1] };
                    float2 vB = { acc[mf][nf][2], acc[mf][nf][3] };
                    *(float2*)&C[(size_t)mA * ldc + n] = vA;
                    *(float2*)&C[(size_t)(mA + 8) * ldc + n] = vB;
                }
            }
            __syncthreads();
        }
    }
}

// ---------------------------------------------------------------------------
// Persistent score GEMM: A (h_read) resident, emb tiles streamed with
// double-buffered cp.async; epilogue with cnt>=2 masking.
// ---------------------------------------------------------------------------
__global__ void __launch_bounds__(256) score_persist_kernel(
    const __nv_bfloat16* __restrict__ Ahi, const __nv_bfloat16* __restrict__ Alo,
    const __nv_bfloat16* __restrict__ Bhi, const __nv_bfloat16* __restrict__ Blo,
    float* __restrict__ out)
{
    extern __shared__ char dsm[];
    const int tid = threadIdx.x, wid = tid >> 5, lane = tid & 31;
    const int m0 = blockIdx.x * 128;
    unsigned tb = (smem_u32(dsm) + 1023) & ~1023u;

    unsigned tahi[2] = { tb,          tb + TILE };
    unsigned talo[2] = { tb + 2*TILE, tb + 3*TILE };
    unsigned bb[2][4];
    #pragma unroll
    for (int b = 0; b < 2; b++)
        #pragma unroll
        for (int t = 0; t < 4; t++)
            bb[b][t] = tb + (4 + 4 * b + t) * TILE;     // hi0,hi1,lo0,lo1

    stage_tile(tahi[0], tahi[1], Ahi, m0, BATCH, tid);
    stage_tile(talo[0], talo[1], Alo, m0, BATCH, tid);

    const int m0w = (wid & 3) * 32;
    const int n0w = (wid >> 2) * 64;
    const int arow = m0w + (lane & 15);
    const int asub = lane >> 4;
    const int brow0 = n0w + ((lane >> 4) << 3) + (lane & 7);
    const int bsub  = (lane >> 3) & 1;
    const int rbase = lane >> 2;
    const int cbase = (lane & 3) * 2;

    // per-CTA-invariant mask bits (hoisted out of the n loop)
    const int mA0 = m0 + m0w + rbase;
    const bool ok[4] = { g_cntv[mA0] >= 2,      g_cntv[mA0 + 8] >= 2,
                         g_cntv[mA0 + 16] >= 2, g_cntv[mA0 + 24] >= 2 };

    const int NT = (NITEMS + 127) / 128;     // 782
    int buf = 0;
    int nt = blockIdx.y;
    if (nt < NT) {
        stage_tile_async(bb[0][0], bb[0][1], Bhi, nt * 128, NITEMS, tid);
        stage_tile_async(bb[0][2], bb[0][3], Blo, nt * 128, NITEMS, tid);
        CP_COMMIT();
    }
    for (; nt < NT; nt += gridDim.y) {
        int ntn = nt + gridDim.y;
        bool pf = ntn < NT;
        if (pf) {
            stage_tile_async(bb[buf^1][0], bb[buf^1][1], Bhi, ntn * 128, NITEMS, tid);
            stage_tile_async(bb[buf^1][2], bb[buf^1][3], Blo, ntn * 128, NITEMS, tid);
            CP_COMMIT();
        }
        if (pf) { CP_WAIT(1); } else { CP_WAIT(0); }
        __syncthreads();

        float acc[2][8][4];
        #pragma unroll
        for (int i = 0; i < 2; i++)
            #pragma unroll
            for (int j = 0; j < 8; j++)
                #pragma unroll
                for (int q = 0; q < 4; q++) acc[i][j][q] = 0.f;

        unsigned bhi[2] = { bb[buf][0], bb[buf][1] };
        unsigned blo[2] = { bb[buf][2], bb[buf][3] };
        compute_3term(acc, tahi, talo, bhi, blo, arow, asub, brow0, bsub);

        const int n0 = nt * 128;
        #pragma unroll
        for (int mf = 0; mf < 2; mf++) {
            const int mA = mA0 + mf * 16;
            const bool okA = ok[mf * 2], okB = ok[mf * 2 + 1];
            #pragma unroll
            for (int nf = 0; nf < 8; nf++) {
                const int n = n0 + n0w + nf * 8 + cbase;
                if (n < NITEMS) {
                    float2 vA, vB;
                    if (okA) { vA.x = acc[mf][nf][0]; vA.y = acc[mf][nf][1]; }
                    else     { vA.x = (n == 0) ? 0.0f : NEGV; vA.y = NEGV; }
                    if (okB) { vB.x = acc[mf][nf][2]; vB.y = acc[mf][nf][3]; }
                    else     { vB.x = (n == 0) ? 0.0f : NEGV; vB.y = NEGV; }
                    *(float2*)&out[(size_t)mA * NITEMS + n] = vA;
                    *(float2*)&out[(size_t)(mA + 8) * NITEMS + n] = vB;
                }
            }
        }
        __syncthreads();
        buf ^= 1;
    }
}

// ---------------------------------------------------------------------------
// K3: per-sample edge aggregation.  X = Hin + agg(Hout[src])/deg -> bf16 hi/lo
// ---------------------------------------------------------------------------
__global__ __launch_bounds__(256) void agg_kernel()
{
    extern __shared__ float agg[];            // L*D floats
    __shared__ int   cinv[L];
    __shared__ float rdeg[L];
    const int b = blockIdx.x, tid = threadIdx.x;

    if (tid < L) { cinv[tid] = g_cinv[b * L + tid]; rdeg[tid] = 0.f; }
    for (int i = tid; i < L * D / 4; i += 256)
        ((float4*)agg)[i] = make_float4(0.f, 0.f, 0.f, 0.f);
    __syncthreads();

    const int cnt = g_cntv[b];
    if (tid < cnt - 1) atomicAdd(&rdeg[cinv[tid + 1]], 1.0f);
    __syncthreads();
    if (tid < L) rdeg[tid] = 1.0f / fmaxf(rdeg[tid], 1.0f);

    const float* Hio = g_blob + OFF_HIO + (size_t)b * L * 2 * D;
    const int nedge = (cnt >= 1) ? cnt - 1 : 0;
    for (int idx = tid; idx < nedge * D; idx += 256) {
        int t = idx >> 7, k = idx & 127;
        atomicAdd(&agg[cinv[t + 1] * D + k], Hio[(size_t)cinv[t] * 2 * D + D + k]);
    }
    __syncthreads();

    for (int idx = tid; idx < L * D; idx += 256) {
        int r = idx >> 7;
        float v = Hio[(size_t)r * 2 * D + (idx & 127)] + agg[idx] * rdeg[r];
        __nv_bfloat16 h = __float2bfloat16(v);
        g_xhi[(size_t)b * L * D + idx] = h;
        g_xlo[(size_t)b * L * D + idx] = __float2bfloat16(v - __bfloat162float(h));
    }
}

// ---------------------------------------------------------------------------
// K4: fused GRU + attention readout (one CTA per sample, H in SMEM)
// ---------------------------------------------------------------------------
__global__ __launch_bounds__(256) void gru_attn_kernel(
    const float* __restrict__ b_ih, const float* __restrict__ b_hh,
    const float* __restrict__ W_read, const float* __restrict__ b_read)
{
    extern __shared__ float H[];              // L*D floats
    __shared__ float hlast[D], loc[D], sc[L];
    const int b = blockIdx.x, tid = threadIdx.x;
    const int nn = g_nn[b], li = g_li[b];

    for (int idx = tid; idx < L * D; idx += 256) {
        int row = idx >> 7, j = idx & 127;
        size_t base = (size_t)b * L + row;
        float sr  = g_blob[OFF_SRZ + base * 256 + j];
        float sz  = g_blob[OFF_SRZ + base * 256 + 128 + j];
        float gin = g_blob[OFF_GIN + base * 128 + j];
        float ghn = g_blob[OFF_GHN + base * 128 + j];
        float h0  = __bfloat162float(g_hallhi[base * 128 + j])
                  + __bfloat162float(g_halllo[base * 128 + j]);
        float r = 1.0f / (1.0f + expf(-(sr + b_ih[j] + b_hh[j])));
        float z = 1.0f / (1.0f + expf(-(sz + b_ih[D + j] + b_hh[D + j])));
        float n = tanhf(gin + b_ih[2 * D + j] + r * (ghn + b_hh[2 * D + j]));
        H[idx] = (1.0f - z) * n + z * h0;
    }
    __syncthreads();

    if (tid < D) hlast[tid] = H[li * D + tid];
    __syncthreads();

    const int w = tid >> 5, lane = tid & 31;
    for (int r = w; r < nn; r += 8) {
        const float* hr = H + r * D;
        float acc = 0.f;
        #pragma unroll
        for (int k = lane; k < D; k += 32) acc = fmaf(hr[k], hlast[k], acc);
        #pragma unroll
        for (int off = 16; off; off >>= 1)
            acc += __shfl_down_sync(0xffffffffu, acc, off);
        if (lane == 0) sc[r] = acc;
    }
    __syncthreads();

    if (tid == 0) {
        float m = -1e30f;
        for (int i = 0; i < nn; i++) m = fmaxf(m, sc[i]);
        float s = 0.f;
        for (int i = 0; i < nn; i++) { float e = expf(sc[i] - m); sc[i] = e; s += e; }
        float inv = (s > 0.f) ? 1.0f / s : 0.f;
        for (int i = 0; i < nn; i++) sc[i] *= inv;
    }
    __syncthreads();

    if (tid < D) {
        float acc = 0.f;
        for (int r = 0; r < nn; r++) acc = fmaf(sc[r], H[r * D + tid], acc);
        loc[tid] = acc;
    }
    __syncthreads();

    #pragma unroll
    for (int t = 0; t < 16; t++) {
        int j = w * 16 + t;
        const float* wr = W_read + (size_t)j * (3 * D);
        float acc = 0.f;
        #pragma unroll
        for (int k = lane; k < D; k += 32)
            acc += wr[k] * hlast[k] + wr[D + k] * loc[k];
        #pragma unroll
        for (int off = 16; off; off >>= 1)
            acc += __shfl_down_sync(0xffffffffu, acc, off);
        if (lane == 0) {
            float hv = tanhf(acc + b_read[j]);
            __nv_bfloat16 h = __float2bfloat16(hv);
            g_ahi[b * D + j] = h;
            g_alo[b * D + j] = __float2bfloat16(hv - __bfloat162float(h));
        }
    }
}

// ---------------------------------------------------------------------------
extern "C" void kernel_launch(void* const* d_in, const int* in_sizes, int n_in,
                              void* d_out, int out_size)
{
    const int*   x      = (const int*)  d_in[0];
    // d_in[1] = attn_mask (unused by reference)
    const float* emb    = (const float*)d_in[2];
    const float* W_in   = (const float*)d_in[3];
    const float* W_out  = (const float*)d_in[4];
    const float* w_ih   = (const float*)d_in[5];
    const float* w_hh   = (const float*)d_in[6];
    const float* b_ih   = (const float*)d_in[7];
    const float* b_hh   = (const float*)d_in[8];
    const float* W_read = (const float*)d_in[9];
    const float* b_read = (const float*)d_in[10];
    float* out = (float*)d_out;

    cudaFuncSetAttribute(agg_kernel,
        cudaFuncAttributeMaxDynamicSharedMemorySize, L * D * (int)sizeof(float));
    cudaFuncSetAttribute(gru_attn_kernel,
        cudaFuncAttributeMaxDynamicSharedMemorySize, L * D * (int)sizeof(float));
    cudaFuncSetAttribute(internal_persist_kernel<1>,
        cudaFuncAttributeMaxDynamicSharedMemorySize, PS_SMEM);
    cudaFuncSetAttribute(internal_persist_kernel<2>,
        cudaFuncAttributeMaxDynamicSharedMemorySize, PS_SMEM);
    cudaFuncSetAttribute(score_persist_kernel,
        cudaFuncAttributeMaxDynamicSharedMemorySize, PS_SMEM);

    __nv_bfloat16 *ehi, *elo, *ahi, *alo, *hallhi, *halllo, *xhi, *xlo;
    __nv_bfloat16 *wiohi, *wiolo, *whhhi, *whhlo, *wihhi, *wihlo;
    cudaGetSymbolAddress((void**)&ehi,    g_ehi);
    cudaGetSymbolAddress((void**)&elo,    g_elo);
    cudaGetSymbolAddress((void**)&ahi,    g_ahi);
    cudaGetSymbolAddress((void**)&alo,    g_alo);
    cudaGetSymbolAddress((void**)&hallhi, g_hallhi);
    cudaGetSymbolAddress((void**)&halllo, g_halllo);
    cudaGetSymbolAddress((void**)&xhi,    g_xhi);
    cudaGetSymbolAddress((void**)&xlo,    g_xlo);
    cudaGetSymbolAddress((void**)&wiohi,  g_wiohi);
    cudaGetSymbolAddress((void**)&wiolo,  g_wiolo);
    cudaGetSymbolAddress((void**)&whhhi,  g_whhhi);
    cudaGetSymbolAddress((void**)&whhlo,  g_whhlo);
    cudaGetSymbolAddress((void**)&wihhi,  g_wihhi);
    cudaGetSymbolAddress((void**)&wihlo,  g_wihlo);

    // K0: all fp32 -> bf16 hi/lo conversions in one launch
    conv_all_kernel<<<CONV_GROUPS / 256, 256>>>(emb, W_in, W_out, w_hh, w_ih);

    // K1: graph build + bf16 hi/lo gather
    build_kernel<<<BATCH, 256>>>(x);

    // G1: Hin | Hout = Hall @ [W_in; W_out]^T  (persistent, weights resident)
    internal_persist_kernel<1><<<dim3(74, 2), 256, PS_SMEM>>>(
        hallhi, halllo, wiohi, wiolo,
        nullptr, nullptr, nullptr, nullptr, OFF_HIO, 2 * D, ROWS / 128);

    // G_ghn: gh_n = Hall @ w_hh_n^T
    internal_persist_kernel<1><<<dim3(148, 1), 256, PS_SMEM>>>(
        hallhi, halllo, whhhi + 2 * D * D, whhlo + 2 * D * D,
        nullptr, nullptr, nullptr, nullptr, OFF_GHN, D, ROWS / 128);

    // K3: X = Hin + agg/deg -> bf16 hi/lo
    agg_kernel<<<BATCH, 256, L * D * sizeof(float)>>>();

    // G_rz: s_rz = X @ w_ih_rz^T + Hall @ w_hh_rz^T   (dual-pair, B resident)
    internal_persist_kernel<2><<<dim3(74, 2), 256, PS_SMEM>>>(
        xhi, xlo, wihhi, wihlo,
        hallhi, halllo, whhhi, whhlo, OFF_SRZ, 2 * D, ROWS / 128);

    // G_gin: gi_n = X @ w_ih_n^T
    internal_persist_kernel<1><<<dim3(148, 1), 256, PS_SMEM>>>(
        xhi, xlo, wihhi + 2 * D * D, wihlo + 2 * D * D,
        nullptr, nullptr, nullptr, nullptr, OFF_GIN, D, ROWS / 128);

    // K4: fused GRU + attention -> h_read hi/lo
    gru_attn_kernel<<<BATCH, 256, L * D * sizeof(float)>>>(b_ih, b_hh, W_read, b_read);

    // K6: persistent tensor-core score GEMM (A resident, emb streamed)
    score_persist_kernel<<<dim3(BATCH / 128, 37), 256, PS_SMEM>>>(
        ahi, alo, ehi, elo, out);
}